// round 1
// baseline (speedup 1.0000x reference)
#include <cuda_runtime.h>
#include <cstdint>

// Problem constants (fixed by the dataset)
#define NMAX   100000
#define DD     128
#define LL     3
#define OCW    512     // concat width
#define CHN    4
#define CHID   256

// ---------------- static device scratch (allocation-free rule) ----------------
__device__ float g_cat[(size_t)NMAX * OCW];     // [N,512] concat buffer (x | h1 | h2 | h3)
__device__ float g_agg[(size_t)NMAX * DD];      // scatter-add target
__device__ float g_t0 [(size_t)NMAX * DD];      // conv MLP ping
__device__ float g_t1 [(size_t)NMAX * DD];      // conv MLP pong
__device__ float g_H1 [(size_t)NMAX * CHN * CHID]; // [N,1024]
__device__ float g_H2 [(size_t)NMAX * CHN * CHID]; // [N,1024]

// ---------------- copy x into cat[:, 0:128] ----------------
__global__ void copy_x_kernel(const float* __restrict__ x, int n) {
    int i = blockIdx.x * blockDim.x + threadIdx.x;   // float4 index
    int total = n * (DD / 4);
    if (i >= total) return;
    int row = i >> 5;          // DD/4 = 32 float4 per row
    int c4  = i & 31;
    float4 v = ((const float4*)x)[i];
    ((float4*)g_cat)[(size_t)row * (OCW / 4) + c4] = v;
}

// ---------------- edge scatter: agg[dst] += h[src]  (h = cat[:, colOff:colOff+128]) ----------------
__global__ void scatter_kernel(const int* __restrict__ edge, int E, int colOff) {
    int t = blockIdx.x * blockDim.x + threadIdx.x;
    int e = t >> 5;
    if (e >= E) return;
    int lane = t & 31;
    int src = edge[e];
    int dst = edge[E + e];
    float4 v = *(const float4*)(g_cat + (size_t)src * OCW + colOff + lane * 4);
    float* p = g_agg + (size_t)dst * DD + lane * 4;
    atomicAdd(p + 0, v.x);
    atomicAdd(p + 1, v.y);
    atomicAdd(p + 2, v.z);
    atomicAdd(p + 3, v.w);
}

// ---------------- generic fp32 GEMM + bias + ReLU ----------------
// C[M, cols] = relu( A_eff @ B_eff + bias ), tiled 128x128, BK=16, 256 threads, 8x8 microtile.
// Channel-mode support: for output col block starting at j0,
//   cblk = j0 / chanWidth
//   A_eff = A + cblk*aColChanStride  (col window into A)
//   B_eff = B + cblk*bChanStride     (per-channel weight block), local col = j0 - cblk*chanWidth
// Optional agg add fused into A load (GIN: (h + agg)).
__global__ __launch_bounds__(256, 2)
void gemm_relu_kernel(const float* __restrict__ A, int lda, int aColChanStride,
                      const float* __restrict__ aggp,
                      const float* __restrict__ B, int ldb, long bChanStride,
                      const float* __restrict__ bias,
                      float* __restrict__ C, int ldc,
                      int M, int K, int chanWidth)
{
    __shared__ float As[16][128];
    __shared__ float Ws[16][128];

    int m0 = blockIdx.x * 128;
    int j0 = blockIdx.y * 128;
    int cblk = j0 / chanWidth;
    const float* Ab = A + (size_t)cblk * aColChanStride;
    const float* Bb = B + (size_t)cblk * bChanStride;
    int jB0 = j0 - cblk * chanWidth;

    int tid = threadIdx.x;
    int tx = tid & 15;       // col group (8 cols each)
    int ty = tid >> 4;       // row group (8 rows each)

    float acc[8][8];
#pragma unroll
    for (int i = 0; i < 8; i++)
#pragma unroll
        for (int j = 0; j < 8; j++) acc[i][j] = 0.f;

    for (int k0 = 0; k0 < K; k0 += 16) {
        // cooperative loads: 512 float4 for A tile, 512 float4 for W tile
#pragma unroll
        for (int it = 0; it < 2; it++) {
            int f = tid + it * 256;            // 0..511
            // A: 128 rows x 4 float4 along K (transpose into As[k][row])
            int row = f >> 2;
            int kg  = (f & 3) * 4;
            float4 v = make_float4(0.f, 0.f, 0.f, 0.f);
            int grow = m0 + row;
            if (grow < M) {
                v = *(const float4*)(Ab + (size_t)grow * lda + k0 + kg);
                if (aggp) {
                    float4 w = *(const float4*)(aggp + (size_t)grow * DD + k0 + kg);
                    v.x += w.x; v.y += w.y; v.z += w.z; v.w += w.w;
                }
            }
            As[kg + 0][row] = v.x;
            As[kg + 1][row] = v.y;
            As[kg + 2][row] = v.z;
            As[kg + 3][row] = v.w;
            // W: 16 k-rows x 32 float4 cols
            int d  = f >> 5;
            int c4 = (f & 31) * 4;
            float4 wv = *(const float4*)(Bb + (size_t)(k0 + d) * ldb + jB0 + c4);
            *(float4*)&Ws[d][c4] = wv;
        }
        __syncthreads();

#pragma unroll
        for (int kk = 0; kk < 16; kk++) {
            float a[8], b[8];
            *(float4*)&a[0] = *(const float4*)&As[kk][ty * 8];
            *(float4*)&a[4] = *(const float4*)&As[kk][ty * 8 + 4];
            *(float4*)&b[0] = *(const float4*)&Ws[kk][tx * 8];
            *(float4*)&b[4] = *(const float4*)&Ws[kk][tx * 8 + 4];
#pragma unroll
            for (int i = 0; i < 8; i++)
#pragma unroll
                for (int j = 0; j < 8; j++)
                    acc[i][j] += a[i] * b[j];
        }
        __syncthreads();
    }

    // epilogue: bias + relu, vectorized stores
    float bcol[8];
#pragma unroll
    for (int j = 0; j < 8; j++) bcol[j] = bias[j0 + tx * 8 + j];

#pragma unroll
    for (int i = 0; i < 8; i++) {
        int row = m0 + ty * 8 + i;
        if (row < M) {
            float4 o0, o1;
            float v;
            v = acc[i][0] + bcol[0]; o0.x = v > 0.f ? v : 0.f;
            v = acc[i][1] + bcol[1]; o0.y = v > 0.f ? v : 0.f;
            v = acc[i][2] + bcol[2]; o0.z = v > 0.f ? v : 0.f;
            v = acc[i][3] + bcol[3]; o0.w = v > 0.f ? v : 0.f;
            v = acc[i][4] + bcol[4]; o1.x = v > 0.f ? v : 0.f;
            v = acc[i][5] + bcol[5]; o1.y = v > 0.f ? v : 0.f;
            v = acc[i][6] + bcol[6]; o1.z = v > 0.f ? v : 0.f;
            v = acc[i][7] + bcol[7]; o1.w = v > 0.f ? v : 0.f;
            float* cp = C + (size_t)row * ldc + j0 + tx * 8;
            *(float4*)(cp)     = o0;
            *(float4*)(cp + 4) = o1;
        }
    }
}

// ---------------- final: out[n,c] = relu( H2[n, c*256: ] . W3[c] + b3[c] ) ----------------
__global__ void final_kernel(const float* __restrict__ W3, const float* __restrict__ b3,
                             float* __restrict__ out, int n)
{
    int w = (blockIdx.x * blockDim.x + threadIdx.x) >> 5;
    int lane = threadIdx.x & 31;
    if (w >= n * CHN) return;
    int row = w >> 2;
    int c   = w & 3;
    const float* h  = g_H2 + (size_t)row * (CHN * CHID) + c * CHID;
    const float* wp = W3 + c * CHID;
    float s = 0.f;
#pragma unroll
    for (int i = 0; i < 2; i++) {
        float4 hv = *(const float4*)(h  + lane * 4 + i * 128);
        float4 wv = *(const float4*)(wp + lane * 4 + i * 128);
        s += hv.x * wv.x + hv.y * wv.y + hv.z * wv.z + hv.w * wv.w;
    }
#pragma unroll
    for (int o = 16; o; o >>= 1) s += __shfl_down_sync(0xffffffffu, s, o);
    if (lane == 0) {
        float v = s + b3[c];
        out[(size_t)row * CHN + c] = v > 0.f ? v : 0.f;
    }
}

// ---------------- launch ----------------
extern "C" void kernel_launch(void* const* d_in, const int* in_sizes, int n_in,
                              void* d_out, int out_size)
{
    const float* x     = (const float*)d_in[0];
    const int*   edge  = (const int*)  d_in[1];
    const float* convW = (const float*)d_in[2];
    const float* convB = (const float*)d_in[3];
    const float* cW1   = (const float*)d_in[4];
    const float* cB1   = (const float*)d_in[5];
    const float* cW2   = (const float*)d_in[6];
    const float* cB2   = (const float*)d_in[7];
    const float* cW3   = (const float*)d_in[8];
    const float* cB3   = (const float*)d_in[9];
    float* out = (float*)d_out;

    int n = in_sizes[0] / DD;
    int E = in_sizes[1] / 2;

    float *cat, *agg, *t0, *t1, *H1, *H2;
    cudaGetSymbolAddress((void**)&cat, g_cat);
    cudaGetSymbolAddress((void**)&agg, g_agg);
    cudaGetSymbolAddress((void**)&t0,  g_t0);
    cudaGetSymbolAddress((void**)&t1,  g_t1);
    cudaGetSymbolAddress((void**)&H1,  g_H1);
    cudaGetSymbolAddress((void**)&H2,  g_H2);

    const int mBlocks = (n + 127) / 128;
    const int BIGWIDTH = 1 << 30;   // conv: no channel blocking

    // 1) cat[:,0:128] = x
    {
        int total = n * (DD / 4);
        copy_x_kernel<<<(total + 255) / 256, 256>>>(x, n);
    }

    // 2) GIN layers
    for (int l = 0; l < LL; l++) {
        cudaMemsetAsync(agg, 0, (size_t)n * DD * sizeof(float), 0);

        {
            long threads = (long)E * 32;
            int blocks = (int)((threads + 255) / 256);
            scatter_kernel<<<blocks, 256>>>(edge, E, l * DD);
        }

        const float* W0 = convW + (size_t)(l * 3 + 0) * DD * DD;
        const float* W1 = convW + (size_t)(l * 3 + 1) * DD * DD;
        const float* W2 = convW + (size_t)(l * 3 + 2) * DD * DD;
        const float* b0 = convB + (size_t)(l * 3 + 0) * DD;
        const float* b1 = convB + (size_t)(l * 3 + 1) * DD;
        const float* b2 = convB + (size_t)(l * 3 + 2) * DD;

        dim3 grid(mBlocks, 1);
        // t0 = relu((h + agg) @ W0 + b0), h = cat[:, l*128:]
        gemm_relu_kernel<<<grid, 256>>>(cat + l * DD, OCW, 0, agg,
                                        W0, DD, 0, b0, t0, DD, n, DD, BIGWIDTH);
        // t1 = relu(t0 @ W1 + b1)
        gemm_relu_kernel<<<grid, 256>>>(t0, DD, 0, nullptr,
                                        W1, DD, 0, b1, t1, DD, n, DD, BIGWIDTH);
        // cat[:, (l+1)*128:] = relu(t1 @ W2 + b2)
        gemm_relu_kernel<<<grid, 256>>>(t1, DD, 0, nullptr,
                                        W2, DD, 0, b2, cat + (l + 1) * DD, OCW, n, DD, BIGWIDTH);
    }

    // 3) channel MLP layer 1: H1[N,1024] = relu(cat @ W1[c] + b1[c])   (A cols shared)
    {
        dim3 grid(mBlocks, (CHN * CHID) / 128);
        gemm_relu_kernel<<<grid, 256>>>(cat, OCW, 0, nullptr,
                                        cW1, CHID, (long)OCW * CHID, cB1,
                                        H1, CHN * CHID, n, OCW, CHID);
    }
    // 4) channel MLP layer 2: block-diagonal per channel
    {
        dim3 grid(mBlocks, (CHN * CHID) / 128);
        gemm_relu_kernel<<<grid, 256>>>(H1, CHN * CHID, CHID, nullptr,
                                        cW2, CHID, (long)CHID * CHID, cB2,
                                        H2, CHN * CHID, n, CHID, CHID);
    }
    // 5) final per-channel dot + relu
    {
        long threads = (long)n * CHN * 32;
        int blocks = (int)((threads + 255) / 256);
        final_kernel<<<blocks, 256>>>(cW3, cB3, out, n);
    }
}

// round 2
// speedup vs baseline: 1.0770x; 1.0770x over previous
#include <cuda_runtime.h>
#include <cstdint>

// Problem constants (fixed by the dataset)
#define NMAX   100000
#define DD     128
#define LL     3
#define OCW    512     // concat width
#define CHN    4
#define CHID   256

// ---------------- static device scratch (allocation-free rule) ----------------
__device__ float g_cat[(size_t)NMAX * OCW];        // [N,512] concat buffer (x | h1 | h2 | h3)
__device__ float g_agg[(size_t)NMAX * DD];         // scatter-add target
__device__ float g_t0 [(size_t)NMAX * DD];         // conv MLP ping
__device__ float g_t1 [(size_t)NMAX * DD];         // conv MLP pong
__device__ float g_H1 [(size_t)NMAX * CHN * CHID]; // [N,1024]

// ---------------- copy x into cat[:, 0:128] ----------------
__global__ void copy_x_kernel(const float* __restrict__ x, int n) {
    int i = blockIdx.x * blockDim.x + threadIdx.x;   // float4 index
    int total = n * (DD / 4);
    if (i >= total) return;
    int row = i >> 5;          // DD/4 = 32 float4 per row
    int c4  = i & 31;
    float4 v = ((const float4*)x)[i];
    ((float4*)g_cat)[(size_t)row * (OCW / 4) + c4] = v;
}

// ---------------- edge scatter: agg[dst] += h[src] via vector RED ----------------
__global__ void scatter_kernel(const int* __restrict__ edge, int E, int colOff) {
    int t = blockIdx.x * blockDim.x + threadIdx.x;
    int e = t >> 5;
    if (e >= E) return;
    int lane = t & 31;
    int src = __ldg(edge + e);
    int dst = __ldg(edge + E + e);
    float4 v = *(const float4*)(g_cat + (size_t)src * OCW + colOff + lane * 4);
    float* p = g_agg + (size_t)dst * DD + lane * 4;
    asm volatile("red.global.add.v4.f32 [%0], {%1,%2,%3,%4};"
                 :: "l"(p), "f"(v.x), "f"(v.y), "f"(v.z), "f"(v.w)
                 : "memory");
}

// ---------------- generic fp32 GEMM + bias + ReLU, double-buffered ----------------
// C[M, cols] = relu( A_eff @ B_eff + bias ), tiled 128x128, BK=16, 256 threads, 8x8 microtile.
// Channel-mode: cblk = j0/chanWidth; A_eff = A + cblk*aColChanStride; B_eff = B + cblk*bChanStride.
// Optional agg add fused into A load (GIN: h + agg).
// FUSED=true: instead of storing C, compute per-row dot of relu(acc+bias) with W3 and atomicAdd to outp.
template<bool FUSED>
__global__ __launch_bounds__(256, 2)
void gemm_relu_kernel(const float* __restrict__ A, int lda, int aColChanStride,
                      const float* __restrict__ aggp,
                      const float* __restrict__ B, int ldb, long bChanStride,
                      const float* __restrict__ bias,
                      float* __restrict__ C, int ldc,
                      int M, int K, int chanWidth,
                      const float* __restrict__ W3, float* __restrict__ outp)
{
    __shared__ float As[2][16][128];
    __shared__ float Ws[2][16][128];

    int m0 = blockIdx.x * 128;
    int j0 = blockIdx.y * 128;
    int cblk = j0 / chanWidth;
    const float* Ab = A + (size_t)cblk * aColChanStride;
    const float* Bb = B + (size_t)cblk * bChanStride;
    int jB0 = j0 - cblk * chanWidth;

    int tid = threadIdx.x;
    int tx = tid & 15;       // col group (8 cols each)
    int ty = tid >> 4;       // row group (8 rows each)

    // cooperative load mapping
    int arow = tid >> 1;            // 0..127
    int akg  = (tid & 1) * 8;       // 0 or 8  (k offset of this thread's two float4)
    int wkr  = tid >> 4;            // 0..15   (k row)
    int wc4  = (tid & 15) * 8;      // col offset, two float4

    const float* aptr = Ab + (size_t)(m0 + arow) * lda + akg;
    const float* gptr = aggp ? (aggp + (size_t)(m0 + arow) * DD + akg) : nullptr;
    const float* wptr = Bb + (size_t)wkr * ldb + jB0 + wc4;
    bool arow_ok = (m0 + arow) < M;

    float4 ra0, ra1, rw0, rw1;

    auto LOAD = [&](int k0) {
        if (arow_ok) {
            ra0 = *(const float4*)(aptr + k0);
            ra1 = *(const float4*)(aptr + k0 + 4);
            if (gptr) {
                float4 g0 = *(const float4*)(gptr + k0);
                float4 g1 = *(const float4*)(gptr + k0 + 4);
                ra0.x += g0.x; ra0.y += g0.y; ra0.z += g0.z; ra0.w += g0.w;
                ra1.x += g1.x; ra1.y += g1.y; ra1.z += g1.z; ra1.w += g1.w;
            }
        } else {
            ra0 = make_float4(0.f, 0.f, 0.f, 0.f);
            ra1 = make_float4(0.f, 0.f, 0.f, 0.f);
        }
        rw0 = *(const float4*)(wptr + (size_t)k0 * ldb);
        rw1 = *(const float4*)(wptr + (size_t)k0 * ldb + 4);
    };

    auto STORE = [&](int b) {
        As[b][akg + 0][arow] = ra0.x;
        As[b][akg + 1][arow] = ra0.y;
        As[b][akg + 2][arow] = ra0.z;
        As[b][akg + 3][arow] = ra0.w;
        As[b][akg + 4][arow] = ra1.x;
        As[b][akg + 5][arow] = ra1.y;
        As[b][akg + 6][arow] = ra1.z;
        As[b][akg + 7][arow] = ra1.w;
        *(float4*)&Ws[b][wkr][wc4]     = rw0;
        *(float4*)&Ws[b][wkr][wc4 + 4] = rw1;
    };

    float acc[8][8];
#pragma unroll
    for (int i = 0; i < 8; i++)
#pragma unroll
        for (int j = 0; j < 8; j++) acc[i][j] = 0.f;

    const int T = K / 16;
    LOAD(0);
    STORE(0);
    __syncthreads();

    int buf = 0;
    for (int t = 0; t < T; t++) {
        if (t + 1 < T) LOAD((t + 1) * 16);

#pragma unroll
        for (int kk = 0; kk < 16; kk++) {
            float a[8], b[8];
            *(float4*)&a[0] = *(const float4*)&As[buf][kk][ty * 8];
            *(float4*)&a[4] = *(const float4*)&As[buf][kk][ty * 8 + 4];
            *(float4*)&b[0] = *(const float4*)&Ws[buf][kk][tx * 8];
            *(float4*)&b[4] = *(const float4*)&Ws[buf][kk][tx * 8 + 4];
#pragma unroll
            for (int i = 0; i < 8; i++)
#pragma unroll
                for (int j = 0; j < 8; j++)
                    acc[i][j] += a[i] * b[j];
        }

        if (t + 1 < T) {
            STORE(buf ^ 1);
            __syncthreads();
        }
        buf ^= 1;
    }

    float bcol[8];
#pragma unroll
    for (int j = 0; j < 8; j++) bcol[j] = bias[j0 + tx * 8 + j];

    if (!FUSED) {
#pragma unroll
        for (int i = 0; i < 8; i++) {
            int row = m0 + ty * 8 + i;
            if (row < M) {
                float4 o0, o1;
                float v;
                v = acc[i][0] + bcol[0]; o0.x = v > 0.f ? v : 0.f;
                v = acc[i][1] + bcol[1]; o0.y = v > 0.f ? v : 0.f;
                v = acc[i][2] + bcol[2]; o0.z = v > 0.f ? v : 0.f;
                v = acc[i][3] + bcol[3]; o0.w = v > 0.f ? v : 0.f;
                v = acc[i][4] + bcol[4]; o1.x = v > 0.f ? v : 0.f;
                v = acc[i][5] + bcol[5]; o1.y = v > 0.f ? v : 0.f;
                v = acc[i][6] + bcol[6]; o1.z = v > 0.f ? v : 0.f;
                v = acc[i][7] + bcol[7]; o1.w = v > 0.f ? v : 0.f;
                float* cp = C + (size_t)row * ldc + j0 + tx * 8;
                *(float4*)(cp)     = o0;
                *(float4*)(cp + 4) = o1;
            }
        }
    } else {
        // fused final layer: partial = sum_j relu(acc+bias) * W3[c, jlocal]; reduce over the
        // 16 threads (same ty) that cover the 128 cols of this block; atomicAdd to outp[row, c].
        float w3[8];
#pragma unroll
        for (int j = 0; j < 8; j++) w3[j] = W3[(size_t)cblk * CHID + jB0 + tx * 8 + j];

#pragma unroll
        for (int i = 0; i < 8; i++) {
            float part = 0.f;
#pragma unroll
            for (int j = 0; j < 8; j++) {
                float v = acc[i][j] + bcol[j];
                v = v > 0.f ? v : 0.f;
                part += v * w3[j];
            }
#pragma unroll
            for (int o = 8; o; o >>= 1)
                part += __shfl_xor_sync(0xffffffffu, part, o);
            int row = m0 + ty * 8 + i;
            if (tx == 0 && row < M)
                atomicAdd(outp + (size_t)row * CHN + cblk, part);
        }
    }
}

// ---------------- out fixup: out = relu(out + b3[c]) ----------------
__global__ void out_bias_relu_kernel(float* __restrict__ out, const float* __restrict__ b3, int n) {
    int i = blockIdx.x * blockDim.x + threadIdx.x;
    if (i >= n * CHN) return;
    float v = out[i] + b3[i & (CHN - 1)];
    out[i] = v > 0.f ? v : 0.f;
}

// ---------------- launch ----------------
extern "C" void kernel_launch(void* const* d_in, const int* in_sizes, int n_in,
                              void* d_out, int out_size)
{
    const float* x     = (const float*)d_in[0];
    const int*   edge  = (const int*)  d_in[1];
    const float* convW = (const float*)d_in[2];
    const float* convB = (const float*)d_in[3];
    const float* cW1   = (const float*)d_in[4];
    const float* cB1   = (const float*)d_in[5];
    const float* cW2   = (const float*)d_in[6];
    const float* cB2   = (const float*)d_in[7];
    const float* cW3   = (const float*)d_in[8];
    const float* cB3   = (const float*)d_in[9];
    float* out = (float*)d_out;

    int n = in_sizes[0] / DD;
    int E = in_sizes[1] / 2;

    float *cat, *agg, *t0, *t1, *H1;
    cudaGetSymbolAddress((void**)&cat, g_cat);
    cudaGetSymbolAddress((void**)&agg, g_agg);
    cudaGetSymbolAddress((void**)&t0,  g_t0);
    cudaGetSymbolAddress((void**)&t1,  g_t1);
    cudaGetSymbolAddress((void**)&H1,  g_H1);

    const int mBlocks = (n + 127) / 128;
    const int BIGWIDTH = 1 << 30;   // conv: no channel blocking

    // 1) cat[:,0:128] = x
    {
        int total = n * (DD / 4);
        copy_x_kernel<<<(total + 255) / 256, 256>>>(x, n);
    }

    // 2) GIN layers
    for (int l = 0; l < LL; l++) {
        cudaMemsetAsync(agg, 0, (size_t)n * DD * sizeof(float), 0);

        {
            long threads = (long)E * 32;
            int blocks = (int)((threads + 255) / 256);
            scatter_kernel<<<blocks, 256>>>(edge, E, l * DD);
        }

        const float* W0 = convW + (size_t)(l * 3 + 0) * DD * DD;
        const float* W1 = convW + (size_t)(l * 3 + 1) * DD * DD;
        const float* W2 = convW + (size_t)(l * 3 + 2) * DD * DD;
        const float* b0 = convB + (size_t)(l * 3 + 0) * DD;
        const float* b1 = convB + (size_t)(l * 3 + 1) * DD;
        const float* b2 = convB + (size_t)(l * 3 + 2) * DD;

        dim3 grid(mBlocks, 1);
        gemm_relu_kernel<false><<<grid, 256>>>(cat + l * DD, OCW, 0, agg,
                                               W0, DD, 0, b0, t0, DD, n, DD, BIGWIDTH,
                                               nullptr, nullptr);
        gemm_relu_kernel<false><<<grid, 256>>>(t0, DD, 0, nullptr,
                                               W1, DD, 0, b1, t1, DD, n, DD, BIGWIDTH,
                                               nullptr, nullptr);
        gemm_relu_kernel<false><<<grid, 256>>>(t1, DD, 0, nullptr,
                                               W2, DD, 0, b2, cat + (l + 1) * DD, OCW, n, DD, BIGWIDTH,
                                               nullptr, nullptr);
    }

    // 3) channel MLP layer 1: H1[N,1024] = relu(cat @ W1[c] + b1[c])
    {
        dim3 grid(mBlocks, (CHN * CHID) / 128);
        gemm_relu_kernel<false><<<grid, 256>>>(cat, OCW, 0, nullptr,
                                               cW1, CHID, (long)OCW * CHID, cB1,
                                               H1, CHN * CHID, n, OCW, CHID,
                                               nullptr, nullptr);
    }

    // 4) channel MLP layer 2 + fused final dot: out partials
    cudaMemsetAsync(out, 0, (size_t)n * CHN * sizeof(float), 0);
    {
        dim3 grid(mBlocks, (CHN * CHID) / 128);
        gemm_relu_kernel<true><<<grid, 256>>>(H1, CHN * CHID, CHID, nullptr,
                                              cW2, CHID, (long)CHID * CHID, cB2,
                                              nullptr, 0, n, CHID, CHID,
                                              cW3, out);
    }

    // 5) out = relu(out + b3)
    {
        int total = n * CHN;
        out_bias_relu_kernel<<<(total + 255) / 256, 256>>>(out, cB3, n);
    }
}

// round 4
// speedup vs baseline: 1.9913x; 1.8489x over previous
#include <cuda_runtime.h>
#include <cuda_bf16.h>
#include <cstdint>

// Problem constants
#define NMAX   100000
#define NPAD   100128
#define DD     128
#define LL     3
#define OCW    512
#define CHN    4
#define CHID   256

// ---------------- static device scratch ----------------
__device__ float g_cat[(size_t)NPAD * OCW];
__device__ float g_agg[(size_t)NPAD * DD];
__device__ __nv_bfloat16 g_catHL[(size_t)NPAD * 1024];  // [hi 512 | lo 512]
__device__ __nv_bfloat16 g_a0  [(size_t)NPAD * 256];    // [hi128|lo128]
__device__ __nv_bfloat16 g_t0  [(size_t)NPAD * 256];
__device__ __nv_bfloat16 g_t1  [(size_t)NPAD * 256];
__device__ __nv_bfloat16 g_H1  [(size_t)NPAD * 2048];   // [hi1024|lo1024]
__device__ __nv_bfloat16 g_convWex[(size_t)9 * 128 * 384];
__device__ __nv_bfloat16 g_W1ex  [(size_t)CHN * 256 * 1536];
__device__ __nv_bfloat16 g_W2ex  [(size_t)CHN * 256 * 768];

// ---------------- helpers ----------------
__device__ __forceinline__ uint32_t smem_u32(const void* p) {
    uint32_t r;
    asm("{ .reg .u64 t; cvta.to.shared.u64 t, %1; cvt.u32.u64 %0, t; }" : "=r"(r) : "l"(p));
    return r;
}
#define LDSM_X4(r0, r1, r2, r3, addr) \
    asm volatile("ldmatrix.sync.aligned.m8n8.x4.shared.b16 {%0,%1,%2,%3}, [%4];" \
        : "=r"(r0), "=r"(r1), "=r"(r2), "=r"(r3) : "r"(addr))

__device__ __forceinline__ void mma16816(float* c, const uint32_t* a, uint32_t b0, uint32_t b1) {
    asm volatile(
        "mma.sync.aligned.m16n8k16.row.col.f32.bf16.bf16.f32 "
        "{%0,%1,%2,%3}, {%4,%5,%6,%7}, {%8,%9}, {%0,%1,%2,%3};"
        : "+f"(c[0]), "+f"(c[1]), "+f"(c[2]), "+f"(c[3])
        : "r"(a[0]), "r"(a[1]), "r"(a[2]), "r"(a[3]), "r"(b0), "r"(b1));
}

// ---------------- weight expansion: W[K,N] fp32 -> Bex[N,3K] = [hi|lo|hi] ----------------
__global__ void expand_w_kernel(const float* __restrict__ W, __nv_bfloat16* __restrict__ Bex,
                                int K, int N) {
    int mi = blockIdx.y;
    const float* Wm = W + (size_t)mi * K * N;
    __nv_bfloat16* Bm = Bex + (size_t)mi * N * 3 * K;
    int id = blockIdx.x * blockDim.x + threadIdx.x;
    if (id >= K * N) return;
    int k = id / N, n = id % N;
    float w = Wm[id];
    __nv_bfloat16 hi = __float2bfloat16(w);
    __nv_bfloat16 lo = __float2bfloat16(w - __bfloat162float(hi));
    Bm[(size_t)n * 3 * K + k]         = hi;
    Bm[(size_t)n * 3 * K + K + k]     = lo;
    Bm[(size_t)n * 3 * K + 2 * K + k] = hi;
}

__device__ __forceinline__ void store_hilo4(__nv_bfloat16* p, int loDelta, float4 v) {
    __nv_bfloat16 h0 = __float2bfloat16(v.x), h1 = __float2bfloat16(v.y);
    __nv_bfloat16 h2 = __float2bfloat16(v.z), h3 = __float2bfloat16(v.w);
    ((__nv_bfloat162*)p)[0] = __nv_bfloat162(h0, h1);
    ((__nv_bfloat162*)p)[1] = __nv_bfloat162(h2, h3);
    __nv_bfloat16 l0 = __float2bfloat16(v.x - __bfloat162float(h0));
    __nv_bfloat16 l1 = __float2bfloat16(v.y - __bfloat162float(h1));
    __nv_bfloat16 l2 = __float2bfloat16(v.z - __bfloat162float(h2));
    __nv_bfloat16 l3 = __float2bfloat16(v.w - __bfloat162float(h3));
    ((__nv_bfloat162*)(p + loDelta))[0] = __nv_bfloat162(l0, l1);
    ((__nv_bfloat162*)(p + loDelta))[1] = __nv_bfloat162(l2, l3);
}

__global__ void prep_x_kernel(const float* __restrict__ x, int n) {
    int i = blockIdx.x * blockDim.x + threadIdx.x;
    if (i >= n * 32) return;
    int row = i >> 5, c4 = i & 31;
    float4 v = ((const float4*)x)[i];
    ((float4*)g_cat)[(size_t)row * 128 + c4] = v;
    store_hilo4(g_catHL + (size_t)row * 1024 + c4 * 4, 512, v);
}

__global__ void prep_ain_kernel(int n, int l) {
    int i = blockIdx.x * blockDim.x + threadIdx.x;
    if (i >= n * 32) return;
    int row = i >> 5, c4 = i & 31;
    float4 a = ((const float4*)g_cat)[(size_t)row * 128 + l * 32 + c4];
    float4 g = ((const float4*)g_agg)[(size_t)row * 32 + c4];
    a.x += g.x; a.y += g.y; a.z += g.z; a.w += g.w;
    store_hilo4(g_a0 + (size_t)row * 256 + c4 * 4, 128, a);
}

__global__ void scatter_kernel(const int* __restrict__ edge, int E, int colOff) {
    int t = blockIdx.x * blockDim.x + threadIdx.x;
    int e = t >> 5;
    if (e >= E) return;
    int lane = t & 31;
    int src = __ldg(edge + e);
    int dst = __ldg(edge + E + e);
    float4 v = *(const float4*)(g_cat + (size_t)src * OCW + colOff + lane * 4);
    float* p = g_agg + (size_t)dst * DD + lane * 4;
    asm volatile("red.global.add.v4.f32 [%0], {%1,%2,%3,%4};"
                 :: "l"(p), "f"(v.x), "f"(v.y), "f"(v.z), "f"(v.w) : "memory");
}

// ---------------- mma.sync GEMM (bf16x3 expanded-K) ----------------
// 128x128 tile, 8 warps (2x4), warp tile 64x32, m16n8k16.
// A bf16 [rows, lda]: hi at col, lo at col+loOffA; expanded e -> src:
//   src = e<K ? e : (e<2K ? e-K : e-2K+loOffA)
// B physically expanded [Nrows, Kex].
// MODE 0: relu(acc+bias) -> outH hi/lo    MODE 1: MODE0 + fp32 to outF
// MODE 3: fused: atomicAdd(outp[row,cblk], dot(relu(acc+bias), W3[cblk]))
template<int MODE>
__global__ void __launch_bounds__(256)
mma_gemm(const __nv_bfloat16* __restrict__ A, int lda, int aChanStride, int loOffA,
         int K, int Kex,
         const __nv_bfloat16* __restrict__ Bx, long bChanStride, int chanWidth,
         const float* __restrict__ bias, int biasChanStride,
         float* __restrict__ outF, int ldF,
         __nv_bfloat16* __restrict__ outH, int ldH, int outHChanStride, int loDeltaOut,
         const float* __restrict__ W3, float* __restrict__ outp, int M)
{
    __shared__ __nv_bfloat16 As[128][72];
    __shared__ __nv_bfloat16 Bs[128][72];

    int tid = threadIdx.x;
    int lane = tid & 31;
    int wid = tid >> 5;
    int warpM = wid & 1;      // 2 row groups of 64
    int warpN = wid >> 1;     // 4 col groups of 32

    int j0 = blockIdx.x * 128;
    int m0 = blockIdx.y * 128;
    int cblk = j0 / chanWidth;
    int jB0 = j0 - cblk * chanWidth;

    const __nv_bfloat16* Ab = A + (size_t)cblk * aChanStride;
    const __nv_bfloat16* Bb = Bx + (size_t)cblk * bChanStride;

    int lrow = tid >> 3;          // 0..31
    int lgrp = tid & 7;           // 8-element column group

    float acc[4][4][4];
#pragma unroll
    for (int i = 0; i < 4; i++)
#pragma unroll
        for (int j = 0; j < 4; j++)
#pragma unroll
            for (int r = 0; r < 4; r++) acc[i][j][r] = 0.f;

    uint32_t asBase = smem_u32(As);
    uint32_t bsBase = smem_u32(Bs);

    const int C = Kex / 64;
    for (int c = 0; c < C; c++) {
        int e = c * 64 + lgrp * 8;
        int srcA = e < K ? e : (e < 2 * K ? e - K : e - 2 * K + loOffA);
        float4 av[4], bv[4];
#pragma unroll
        for (int i = 0; i < 4; i++) {
            av[i] = *(const float4*)(Ab + (size_t)(m0 + lrow + i * 32) * lda + srcA);
            bv[i] = *(const float4*)(Bb + (size_t)(jB0 + lrow + i * 32) * Kex + e);
        }
        if (c) __syncthreads();
#pragma unroll
        for (int i = 0; i < 4; i++) {
            *(float4*)&As[lrow + i * 32][lgrp * 8] = av[i];
            *(float4*)&Bs[lrow + i * 32][lgrp * 8] = bv[i];
        }
        __syncthreads();

#pragma unroll
        for (int ks = 0; ks < 4; ks++) {
            uint32_t af[4][4], bf[2][4];
            int kcol = ks * 16 + (lane >> 4) * 8;
#pragma unroll
            for (int i = 0; i < 4; i++) {
                uint32_t addr = asBase + (uint32_t)(((warpM * 64 + i * 16 + (lane & 15)) * 72 + kcol) * 2);
                LDSM_X4(af[i][0], af[i][1], af[i][2], af[i][3], addr);
            }
#pragma unroll
            for (int jj = 0; jj < 2; jj++) {
                uint32_t addr = bsBase + (uint32_t)(((warpN * 32 + jj * 16 + (lane & 15)) * 72 + kcol) * 2);
                LDSM_X4(bf[jj][0], bf[jj][1], bf[jj][2], bf[jj][3], addr);
            }
#pragma unroll
            for (int i = 0; i < 4; i++)
#pragma unroll
                for (int j = 0; j < 4; j++) {
                    int jj = j >> 1, sel = j & 1;
                    mma16816(acc[i][j], af[i], bf[jj][sel], bf[jj][sel + 2]);
                }
        }
    }

    // ---------------- epilogue ----------------
    int groupID = lane >> 2;
    int tcol = (lane & 3) * 2;

    // per-j column bias / W3
    float bv0[4], bv1[4], wv0[4], wv1[4];
#pragma unroll
    for (int j = 0; j < 4; j++) {
        int colC = jB0 + warpN * 32 + j * 8 + tcol;   // col within channel
        const float* bp = bias + (size_t)cblk * biasChanStride + colC;
        bv0[j] = __ldg(bp);
        bv1[j] = __ldg(bp + 1);
        if (MODE == 3) {
            wv0[j] = __ldg(W3 + (size_t)cblk * CHID + colC);
            wv1[j] = __ldg(W3 + (size_t)cblk * CHID + colC + 1);
        }
    }

#pragma unroll
    for (int i = 0; i < 4; i++) {
        int row0 = m0 + warpM * 64 + i * 16 + groupID;
        int row1 = row0 + 8;
        if (MODE == 3) {
            float p0 = 0.f, p1 = 0.f;
#pragma unroll
            for (int j = 0; j < 4; j++) {
                float v00 = fmaxf(acc[i][j][0] + bv0[j], 0.f);
                float v01 = fmaxf(acc[i][j][1] + bv1[j], 0.f);
                float v10 = fmaxf(acc[i][j][2] + bv0[j], 0.f);
                float v11 = fmaxf(acc[i][j][3] + bv1[j], 0.f);
                p0 += v00 * wv0[j] + v01 * wv1[j];
                p1 += v10 * wv0[j] + v11 * wv1[j];
            }
            p0 += __shfl_xor_sync(0xffffffffu, p0, 1);
            p0 += __shfl_xor_sync(0xffffffffu, p0, 2);
            p1 += __shfl_xor_sync(0xffffffffu, p1, 1);
            p1 += __shfl_xor_sync(0xffffffffu, p1, 2);
            if ((lane & 3) == 0) {
                if (row0 < M) atomicAdd(outp + (size_t)row0 * CHN + cblk, p0);
                if (row1 < M) atomicAdd(outp + (size_t)row1 * CHN + cblk, p1);
            }
        } else {
#pragma unroll
            for (int j = 0; j < 4; j++) {
                int colC = jB0 + warpN * 32 + j * 8 + tcol;
                float v00 = fmaxf(acc[i][j][0] + bv0[j], 0.f);
                float v01 = fmaxf(acc[i][j][1] + bv1[j], 0.f);
                float v10 = fmaxf(acc[i][j][2] + bv0[j], 0.f);
                float v11 = fmaxf(acc[i][j][3] + bv1[j], 0.f);

                __nv_bfloat16 h00 = __float2bfloat16(v00), h01 = __float2bfloat16(v01);
                __nv_bfloat16 h10 = __float2bfloat16(v10), h11 = __float2bfloat16(v11);
                __nv_bfloat16* p0h = outH + (size_t)row0 * ldH + cblk * outHChanStride + colC;
                __nv_bfloat16* p1h = outH + (size_t)row1 * ldH + cblk * outHChanStride + colC;
                *(__nv_bfloat162*)p0h = __nv_bfloat162(h00, h01);
                *(__nv_bfloat162*)p1h = __nv_bfloat162(h10, h11);
                __nv_bfloat16 l00 = __float2bfloat16(v00 - __bfloat162float(h00));
                __nv_bfloat16 l01 = __float2bfloat16(v01 - __bfloat162float(h01));
                __nv_bfloat16 l10 = __float2bfloat16(v10 - __bfloat162float(h10));
                __nv_bfloat16 l11 = __float2bfloat16(v11 - __bfloat162float(h11));
                *(__nv_bfloat162*)(p0h + loDeltaOut) = __nv_bfloat162(l00, l01);
                *(__nv_bfloat162*)(p1h + loDeltaOut) = __nv_bfloat162(l10, l11);

                if (MODE == 1) {
                    int gcol = j0 + warpN * 32 + j * 8 + tcol;
                    *(float2*)(outF + (size_t)row0 * ldF + gcol) = make_float2(v00, v01);
                    *(float2*)(outF + (size_t)row1 * ldF + gcol) = make_float2(v10, v11);
                }
            }
        }
    }
}

__global__ void out_bias_relu_kernel(float* __restrict__ out, const float* __restrict__ b3, int n) {
    int i = blockIdx.x * blockDim.x + threadIdx.x;
    if (i >= n * CHN) return;
    float v = out[i] + b3[i & (CHN - 1)];
    out[i] = v > 0.f ? v : 0.f;
}

// ---------------- launch ----------------
extern "C" void kernel_launch(void* const* d_in, const int* in_sizes, int n_in,
                              void* d_out, int out_size)
{
    const float* x     = (const float*)d_in[0];
    const int*   edge  = (const int*)  d_in[1];
    const float* convW = (const float*)d_in[2];
    const float* convB = (const float*)d_in[3];
    const float* cW1   = (const float*)d_in[4];
    const float* cB1   = (const float*)d_in[5];
    const float* cW2   = (const float*)d_in[6];
    const float* cB2   = (const float*)d_in[7];
    const float* cW3   = (const float*)d_in[8];
    const float* cB3   = (const float*)d_in[9];
    float* out = (float*)d_out;

    int n = in_sizes[0] / DD;
    int E = in_sizes[1] / 2;

    float *cat, *agg;
    __nv_bfloat16 *convWex, *W1ex, *W2ex, *catHL, *a0, *t0, *t1, *H1;
    cudaGetSymbolAddress((void**)&cat, g_cat);
    cudaGetSymbolAddress((void**)&agg, g_agg);
    cudaGetSymbolAddress((void**)&catHL, g_catHL);
    cudaGetSymbolAddress((void**)&a0, g_a0);
    cudaGetSymbolAddress((void**)&t0, g_t0);
    cudaGetSymbolAddress((void**)&t1, g_t1);
    cudaGetSymbolAddress((void**)&H1, g_H1);
    cudaGetSymbolAddress((void**)&convWex, g_convWex);
    cudaGetSymbolAddress((void**)&W1ex, g_W1ex);
    cudaGetSymbolAddress((void**)&W2ex, g_W2ex);

    const int mBlocks = (n + 127) / 128;
    const int BIG = 1 << 30;

    // weight expansion
    { dim3 g((128 * 128 + 255) / 256, 9); expand_w_kernel<<<g, 256>>>(convW, convWex, 128, 128); }
    { dim3 g((512 * 256 + 255) / 256, CHN); expand_w_kernel<<<g, 256>>>(cW1, W1ex, 512, 256); }
    { dim3 g((256 * 256 + 255) / 256, CHN); expand_w_kernel<<<g, 256>>>(cW2, W2ex, 256, 256); }

    prep_x_kernel<<<(n * 32 + 255) / 256, 256>>>(x, n);

    for (int l = 0; l < LL; l++) {
        cudaMemsetAsync(agg, 0, (size_t)n * DD * sizeof(float), 0);
        {
            long th = (long)E * 32;
            scatter_kernel<<<(int)((th + 255) / 256), 256>>>(edge, E, l * DD);
        }
        prep_ain_kernel<<<(n * 32 + 255) / 256, 256>>>(n, l);

        const float* b0 = convB + (size_t)(l * 3 + 0) * DD;
        const float* b1 = convB + (size_t)(l * 3 + 1) * DD;
        const float* b2 = convB + (size_t)(l * 3 + 2) * DD;
        const __nv_bfloat16* B0 = convWex + (size_t)(l * 3 + 0) * 128 * 384;
        const __nv_bfloat16* B1 = convWex + (size_t)(l * 3 + 1) * 128 * 384;
        const __nv_bfloat16* B2 = convWex + (size_t)(l * 3 + 2) * 128 * 384;

        dim3 grid(1, mBlocks);
        mma_gemm<0><<<grid, 256>>>(a0, 256, 0, 128, 128, 384, B0, 0, BIG, b0, 0,
                                   nullptr, 0, t0, 256, 0, 128, nullptr, nullptr, n);
        mma_gemm<0><<<grid, 256>>>(t0, 256, 0, 128, 128, 384, B1, 0, BIG, b1, 0,
                                   nullptr, 0, t1, 256, 0, 128, nullptr, nullptr, n);
        mma_gemm<1><<<grid, 256>>>(t1, 256, 0, 128, 128, 384, B2, 0, BIG, b2, 0,
                                   cat + (l + 1) * DD, OCW,
                                   catHL + (l + 1) * DD, 1024, 0, 512, nullptr, nullptr, n);
    }

    // channel MLP layer 1
    {
        dim3 grid((CHN * CHID) / 128, mBlocks);
        mma_gemm<0><<<grid, 256>>>(catHL, 1024, 0, 512, 512, 1536,
                                   W1ex, (long)256 * 1536, CHID, cB1, CHID,
                                   nullptr, 0, H1, 2048, 256, 1024, nullptr, nullptr, n);
    }

    // channel MLP layer 2 + fused final dot
    cudaMemsetAsync(out, 0, (size_t)n * CHN * sizeof(float), 0);
    {
        dim3 grid((CHN * CHID) / 128, mBlocks);
        mma_gemm<3><<<grid, 256>>>(H1, 2048, 256, 1024, 256, 768,
                                   W2ex, (long)256 * 768, CHID, cB2, CHID,
                                   nullptr, 0, nullptr, 0, 0, 0, cW3, out, n);
    }

    out_bias_relu_kernel<<<(n * CHN + 255) / 256, 256>>>(out, cB3, n);
}

// round 5
// speedup vs baseline: 2.5453x; 1.2782x over previous
#include <cuda_runtime.h>
#include <cuda_bf16.h>
#include <cstdint>

// Problem constants
#define NMAX   100000
#define NPAD   100128
#define DD     128
#define LL     3
#define OCW    512
#define CHN    4
#define CHID   256
#define EMAX   2000000

// ---------------- static device scratch ----------------
__device__ float g_cat[(size_t)NPAD * OCW];
__device__ __nv_bfloat16 g_catHL[(size_t)NPAD * 1024];  // [hi 512 | lo 512]
__device__ __nv_bfloat16 g_a0  [(size_t)NPAD * 256];    // [hi128|lo128]
__device__ __nv_bfloat16 g_t0  [(size_t)NPAD * 256];
__device__ __nv_bfloat16 g_t1  [(size_t)NPAD * 256];
__device__ __nv_bfloat16 g_H1  [(size_t)NPAD * 2048];   // [hi1024|lo1024]
__device__ __nv_bfloat16 g_convWex[(size_t)9 * 128 * 384];
__device__ __nv_bfloat16 g_W1ex  [(size_t)CHN * 256 * 1536];
__device__ __nv_bfloat16 g_W2ex  [(size_t)CHN * 256 * 768];
// CSR (built once per call; graph identical across layers)
__device__ int g_cnt   [NPAD + 1];
__device__ int g_rowptr[NPAD + 1];
__device__ int g_wp    [NPAD + 1];
__device__ int g_bsum  [256];
__device__ int g_csr   [EMAX];

// ---------------- helpers ----------------
__device__ __forceinline__ uint32_t smem_u32(const void* p) {
    uint32_t r;
    asm("{ .reg .u64 t; cvta.to.shared.u64 t, %1; cvt.u32.u64 %0, t; }" : "=r"(r) : "l"(p));
    return r;
}
#define LDSM_X4(r0, r1, r2, r3, addr) \
    asm volatile("ldmatrix.sync.aligned.m8n8.x4.shared.b16 {%0,%1,%2,%3}, [%4];" \
        : "=r"(r0), "=r"(r1), "=r"(r2), "=r"(r3) : "r"(addr))

__device__ __forceinline__ void mma16816(float* c, const uint32_t* a, uint32_t b0, uint32_t b1) {
    asm volatile(
        "mma.sync.aligned.m16n8k16.row.col.f32.bf16.bf16.f32 "
        "{%0,%1,%2,%3}, {%4,%5,%6,%7}, {%8,%9}, {%0,%1,%2,%3};"
        : "+f"(c[0]), "+f"(c[1]), "+f"(c[2]), "+f"(c[3])
        : "r"(a[0]), "r"(a[1]), "r"(a[2]), "r"(a[3]), "r"(b0), "r"(b1));
}

// ---------------- weight expansion: W[K,N] fp32 -> Bex[N,3K] = [hi|lo|hi] ----------------
__global__ void expand_w_kernel(const float* __restrict__ W, __nv_bfloat16* __restrict__ Bex,
                                int K, int N) {
    int mi = blockIdx.y;
    const float* Wm = W + (size_t)mi * K * N;
    __nv_bfloat16* Bm = Bex + (size_t)mi * N * 3 * K;
    int id = blockIdx.x * blockDim.x + threadIdx.x;
    if (id >= K * N) return;
    int k = id / N, n = id % N;
    float w = Wm[id];
    __nv_bfloat16 hi = __float2bfloat16(w);
    __nv_bfloat16 lo = __float2bfloat16(w - __bfloat162float(hi));
    Bm[(size_t)n * 3 * K + k]         = hi;
    Bm[(size_t)n * 3 * K + K + k]     = lo;
    Bm[(size_t)n * 3 * K + 2 * K + k] = hi;
}

__device__ __forceinline__ void store_hilo4(__nv_bfloat16* p, int loDelta, float4 v) {
    __nv_bfloat16 h0 = __float2bfloat16(v.x), h1 = __float2bfloat16(v.y);
    __nv_bfloat16 h2 = __float2bfloat16(v.z), h3 = __float2bfloat16(v.w);
    ((__nv_bfloat162*)p)[0] = __nv_bfloat162(h0, h1);
    ((__nv_bfloat162*)p)[1] = __nv_bfloat162(h2, h3);
    __nv_bfloat16 l0 = __float2bfloat16(v.x - __bfloat162float(h0));
    __nv_bfloat16 l1 = __float2bfloat16(v.y - __bfloat162float(h1));
    __nv_bfloat16 l2 = __float2bfloat16(v.z - __bfloat162float(h2));
    __nv_bfloat16 l3 = __float2bfloat16(v.w - __bfloat162float(h3));
    ((__nv_bfloat162*)(p + loDelta))[0] = __nv_bfloat162(l0, l1);
    ((__nv_bfloat162*)(p + loDelta))[1] = __nv_bfloat162(l2, l3);
}

__global__ void prep_x_kernel(const float* __restrict__ x, int n) {
    int i = blockIdx.x * blockDim.x + threadIdx.x;
    if (i >= n * 32) return;
    int row = i >> 5, c4 = i & 31;
    float4 v = ((const float4*)x)[i];
    ((float4*)g_cat)[(size_t)row * 128 + c4] = v;
    store_hilo4(g_catHL + (size_t)row * 1024 + c4 * 4, 512, v);
}

// ---------------- CSR build ----------------
__global__ void hist_kernel(const int* __restrict__ edge, int E) {
    int e = blockIdx.x * blockDim.x + threadIdx.x;
    if (e < E) atomicAdd(&g_cnt[__ldg(edge + E + e)], 1);
}
// per-block exclusive scan of 1024 elems (256 thr x 4)
__global__ void scan1_kernel(int n) {
    __shared__ int warpSums[8];
    int t = threadIdx.x;
    int base = blockIdx.x * 1024 + t * 4;
    int v[4];
#pragma unroll
    for (int j = 0; j < 4; j++) v[j] = (base + j < n) ? g_cnt[base + j] : 0;
    int tsum = v[0] + v[1] + v[2] + v[3];
    int lane = t & 31, w = t >> 5;
    int x = tsum;
#pragma unroll
    for (int o = 1; o < 32; o <<= 1) {
        int y = __shfl_up_sync(0xffffffffu, x, o);
        if (lane >= o) x += y;
    }
    int excl = x - tsum;
    if (lane == 31) warpSums[w] = x;
    __syncthreads();
    if (t == 0) {
        int run = 0;
#pragma unroll
        for (int i = 0; i < 8; i++) { int tm = warpSums[i]; warpSums[i] = run; run += tm; }
        g_bsum[blockIdx.x] = run;
    }
    __syncthreads();
    int off = warpSums[w] + excl;
#pragma unroll
    for (int j = 0; j < 4; j++) {
        if (base + j < n) g_rowptr[base + j] = off;
        off += v[j];
    }
}
__global__ void scan2_kernel(int nb) {
    if (threadIdx.x == 0) {
        int run = 0;
        for (int i = 0; i < nb; i++) { int t = g_bsum[i]; g_bsum[i] = run; run += t; }
    }
}
__global__ void scan3_kernel(int n, int E) {
    int i = blockIdx.x * blockDim.x + threadIdx.x;
    if (i < n) {
        int v = g_rowptr[i] + g_bsum[i >> 10];
        g_rowptr[i] = v;
        g_wp[i] = v;
    }
    if (i == 0) g_rowptr[n] = E;
}
__global__ void fill_kernel(const int* __restrict__ edge, int E) {
    int e = blockIdx.x * blockDim.x + threadIdx.x;
    if (e >= E) return;
    int s = __ldg(edge + e);
    int d = __ldg(edge + E + e);
    int pos = atomicAdd(&g_wp[d], 1);
    g_csr[pos] = s;
}

// ---------------- gather + prep fused: a0[w] = hilo( cat[w] + sum_{src in N(w)} cat[src] ) ----------------
__global__ void gather_kernel(int n, int colOff) {
    int w = (blockIdx.x * blockDim.x + threadIdx.x) >> 5;
    if (w >= n) return;
    int lane = threadIdx.x & 31;
    int beg = __ldg(&g_rowptr[w]);
    int end = __ldg(&g_rowptr[w + 1]);
    const float* base = g_cat + colOff + lane * 4;
    float4 s = *(const float4*)(base + (size_t)w * OCW);
    int i = beg;
    for (; i + 1 < end; i += 2) {
        int s0 = __ldg(&g_csr[i]);
        int s1 = __ldg(&g_csr[i + 1]);
        float4 v0 = *(const float4*)(base + (size_t)s0 * OCW);
        float4 v1 = *(const float4*)(base + (size_t)s1 * OCW);
        s.x += v0.x; s.y += v0.y; s.z += v0.z; s.w += v0.w;
        s.x += v1.x; s.y += v1.y; s.z += v1.z; s.w += v1.w;
    }
    if (i < end) {
        int s0 = __ldg(&g_csr[i]);
        float4 v0 = *(const float4*)(base + (size_t)s0 * OCW);
        s.x += v0.x; s.y += v0.y; s.z += v0.z; s.w += v0.w;
    }
    store_hilo4(g_a0 + (size_t)w * 256 + lane * 4, 128, s);
}

// ---------------- mma.sync GEMM (bf16x3 expanded-K), software-pipelined ----------------
template<int MODE>
__global__ void __launch_bounds__(256)
mma_gemm(const __nv_bfloat16* __restrict__ A, int lda, int aChanStride, int loOffA,
         int K, int Kex,
         const __nv_bfloat16* __restrict__ Bx, long bChanStride, int chanWidth,
         const float* __restrict__ bias, int biasChanStride,
         float* __restrict__ outF, int ldF,
         __nv_bfloat16* __restrict__ outH, int ldH, int outHChanStride, int loDeltaOut,
         const float* __restrict__ W3, float* __restrict__ outp, int M)
{
    __shared__ __nv_bfloat16 As[128][72];
    __shared__ __nv_bfloat16 Bs[128][72];

    int tid = threadIdx.x;
    int lane = tid & 31;
    int wid = tid >> 5;
    int warpM = wid & 1;
    int warpN = wid >> 1;

    int j0 = blockIdx.x * 128;
    int m0 = blockIdx.y * 128;
    int cblk = j0 / chanWidth;
    int jB0 = j0 - cblk * chanWidth;

    const __nv_bfloat16* Ab = A + (size_t)cblk * aChanStride;
    const __nv_bfloat16* Bb = Bx + (size_t)cblk * bChanStride;

    int lrow = tid >> 3;
    int lgrp = tid & 7;

    float acc[4][4][4];
#pragma unroll
    for (int i = 0; i < 4; i++)
#pragma unroll
        for (int j = 0; j < 4; j++)
#pragma unroll
            for (int r = 0; r < 4; r++) acc[i][j][r] = 0.f;

    uint32_t asBase = smem_u32(As);
    uint32_t bsBase = smem_u32(Bs);

    float4 av[4], bv[4];
    auto LOAD = [&](int c) {
        int e = c * 64 + lgrp * 8;
        int srcA = e < K ? e : (e < 2 * K ? e - K : e - 2 * K + loOffA);
#pragma unroll
        for (int i = 0; i < 4; i++) {
            av[i] = *(const float4*)(Ab + (size_t)(m0 + lrow + i * 32) * lda + srcA);
            bv[i] = *(const float4*)(Bb + (size_t)(jB0 + lrow + i * 32) * Kex + e);
        }
    };

    const int C = Kex / 64;
    LOAD(0);
    for (int c = 0; c < C; c++) {
        if (c) __syncthreads();
#pragma unroll
        for (int i = 0; i < 4; i++) {
            *(float4*)&As[lrow + i * 32][lgrp * 8] = av[i];
            *(float4*)&Bs[lrow + i * 32][lgrp * 8] = bv[i];
        }
        __syncthreads();
        if (c + 1 < C) LOAD(c + 1);   // LDG latency hidden behind this chunk's MMAs

#pragma unroll
        for (int ks = 0; ks < 4; ks++) {
            uint32_t af[4][4], bf[2][4];
            int kcol = ks * 16 + (lane >> 4) * 8;
#pragma unroll
            for (int i = 0; i < 4; i++) {
                uint32_t addr = asBase + (uint32_t)(((warpM * 64 + i * 16 + (lane & 15)) * 72 + kcol) * 2);
                LDSM_X4(af[i][0], af[i][1], af[i][2], af[i][3], addr);
            }
#pragma unroll
            for (int jj = 0; jj < 2; jj++) {
                uint32_t addr = bsBase + (uint32_t)(((warpN * 32 + jj * 16 + (lane & 15)) * 72 + kcol) * 2);
                LDSM_X4(bf[jj][0], bf[jj][1], bf[jj][2], bf[jj][3], addr);
            }
#pragma unroll
            for (int i = 0; i < 4; i++)
#pragma unroll
                for (int j = 0; j < 4; j++) {
                    int jj = j >> 1, sel = j & 1;
                    mma16816(acc[i][j], af[i], bf[jj][sel], bf[jj][sel + 2]);
                }
        }
    }

    // ---------------- epilogue ----------------
    int groupID = lane >> 2;
    int tcol = (lane & 3) * 2;

    float bv0[4], bv1[4], wv0[4], wv1[4];
#pragma unroll
    for (int j = 0; j < 4; j++) {
        int colC = jB0 + warpN * 32 + j * 8 + tcol;
        const float* bp = bias + (size_t)cblk * biasChanStride + colC;
        bv0[j] = __ldg(bp);
        bv1[j] = __ldg(bp + 1);
        if (MODE == 3) {
            wv0[j] = __ldg(W3 + (size_t)cblk * CHID + colC);
            wv1[j] = __ldg(W3 + (size_t)cblk * CHID + colC + 1);
        }
    }

#pragma unroll
    for (int i = 0; i < 4; i++) {
        int row0 = m0 + warpM * 64 + i * 16 + groupID;
        int row1 = row0 + 8;
        if (MODE == 3) {
            float p0 = 0.f, p1 = 0.f;
#pragma unroll
            for (int j = 0; j < 4; j++) {
                float v00 = fmaxf(acc[i][j][0] + bv0[j], 0.f);
                float v01 = fmaxf(acc[i][j][1] + bv1[j], 0.f);
                float v10 = fmaxf(acc[i][j][2] + bv0[j], 0.f);
                float v11 = fmaxf(acc[i][j][3] + bv1[j], 0.f);
                p0 += v00 * wv0[j] + v01 * wv1[j];
                p1 += v10 * wv0[j] + v11 * wv1[j];
            }
            p0 += __shfl_xor_sync(0xffffffffu, p0, 1);
            p0 += __shfl_xor_sync(0xffffffffu, p0, 2);
            p1 += __shfl_xor_sync(0xffffffffu, p1, 1);
            p1 += __shfl_xor_sync(0xffffffffu, p1, 2);
            if ((lane & 3) == 0) {
                if (row0 < M) atomicAdd(outp + (size_t)row0 * CHN + cblk, p0);
                if (row1 < M) atomicAdd(outp + (size_t)row1 * CHN + cblk, p1);
            }
        } else {
#pragma unroll
            for (int j = 0; j < 4; j++) {
                int colC = jB0 + warpN * 32 + j * 8 + tcol;
                float v00 = fmaxf(acc[i][j][0] + bv0[j], 0.f);
                float v01 = fmaxf(acc[i][j][1] + bv1[j], 0.f);
                float v10 = fmaxf(acc[i][j][2] + bv0[j], 0.f);
                float v11 = fmaxf(acc[i][j][3] + bv1[j], 0.f);

                __nv_bfloat16 h00 = __float2bfloat16(v00), h01 = __float2bfloat16(v01);
                __nv_bfloat16 h10 = __float2bfloat16(v10), h11 = __float2bfloat16(v11);
                __nv_bfloat16* p0h = outH + (size_t)row0 * ldH + cblk * outHChanStride + colC;
                __nv_bfloat16* p1h = outH + (size_t)row1 * ldH + cblk * outHChanStride + colC;
                *(__nv_bfloat162*)p0h = __nv_bfloat162(h00, h01);
                *(__nv_bfloat162*)p1h = __nv_bfloat162(h10, h11);
                __nv_bfloat16 l00 = __float2bfloat16(v00 - __bfloat162float(h00));
                __nv_bfloat16 l01 = __float2bfloat16(v01 - __bfloat162float(h01));
                __nv_bfloat16 l10 = __float2bfloat16(v10 - __bfloat162float(h10));
                __nv_bfloat16 l11 = __float2bfloat16(v11 - __bfloat162float(h11));
                *(__nv_bfloat162*)(p0h + loDeltaOut) = __nv_bfloat162(l00, l01);
                *(__nv_bfloat162*)(p1h + loDeltaOut) = __nv_bfloat162(l10, l11);

                if (MODE == 1) {
                    int gcol = j0 + warpN * 32 + j * 8 + tcol;
                    *(float2*)(outF + (size_t)row0 * ldF + gcol) = make_float2(v00, v01);
                    *(float2*)(outF + (size_t)row1 * ldF + gcol) = make_float2(v10, v11);
                }
            }
        }
    }
}

__global__ void out_bias_relu_kernel(float* __restrict__ out, const float* __restrict__ b3, int n) {
    int i = blockIdx.x * blockDim.x + threadIdx.x;
    if (i >= n * CHN) return;
    float v = out[i] + b3[i & (CHN - 1)];
    out[i] = v > 0.f ? v : 0.f;
}

// ---------------- launch ----------------
extern "C" void kernel_launch(void* const* d_in, const int* in_sizes, int n_in,
                              void* d_out, int out_size)
{
    const float* x     = (const float*)d_in[0];
    const int*   edge  = (const int*)  d_in[1];
    const float* convW = (const float*)d_in[2];
    const float* convB = (const float*)d_in[3];
    const float* cW1   = (const float*)d_in[4];
    const float* cB1   = (const float*)d_in[5];
    const float* cW2   = (const float*)d_in[6];
    const float* cB2   = (const float*)d_in[7];
    const float* cW3   = (const float*)d_in[8];
    const float* cB3   = (const float*)d_in[9];
    float* out = (float*)d_out;

    int n = in_sizes[0] / DD;
    int E = in_sizes[1] / 2;

    float *cat;
    __nv_bfloat16 *convWex, *W1ex, *W2ex, *catHL, *a0, *t0, *t1, *H1;
    int *cnt;
    cudaGetSymbolAddress((void**)&cat, g_cat);
    cudaGetSymbolAddress((void**)&catHL, g_catHL);
    cudaGetSymbolAddress((void**)&a0, g_a0);
    cudaGetSymbolAddress((void**)&t0, g_t0);
    cudaGetSymbolAddress((void**)&t1, g_t1);
    cudaGetSymbolAddress((void**)&H1, g_H1);
    cudaGetSymbolAddress((void**)&convWex, g_convWex);
    cudaGetSymbolAddress((void**)&W1ex, g_W1ex);
    cudaGetSymbolAddress((void**)&W2ex, g_W2ex);
    cudaGetSymbolAddress((void**)&cnt, g_cnt);

    const int mBlocks = (n + 127) / 128;
    const int BIG = 1 << 30;

    // weight expansion
    { dim3 g((128 * 128 + 255) / 256, 9); expand_w_kernel<<<g, 256>>>(convW, convWex, 128, 128); }
    { dim3 g((512 * 256 + 255) / 256, CHN); expand_w_kernel<<<g, 256>>>(cW1, W1ex, 512, 256); }
    { dim3 g((256 * 256 + 255) / 256, CHN); expand_w_kernel<<<g, 256>>>(cW2, W2ex, 256, 256); }

    prep_x_kernel<<<(n * 32 + 255) / 256, 256>>>(x, n);

    // ---- CSR build (once; reused by all 3 layers) ----
    cudaMemsetAsync(cnt, 0, (size_t)(n + 1) * sizeof(int), 0);
    hist_kernel<<<(E + 255) / 256, 256>>>(edge, E);
    int nb = (n + 1023) / 1024;
    scan1_kernel<<<nb, 256>>>(n);
    scan2_kernel<<<1, 32>>>(nb);
    scan3_kernel<<<(n + 255) / 256, 256>>>(n, E);
    fill_kernel<<<(E + 255) / 256, 256>>>(edge, E);

    for (int l = 0; l < LL; l++) {
        {
            long th = (long)n * 32;
            gather_kernel<<<(int)((th + 255) / 256), 256>>>(n, l * DD);
        }

        const float* b0 = convB + (size_t)(l * 3 + 0) * DD;
        const float* b1 = convB + (size_t)(l * 3 + 1) * DD;
        const float* b2 = convB + (size_t)(l * 3 + 2) * DD;
        const __nv_bfloat16* B0 = convWex + (size_t)(l * 3 + 0) * 128 * 384;
        const __nv_bfloat16* B1 = convWex + (size_t)(l * 3 + 1) * 128 * 384;
        const __nv_bfloat16* B2 = convWex + (size_t)(l * 3 + 2) * 128 * 384;

        dim3 grid(1, mBlocks);
        mma_gemm<0><<<grid, 256>>>(a0, 256, 0, 128, 128, 384, B0, 0, BIG, b0, 0,
                                   nullptr, 0, t0, 256, 0, 128, nullptr, nullptr, n);
        mma_gemm<0><<<grid, 256>>>(t0, 256, 0, 128, 128, 384, B1, 0, BIG, b1, 0,
                                   nullptr, 0, t1, 256, 0, 128, nullptr, nullptr, n);
        mma_gemm<1><<<grid, 256>>>(t1, 256, 0, 128, 128, 384, B2, 0, BIG, b2, 0,
                                   cat + (l + 1) * DD, OCW,
                                   catHL + (l + 1) * DD, 1024, 0, 512, nullptr, nullptr, n);
    }

    // channel MLP layer 1
    {
        dim3 grid((CHN * CHID) / 128, mBlocks);
        mma_gemm<0><<<grid, 256>>>(catHL, 1024, 0, 512, 512, 1536,
                                   W1ex, (long)256 * 1536, CHID, cB1, CHID,
                                   nullptr, 0, H1, 2048, 256, 1024, nullptr, nullptr, n);
    }

    // channel MLP layer 2 + fused final dot
    cudaMemsetAsync(out, 0, (size_t)n * CHN * sizeof(float), 0);
    {
        dim3 grid((CHN * CHID) / 128, mBlocks);
        mma_gemm<3><<<grid, 256>>>(H1, 2048, 256, 1024, 256, 768,
                                   W2ex, (long)256 * 768, CHID, cB2, CHID,
                                   nullptr, 0, nullptr, 0, 0, 0, cW3, out, n);
    }

    out_bias_relu_kernel<<<(n * CHN + 255) / 256, 256>>>(out, cB3, n);
}

// round 6
// speedup vs baseline: 2.6005x; 1.0217x over previous
#include <cuda_runtime.h>
#include <cuda_bf16.h>
#include <cstdint>

// Problem constants
#define NMAX   100000
#define NPAD   100128
#define DD     128
#define LL     3
#define OCW    512
#define CHN    4
#define CHID   256
#define EMAX   2000000

// ---------------- static device scratch ----------------
__device__ float g_cat[(size_t)NPAD * OCW];
__device__ __nv_bfloat16 g_catHL[(size_t)NPAD * 1024];  // [hi 512 | lo 512]
__device__ __nv_bfloat16 g_a0  [(size_t)NPAD * 256];    // [hi128|lo128]
__device__ __nv_bfloat16 g_t0  [(size_t)NPAD * 256];
__device__ __nv_bfloat16 g_t1  [(size_t)NPAD * 256];
__device__ __nv_bfloat16 g_H1  [(size_t)NPAD * 2048];   // [hi1024|lo1024]
__device__ __nv_bfloat16 g_convWex[(size_t)9 * 128 * 384];
__device__ __nv_bfloat16 g_W1ex  [(size_t)CHN * 256 * 1536];
__device__ __nv_bfloat16 g_W2ex  [(size_t)CHN * 256 * 768];
// CSR
__device__ int g_cnt   [NPAD + 1];
__device__ int g_rowptr[NPAD + 1];
__device__ int g_wp    [NPAD + 1];
__device__ int g_bsum  [256];
__device__ int g_csr   [EMAX];

// ---------------- helpers ----------------
__device__ __forceinline__ uint32_t smem_u32(const void* p) {
    uint32_t r;
    asm("{ .reg .u64 t; cvta.to.shared.u64 t, %1; cvt.u32.u64 %0, t; }" : "=r"(r) : "l"(p));
    return r;
}
#define LDSM_X4(r0, r1, r2, r3, addr) \
    asm volatile("ldmatrix.sync.aligned.m8n8.x4.shared.b16 {%0,%1,%2,%3}, [%4];" \
        : "=r"(r0), "=r"(r1), "=r"(r2), "=r"(r3) : "r"(addr))

__device__ __forceinline__ void mma16816(float* c, const uint32_t* a, uint32_t b0, uint32_t b1) {
    asm volatile(
        "mma.sync.aligned.m16n8k16.row.col.f32.bf16.bf16.f32 "
        "{%0,%1,%2,%3}, {%4,%5,%6,%7}, {%8,%9}, {%0,%1,%2,%3};"
        : "+f"(c[0]), "+f"(c[1]), "+f"(c[2]), "+f"(c[3])
        : "r"(a[0]), "r"(a[1]), "r"(a[2]), "r"(a[3]), "r"(b0), "r"(b1));
}
__device__ __forceinline__ void cp16(uint32_t dst, const void* src) {
    asm volatile("cp.async.cg.shared.global [%0], [%1], 16;" :: "r"(dst), "l"(src));
}
#define CP_COMMIT() asm volatile("cp.async.commit_group;" ::: "memory")

// ---------------- weight expansion ----------------
__global__ void expand_w_kernel(const float* __restrict__ W, __nv_bfloat16* __restrict__ Bex,
                                int K, int N) {
    int mi = blockIdx.y;
    const float* Wm = W + (size_t)mi * K * N;
    __nv_bfloat16* Bm = Bex + (size_t)mi * N * 3 * K;
    int id = blockIdx.x * blockDim.x + threadIdx.x;
    if (id >= K * N) return;
    int k = id / N, n = id % N;
    float w = Wm[id];
    __nv_bfloat16 hi = __float2bfloat16(w);
    __nv_bfloat16 lo = __float2bfloat16(w - __bfloat162float(hi));
    Bm[(size_t)n * 3 * K + k]         = hi;
    Bm[(size_t)n * 3 * K + K + k]     = lo;
    Bm[(size_t)n * 3 * K + 2 * K + k] = hi;
}

__device__ __forceinline__ void store_hilo4(__nv_bfloat16* p, int loDelta, float4 v) {
    __nv_bfloat16 h0 = __float2bfloat16(v.x), h1 = __float2bfloat16(v.y);
    __nv_bfloat16 h2 = __float2bfloat16(v.z), h3 = __float2bfloat16(v.w);
    ((__nv_bfloat162*)p)[0] = __nv_bfloat162(h0, h1);
    ((__nv_bfloat162*)p)[1] = __nv_bfloat162(h2, h3);
    __nv_bfloat16 l0 = __float2bfloat16(v.x - __bfloat162float(h0));
    __nv_bfloat16 l1 = __float2bfloat16(v.y - __bfloat162float(h1));
    __nv_bfloat16 l2 = __float2bfloat16(v.z - __bfloat162float(h2));
    __nv_bfloat16 l3 = __float2bfloat16(v.w - __bfloat162float(h3));
    ((__nv_bfloat162*)(p + loDelta))[0] = __nv_bfloat162(l0, l1);
    ((__nv_bfloat162*)(p + loDelta))[1] = __nv_bfloat162(l2, l3);
}

__global__ void prep_x_kernel(const float* __restrict__ x, int n) {
    int i = blockIdx.x * blockDim.x + threadIdx.x;
    if (i >= n * 32) return;
    int row = i >> 5, c4 = i & 31;
    float4 v = ((const float4*)x)[i];
    ((float4*)g_cat)[(size_t)row * 128 + c4] = v;
    store_hilo4(g_catHL + (size_t)row * 1024 + c4 * 4, 512, v);
}

// ---------------- CSR build ----------------
__global__ void hist_kernel(const int* __restrict__ edge, int E) {
    int e = blockIdx.x * blockDim.x + threadIdx.x;
    if (e < E) atomicAdd(&g_cnt[__ldg(edge + E + e)], 1);
}
__global__ void scan1_kernel(int n) {
    __shared__ int warpSums[8];
    int t = threadIdx.x;
    int base = blockIdx.x * 1024 + t * 4;
    int v[4];
#pragma unroll
    for (int j = 0; j < 4; j++) v[j] = (base + j < n) ? g_cnt[base + j] : 0;
    int tsum = v[0] + v[1] + v[2] + v[3];
    int lane = t & 31, w = t >> 5;
    int x = tsum;
#pragma unroll
    for (int o = 1; o < 32; o <<= 1) {
        int y = __shfl_up_sync(0xffffffffu, x, o);
        if (lane >= o) x += y;
    }
    int excl = x - tsum;
    if (lane == 31) warpSums[w] = x;
    __syncthreads();
    if (t == 0) {
        int run = 0;
#pragma unroll
        for (int i = 0; i < 8; i++) { int tm = warpSums[i]; warpSums[i] = run; run += tm; }
        g_bsum[blockIdx.x] = run;
    }
    __syncthreads();
    int off = warpSums[w] + excl;
#pragma unroll
    for (int j = 0; j < 4; j++) {
        if (base + j < n) g_rowptr[base + j] = off;
        off += v[j];
    }
}
__global__ void scan2_kernel(int nb) {
    if (threadIdx.x == 0) {
        int run = 0;
        for (int i = 0; i < nb; i++) { int t = g_bsum[i]; g_bsum[i] = run; run += t; }
    }
}
__global__ void scan3_kernel(int n, int E) {
    int i = blockIdx.x * blockDim.x + threadIdx.x;
    if (i < n) {
        int v = g_rowptr[i] + g_bsum[i >> 10];
        g_rowptr[i] = v;
        g_wp[i] = v;
    }
    if (i == 0) g_rowptr[n] = E;
}
__global__ void fill_kernel(const int* __restrict__ edge, int E) {
    int e = blockIdx.x * blockDim.x + threadIdx.x;
    if (e >= E) return;
    int s = __ldg(edge + e);
    int d = __ldg(edge + E + e);
    int pos = atomicAdd(&g_wp[d], 1);
    g_csr[pos] = s;
}

// ---------------- gather + prep fused ----------------
__global__ void gather_kernel(int n, int colOff) {
    int w = (blockIdx.x * blockDim.x + threadIdx.x) >> 5;
    if (w >= n) return;
    int lane = threadIdx.x & 31;
    int beg = __ldg(&g_rowptr[w]);
    int end = __ldg(&g_rowptr[w + 1]);
    const float* base = g_cat + colOff + lane * 4;
    float4 s = *(const float4*)(base + (size_t)w * OCW);
    int i = beg;
    for (; i + 1 < end; i += 2) {
        int s0 = __ldg(&g_csr[i]);
        int s1 = __ldg(&g_csr[i + 1]);
        float4 v0 = *(const float4*)(base + (size_t)s0 * OCW);
        float4 v1 = *(const float4*)(base + (size_t)s1 * OCW);
        s.x += v0.x; s.y += v0.y; s.z += v0.z; s.w += v0.w;
        s.x += v1.x; s.y += v1.y; s.z += v1.z; s.w += v1.w;
    }
    if (i < end) {
        int s0 = __ldg(&g_csr[i]);
        float4 v0 = *(const float4*)(base + (size_t)s0 * OCW);
        s.x += v0.x; s.y += v0.y; s.z += v0.z; s.w += v0.w;
    }
    store_hilo4(g_a0 + (size_t)w * 256 + lane * 4, 128, s);
}

// ---------------- mma.sync GEMM, cp.async 3-stage pipeline ----------------
// stage layout: [A 128x72 bf16][B 128x72 bf16] = 36864 B per stage, 3 stages dynamic smem
#define STAGES      3
#define ROWB        144               // 72 bf16 padded row, bytes
#define A_BYTES     (128 * ROWB)      // 18432
#define STAGE_BYTES (2 * A_BYTES)     // 36864

template<int MODE>
__global__ void __launch_bounds__(256, 2)
mma_gemm(const __nv_bfloat16* __restrict__ A, int lda, int aChanStride, int loOffA,
         int K, int Kex,
         const __nv_bfloat16* __restrict__ Bx, long bChanStride, int chanWidth,
         const float* __restrict__ bias, int biasChanStride,
         float* __restrict__ outF, int ldF,
         __nv_bfloat16* __restrict__ outH, int ldH, int outHChanStride, int loDeltaOut,
         const float* __restrict__ W3, float* __restrict__ outp, int M)
{
    extern __shared__ char smem[];
    uint32_t sb = smem_u32(smem);

    int tid = threadIdx.x;
    int lane = tid & 31;
    int wid = tid >> 5;
    int warpM = wid & 1;
    int warpN = wid >> 1;

    int j0 = blockIdx.x * 128;
    int m0 = blockIdx.y * 128;
    int cblk = j0 / chanWidth;
    int jB0 = j0 - cblk * chanWidth;

    const __nv_bfloat16* Ab = A + (size_t)cblk * aChanStride;
    const __nv_bfloat16* Bb = Bx + (size_t)cblk * bChanStride;

    float acc[4][4][4];
#pragma unroll
    for (int i = 0; i < 4; i++)
#pragma unroll
        for (int j = 0; j < 4; j++)
#pragma unroll
            for (int r = 0; r < 4; r++) acc[i][j][r] = 0.f;

    const int C = Kex / 64;

    auto ISSUE = [&](int c) {
        uint32_t st = sb + (c % STAGES) * STAGE_BYTES;
        int e0 = c * 64;
#pragma unroll
        for (int i = 0; i < 4; i++) {
            int id = tid + i * 256;          // 0..1023
            int row = id >> 3;
            int kg  = id & 7;
            int e = e0 + kg * 8;
            int src = e < K ? e : (e < 2 * K ? e - K : e - 2 * K + loOffA);
            cp16(st + row * ROWB + kg * 16,
                 Ab + (size_t)(m0 + row) * lda + src);
            cp16(st + A_BYTES + row * ROWB + kg * 16,
                 Bb + (size_t)(jB0 + row) * Kex + e);
        }
        CP_COMMIT();
    };

    ISSUE(0);
    if (C > 1) ISSUE(1);

    for (int c = 0; c < C; c++) {
        if (c == C - 1) asm volatile("cp.async.wait_group 0;" ::: "memory");
        else            asm volatile("cp.async.wait_group 1;" ::: "memory");
        __syncthreads();
        if (c + STAGES - 1 < C) ISSUE(c + STAGES - 1);

        uint32_t aBase = sb + (c % STAGES) * STAGE_BYTES;
        uint32_t bBase = aBase + A_BYTES;

#pragma unroll
        for (int ks = 0; ks < 4; ks++) {
            uint32_t af[4][4], bf[2][4];
            int kcol = ks * 16 + (lane >> 4) * 8;
#pragma unroll
            for (int i = 0; i < 4; i++) {
                uint32_t addr = aBase + (uint32_t)((warpM * 64 + i * 16 + (lane & 15)) * ROWB + kcol * 2);
                LDSM_X4(af[i][0], af[i][1], af[i][2], af[i][3], addr);
            }
#pragma unroll
            for (int jj = 0; jj < 2; jj++) {
                uint32_t addr = bBase + (uint32_t)((warpN * 32 + jj * 16 + (lane & 15)) * ROWB + kcol * 2);
                LDSM_X4(bf[jj][0], bf[jj][1], bf[jj][2], bf[jj][3], addr);
            }
#pragma unroll
            for (int i = 0; i < 4; i++)
#pragma unroll
                for (int j = 0; j < 4; j++) {
                    int jj = j >> 1, sel = j & 1;
                    mma16816(acc[i][j], af[i], bf[jj][sel], bf[jj][sel + 2]);
                }
        }
        __syncthreads();
    }

    // ---------------- epilogue ----------------
    int groupID = lane >> 2;
    int tcol = (lane & 3) * 2;

    float bv0[4], bv1[4], wv0[4], wv1[4];
#pragma unroll
    for (int j = 0; j < 4; j++) {
        int colC = jB0 + warpN * 32 + j * 8 + tcol;
        const float* bp = bias + (size_t)cblk * biasChanStride + colC;
        bv0[j] = __ldg(bp);
        bv1[j] = __ldg(bp + 1);
        if (MODE == 3) {
            wv0[j] = __ldg(W3 + (size_t)cblk * CHID + colC);
            wv1[j] = __ldg(W3 + (size_t)cblk * CHID + colC + 1);
        }
    }

#pragma unroll
    for (int i = 0; i < 4; i++) {
        int row0 = m0 + warpM * 64 + i * 16 + groupID;
        int row1 = row0 + 8;
        if (MODE == 3) {
            float p0 = 0.f, p1 = 0.f;
#pragma unroll
            for (int j = 0; j < 4; j++) {
                float v00 = fmaxf(acc[i][j][0] + bv0[j], 0.f);
                float v01 = fmaxf(acc[i][j][1] + bv1[j], 0.f);
                float v10 = fmaxf(acc[i][j][2] + bv0[j], 0.f);
                float v11 = fmaxf(acc[i][j][3] + bv1[j], 0.f);
                p0 += v00 * wv0[j] + v01 * wv1[j];
                p1 += v10 * wv0[j] + v11 * wv1[j];
            }
            p0 += __shfl_xor_sync(0xffffffffu, p0, 1);
            p0 += __shfl_xor_sync(0xffffffffu, p0, 2);
            p1 += __shfl_xor_sync(0xffffffffu, p1, 1);
            p1 += __shfl_xor_sync(0xffffffffu, p1, 2);
            if ((lane & 3) == 0) {
                if (row0 < M) atomicAdd(outp + (size_t)row0 * CHN + cblk, p0);
                if (row1 < M) atomicAdd(outp + (size_t)row1 * CHN + cblk, p1);
            }
        } else {
#pragma unroll
            for (int j = 0; j < 4; j++) {
                int colC = jB0 + warpN * 32 + j * 8 + tcol;
                float v00 = fmaxf(acc[i][j][0] + bv0[j], 0.f);
                float v01 = fmaxf(acc[i][j][1] + bv1[j], 0.f);
                float v10 = fmaxf(acc[i][j][2] + bv0[j], 0.f);
                float v11 = fmaxf(acc[i][j][3] + bv1[j], 0.f);

                __nv_bfloat16 h00 = __float2bfloat16(v00), h01 = __float2bfloat16(v01);
                __nv_bfloat16 h10 = __float2bfloat16(v10), h11 = __float2bfloat16(v11);
                __nv_bfloat16* p0h = outH + (size_t)row0 * ldH + cblk * outHChanStride + colC;
                __nv_bfloat16* p1h = outH + (size_t)row1 * ldH + cblk * outHChanStride + colC;
                *(__nv_bfloat162*)p0h = __nv_bfloat162(h00, h01);
                *(__nv_bfloat162*)p1h = __nv_bfloat162(h10, h11);
                __nv_bfloat16 l00 = __float2bfloat16(v00 - __bfloat162float(h00));
                __nv_bfloat16 l01 = __float2bfloat16(v01 - __bfloat162float(h01));
                __nv_bfloat16 l10 = __float2bfloat16(v10 - __bfloat162float(h10));
                __nv_bfloat16 l11 = __float2bfloat16(v11 - __bfloat162float(h11));
                *(__nv_bfloat162*)(p0h + loDeltaOut) = __nv_bfloat162(l00, l01);
                *(__nv_bfloat162*)(p1h + loDeltaOut) = __nv_bfloat162(l10, l11);

                if (MODE == 1) {
                    int gcol = j0 + warpN * 32 + j * 8 + tcol;
                    *(float2*)(outF + (size_t)row0 * ldF + gcol) = make_float2(v00, v01);
                    *(float2*)(outF + (size_t)row1 * ldF + gcol) = make_float2(v10, v11);
                }
            }
        }
    }
}

__global__ void out_bias_relu_kernel(float* __restrict__ out, const float* __restrict__ b3, int n) {
    int i = blockIdx.x * blockDim.x + threadIdx.x;
    if (i >= n * CHN) return;
    float v = out[i] + b3[i & (CHN - 1)];
    out[i] = v > 0.f ? v : 0.f;
}

// ---------------- launch ----------------
extern "C" void kernel_launch(void* const* d_in, const int* in_sizes, int n_in,
                              void* d_out, int out_size)
{
    const float* x     = (const float*)d_in[0];
    const int*   edge  = (const int*)  d_in[1];
    const float* convW = (const float*)d_in[2];
    const float* convB = (const float*)d_in[3];
    const float* cW1   = (const float*)d_in[4];
    const float* cB1   = (const float*)d_in[5];
    const float* cW2   = (const float*)d_in[6];
    const float* cB2   = (const float*)d_in[7];
    const float* cW3   = (const float*)d_in[8];
    const float* cB3   = (const float*)d_in[9];
    float* out = (float*)d_out;

    int n = in_sizes[0] / DD;
    int E = in_sizes[1] / 2;

    float *cat;
    __nv_bfloat16 *convWex, *W1ex, *W2ex, *catHL, *a0, *t0, *t1, *H1;
    int *cnt;
    cudaGetSymbolAddress((void**)&cat, g_cat);
    cudaGetSymbolAddress((void**)&catHL, g_catHL);
    cudaGetSymbolAddress((void**)&a0, g_a0);
    cudaGetSymbolAddress((void**)&t0, g_t0);
    cudaGetSymbolAddress((void**)&t1, g_t1);
    cudaGetSymbolAddress((void**)&H1, g_H1);
    cudaGetSymbolAddress((void**)&convWex, g_convWex);
    cudaGetSymbolAddress((void**)&W1ex, g_W1ex);
    cudaGetSymbolAddress((void**)&W2ex, g_W2ex);
    cudaGetSymbolAddress((void**)&cnt, g_cnt);

    const int DSMEM = STAGES * STAGE_BYTES;   // 110592
    cudaFuncSetAttribute(mma_gemm<0>, cudaFuncAttributeMaxDynamicSharedMemorySize, DSMEM);
    cudaFuncSetAttribute(mma_gemm<1>, cudaFuncAttributeMaxDynamicSharedMemorySize, DSMEM);
    cudaFuncSetAttribute(mma_gemm<3>, cudaFuncAttributeMaxDynamicSharedMemorySize, DSMEM);

    const int mBlocks = (n + 127) / 128;
    const int BIG = 1 << 30;

    // weight expansion
    { dim3 g((128 * 128 + 255) / 256, 9); expand_w_kernel<<<g, 256>>>(convW, convWex, 128, 128); }
    { dim3 g((512 * 256 + 255) / 256, CHN); expand_w_kernel<<<g, 256>>>(cW1, W1ex, 512, 256); }
    { dim3 g((256 * 256 + 255) / 256, CHN); expand_w_kernel<<<g, 256>>>(cW2, W2ex, 256, 256); }

    prep_x_kernel<<<(n * 32 + 255) / 256, 256>>>(x, n);

    // CSR build (once)
    cudaMemsetAsync(cnt, 0, (size_t)(n + 1) * sizeof(int), 0);
    hist_kernel<<<(E + 255) / 256, 256>>>(edge, E);
    int nb = (n + 1023) / 1024;
    scan1_kernel<<<nb, 256>>>(n);
    scan2_kernel<<<1, 32>>>(nb);
    scan3_kernel<<<(n + 255) / 256, 256>>>(n, E);
    fill_kernel<<<(E + 255) / 256, 256>>>(edge, E);

    for (int l = 0; l < LL; l++) {
        {
            long th = (long)n * 32;
            gather_kernel<<<(int)((th + 255) / 256), 256>>>(n, l * DD);
        }

        const float* b0 = convB + (size_t)(l * 3 + 0) * DD;
        const float* b1 = convB + (size_t)(l * 3 + 1) * DD;
        const float* b2 = convB + (size_t)(l * 3 + 2) * DD;
        const __nv_bfloat16* B0 = convWex + (size_t)(l * 3 + 0) * 128 * 384;
        const __nv_bfloat16* B1 = convWex + (size_t)(l * 3 + 1) * 128 * 384;
        const __nv_bfloat16* B2 = convWex + (size_t)(l * 3 + 2) * 128 * 384;

        dim3 grid(1, mBlocks);
        mma_gemm<0><<<grid, 256, DSMEM>>>(a0, 256, 0, 128, 128, 384, B0, 0, BIG, b0, 0,
                                          nullptr, 0, t0, 256, 0, 128, nullptr, nullptr, n);
        mma_gemm<0><<<grid, 256, DSMEM>>>(t0, 256, 0, 128, 128, 384, B1, 0, BIG, b1, 0,
                                          nullptr, 0, t1, 256, 0, 128, nullptr, nullptr, n);
        mma_gemm<1><<<grid, 256, DSMEM>>>(t1, 256, 0, 128, 128, 384, B2, 0, BIG, b2, 0,
                                          cat + (l + 1) * DD, OCW,
                                          catHL + (l + 1) * DD, 1024, 0, 512, nullptr, nullptr, n);
    }

    // channel MLP layer 1
    {
        dim3 grid((CHN * CHID) / 128, mBlocks);
        mma_gemm<0><<<grid, 256, DSMEM>>>(catHL, 1024, 0, 512, 512, 1536,
                                          W1ex, (long)256 * 1536, CHID, cB1, CHID,
                                          nullptr, 0, H1, 2048, 256, 1024, nullptr, nullptr, n);
    }

    // channel MLP layer 2 + fused final dot
    cudaMemsetAsync(out, 0, (size_t)n * CHN * sizeof(float), 0);
    {
        dim3 grid((CHN * CHID) / 128, mBlocks);
        mma_gemm<3><<<grid, 256, DSMEM>>>(H1, 2048, 256, 1024, 256, 768,
                                          W2ex, (long)256 * 768, CHID, cB2, CHID,
                                          nullptr, 0, nullptr, 0, 0, 0, cW3, out, n);
    }

    out_bias_relu_kernel<<<(n * CHN + 255) / 256, 256>>>(out, cB3, n);
}

// round 7
// speedup vs baseline: 2.6068x; 1.0024x over previous
#include <cuda_runtime.h>
#include <cuda_bf16.h>
#include <cstdint>

// Problem constants
#define NMAX   100000
#define NPAD   100128
#define DD     128
#define LL     3
#define OCW    512
#define CHN    4
#define CHID   256
#define EMAX   2000000

// ---------------- static device scratch ----------------
__device__ float g_cat[(size_t)NPAD * OCW];
__device__ __nv_bfloat16 g_catHL[(size_t)NPAD * 1024];  // [hi 512 | lo 512]
__device__ __nv_bfloat16 g_a0  [(size_t)NPAD * 256];    // [hi128|lo128]
__device__ __nv_bfloat16 g_t0  [(size_t)NPAD * 256];
__device__ __nv_bfloat16 g_t1  [(size_t)NPAD * 256];
__device__ __nv_bfloat16 g_H1  [(size_t)NPAD * 2048];   // [hi1024|lo1024]
__device__ __nv_bfloat16 g_convWex[(size_t)9 * 128 * 384];
__device__ __nv_bfloat16 g_W1ex  [(size_t)CHN * 256 * 1536];
__device__ __nv_bfloat16 g_W2ex  [(size_t)CHN * 256 * 768];
// CSR
__device__ int g_cnt   [NPAD + 1];
__device__ int g_rowptr[NPAD + 1];
__device__ int g_wp    [NPAD + 1];
__device__ int g_bsum  [256];
__device__ int g_csr   [EMAX];

// ---------------- helpers ----------------
__device__ __forceinline__ uint32_t smem_u32(const void* p) {
    uint32_t r;
    asm("{ .reg .u64 t; cvta.to.shared.u64 t, %1; cvt.u32.u64 %0, t; }" : "=r"(r) : "l"(p));
    return r;
}
#define LDSM_X4(r0, r1, r2, r3, addr) \
    asm volatile("ldmatrix.sync.aligned.m8n8.x4.shared.b16 {%0,%1,%2,%3}, [%4];" \
        : "=r"(r0), "=r"(r1), "=r"(r2), "=r"(r3) : "r"(addr))

__device__ __forceinline__ void mma16816(float* c, const uint32_t* a, uint32_t b0, uint32_t b1) {
    asm volatile(
        "mma.sync.aligned.m16n8k16.row.col.f32.bf16.bf16.f32 "
        "{%0,%1,%2,%3}, {%4,%5,%6,%7}, {%8,%9}, {%0,%1,%2,%3};"
        : "+f"(c[0]), "+f"(c[1]), "+f"(c[2]), "+f"(c[3])
        : "r"(a[0]), "r"(a[1]), "r"(a[2]), "r"(a[3]), "r"(b0), "r"(b1));
}
__device__ __forceinline__ void cp16(uint32_t dst, const void* src) {
    asm volatile("cp.async.cg.shared.global [%0], [%1], 16;" :: "r"(dst), "l"(src));
}
#define CP_COMMIT() asm volatile("cp.async.commit_group;" ::: "memory")

// ---------------- weight expansion ----------------
__global__ void expand_w_kernel(const float* __restrict__ W, __nv_bfloat16* __restrict__ Bex,
                                int K, int N) {
    int mi = blockIdx.y;
    const float* Wm = W + (size_t)mi * K * N;
    __nv_bfloat16* Bm = Bex + (size_t)mi * N * 3 * K;
    int id = blockIdx.x * blockDim.x + threadIdx.x;
    if (id >= K * N) return;
    int k = id / N, n = id % N;
    float w = Wm[id];
    __nv_bfloat16 hi = __float2bfloat16(w);
    __nv_bfloat16 lo = __float2bfloat16(w - __bfloat162float(hi));
    Bm[(size_t)n * 3 * K + k]         = hi;
    Bm[(size_t)n * 3 * K + K + k]     = lo;
    Bm[(size_t)n * 3 * K + 2 * K + k] = hi;
}

__device__ __forceinline__ void store_hilo4(__nv_bfloat16* p, int loDelta, float4 v) {
    __nv_bfloat16 h0 = __float2bfloat16(v.x), h1 = __float2bfloat16(v.y);
    __nv_bfloat16 h2 = __float2bfloat16(v.z), h3 = __float2bfloat16(v.w);
    ((__nv_bfloat162*)p)[0] = __nv_bfloat162(h0, h1);
    ((__nv_bfloat162*)p)[1] = __nv_bfloat162(h2, h3);
    __nv_bfloat16 l0 = __float2bfloat16(v.x - __bfloat162float(h0));
    __nv_bfloat16 l1 = __float2bfloat16(v.y - __bfloat162float(h1));
    __nv_bfloat16 l2 = __float2bfloat16(v.z - __bfloat162float(h2));
    __nv_bfloat16 l3 = __float2bfloat16(v.w - __bfloat162float(h3));
    ((__nv_bfloat162*)(p + loDelta))[0] = __nv_bfloat162(l0, l1);
    ((__nv_bfloat162*)(p + loDelta))[1] = __nv_bfloat162(l2, l3);
}

__global__ void prep_x_kernel(const float* __restrict__ x, int n) {
    int i = blockIdx.x * blockDim.x + threadIdx.x;
    if (i >= n * 32) return;
    int row = i >> 5, c4 = i & 31;
    float4 v = ((const float4*)x)[i];
    ((float4*)g_cat)[(size_t)row * 128 + c4] = v;
    store_hilo4(g_catHL + (size_t)row * 1024 + c4 * 4, 512, v);
}

// ---------------- CSR build ----------------
__global__ void hist_kernel(const int* __restrict__ edge, int E) {
    int e = blockIdx.x * blockDim.x + threadIdx.x;
    if (e < E) atomicAdd(&g_cnt[__ldg(edge + E + e)], 1);
}
__global__ void scan1_kernel(int n) {
    __shared__ int warpSums[8];
    int t = threadIdx.x;
    int base = blockIdx.x * 1024 + t * 4;
    int v[4];
#pragma unroll
    for (int j = 0; j < 4; j++) v[j] = (base + j < n) ? g_cnt[base + j] : 0;
    int tsum = v[0] + v[1] + v[2] + v[3];
    int lane = t & 31, w = t >> 5;
    int x = tsum;
#pragma unroll
    for (int o = 1; o < 32; o <<= 1) {
        int y = __shfl_up_sync(0xffffffffu, x, o);
        if (lane >= o) x += y;
    }
    int excl = x - tsum;
    if (lane == 31) warpSums[w] = x;
    __syncthreads();
    if (t == 0) {
        int run = 0;
#pragma unroll
        for (int i = 0; i < 8; i++) { int tm = warpSums[i]; warpSums[i] = run; run += tm; }
        g_bsum[blockIdx.x] = run;
    }
    __syncthreads();
    int off = warpSums[w] + excl;
#pragma unroll
    for (int j = 0; j < 4; j++) {
        if (base + j < n) g_rowptr[base + j] = off;
        off += v[j];
    }
}
__global__ void scan2_kernel(int nb) {
    if (threadIdx.x == 0) {
        int run = 0;
        for (int i = 0; i < nb; i++) { int t = g_bsum[i]; g_bsum[i] = run; run += t; }
    }
}
__global__ void scan3_kernel(int n, int E) {
    int i = blockIdx.x * blockDim.x + threadIdx.x;
    if (i < n) {
        int v = g_rowptr[i] + g_bsum[i >> 10];
        g_rowptr[i] = v;
        g_wp[i] = v;
    }
    if (i == 0) g_rowptr[n] = E;
}
__global__ void fill_kernel(const int* __restrict__ edge, int E) {
    int e = blockIdx.x * blockDim.x + threadIdx.x;
    if (e >= E) return;
    int s = __ldg(edge + e);
    int d = __ldg(edge + E + e);
    int pos = atomicAdd(&g_wp[d], 1);
    g_csr[pos] = s;
}

// ---------------- gather + prep fused ----------------
__global__ void gather_kernel(int n, int colOff) {
    int w = (blockIdx.x * blockDim.x + threadIdx.x) >> 5;
    if (w >= n) return;
    int lane = threadIdx.x & 31;
    int beg = __ldg(&g_rowptr[w]);
    int end = __ldg(&g_rowptr[w + 1]);
    const float* base = g_cat + colOff + lane * 4;
    float4 s = *(const float4*)(base + (size_t)w * OCW);
    int i = beg;
    for (; i + 1 < end; i += 2) {
        int s0 = __ldg(&g_csr[i]);
        int s1 = __ldg(&g_csr[i + 1]);
        float4 v0 = *(const float4*)(base + (size_t)s0 * OCW);
        float4 v1 = *(const float4*)(base + (size_t)s1 * OCW);
        s.x += v0.x; s.y += v0.y; s.z += v0.z; s.w += v0.w;
        s.x += v1.x; s.y += v1.y; s.z += v1.z; s.w += v1.w;
    }
    if (i < end) {
        int s0 = __ldg(&g_csr[i]);
        float4 v0 = *(const float4*)(base + (size_t)s0 * OCW);
        s.x += v0.x; s.y += v0.y; s.z += v0.z; s.w += v0.w;
    }
    store_hilo4(g_a0 + (size_t)w * 256 + lane * 4, 128, s);
}

// ---------------- mma.sync GEMM, cp.async 3-stage pipeline ----------------
// stage layout: [A 128x72 bf16][B 128x72 bf16] = 36864 B per stage, 3 stages dynamic smem
#define STAGES      3
#define ROWB        144               // 72 bf16 padded row, bytes
#define A_BYTES     (128 * ROWB)      // 18432
#define STAGE_BYTES (2 * A_BYTES)     // 36864

template<int MODE>
__global__ void __launch_bounds__(256, 2)
mma_gemm(const __nv_bfloat16* __restrict__ A, int lda, int aChanStride, int loOffA,
         int K, int Kex,
         const __nv_bfloat16* __restrict__ Bx, long bChanStride, int chanWidth,
         const float* __restrict__ bias, int biasChanStride,
         float* __restrict__ outF, int ldF,
         __nv_bfloat16* __restrict__ outH, int ldH, int outHChanStride, int loDeltaOut,
         const float* __restrict__ W3, float* __restrict__ outp, int M)
{
    extern __shared__ char smem[];
    uint32_t sb = smem_u32(smem);

    int tid = threadIdx.x;
    int lane = tid & 31;
    int wid = tid >> 5;
    int warpM = wid & 1;
    int warpN = wid >> 1;

    int j0 = blockIdx.x * 128;
    int m0 = blockIdx.y * 128;
    int cblk = j0 / chanWidth;
    int jB0 = j0 - cblk * chanWidth;

    const __nv_bfloat16* Ab = A + (size_t)cblk * aChanStride;
    const __nv_bfloat16* Bb = Bx + (size_t)cblk * bChanStride;

    float acc[4][4][4];
#pragma unroll
    for (int i = 0; i < 4; i++)
#pragma unroll
        for (int j = 0; j < 4; j++)
#pragma unroll
            for (int r = 0; r < 4; r++) acc[i][j][r] = 0.f;

    const int C = Kex / 64;

    auto ISSUE = [&](int c) {
        uint32_t st = sb + (c % STAGES) * STAGE_BYTES;
        int e0 = c * 64;
#pragma unroll
        for (int i = 0; i < 4; i++) {
            int id = tid + i * 256;          // 0..1023
            int row = id >> 3;
            int kg  = id & 7;
            int e = e0 + kg * 8;
            int src = e < K ? e : (e < 2 * K ? e - K : e - 2 * K + loOffA);
            cp16(st + row * ROWB + kg * 16,
                 Ab + (size_t)(m0 + row) * lda + src);
            cp16(st + A_BYTES + row * ROWB + kg * 16,
                 Bb + (size_t)(jB0 + row) * Kex + e);
        }
        CP_COMMIT();
    };

    ISSUE(0);
    if (C > 1) ISSUE(1);

    for (int c = 0; c < C; c++) {
        if (c == C - 1) asm volatile("cp.async.wait_group 0;" ::: "memory");
        else            asm volatile("cp.async.wait_group 1;" ::: "memory");
        __syncthreads();
        if (c + STAGES - 1 < C) ISSUE(c + STAGES - 1);

        uint32_t aBase = sb + (c % STAGES) * STAGE_BYTES;
        uint32_t bBase = aBase + A_BYTES;

#pragma unroll
        for (int ks = 0; ks < 4; ks++) {
            uint32_t af[4][4], bf[2][4];
            int kcol = ks * 16 + (lane >> 4) * 8;
#pragma unroll
            for (int i = 0; i < 4; i++) {
                uint32_t addr = aBase + (uint32_t)((warpM * 64 + i * 16 + (lane & 15)) * ROWB + kcol * 2);
                LDSM_X4(af[i][0], af[i][1], af[i][2], af[i][3], addr);
            }
#pragma unroll
            for (int jj = 0; jj < 2; jj++) {
                uint32_t addr = bBase + (uint32_t)((warpN * 32 + jj * 16 + (lane & 15)) * ROWB + kcol * 2);
                LDSM_X4(bf[jj][0], bf[jj][1], bf[jj][2], bf[jj][3], addr);
            }
#pragma unroll
            for (int i = 0; i < 4; i++)
#pragma unroll
                for (int j = 0; j < 4; j++) {
                    int jj = j >> 1, sel = j & 1;
                    mma16816(acc[i][j], af[i], bf[jj][sel], bf[jj][sel + 2]);
                }
        }
        __syncthreads();
    }

    // ---------------- epilogue ----------------
    int groupID = lane >> 2;
    int tcol = (lane & 3) * 2;

    float bv0[4], bv1[4], wv0[4], wv1[4];
#pragma unroll
    for (int j = 0; j < 4; j++) {
        int colC = jB0 + warpN * 32 + j * 8 + tcol;
        const float* bp = bias + (size_t)cblk * biasChanStride + colC;
        bv0[j] = __ldg(bp);
        bv1[j] = __ldg(bp + 1);
        if (MODE == 3) {
            wv0[j] = __ldg(W3 + (size_t)cblk * CHID + colC);
            wv1[j] = __ldg(W3 + (size_t)cblk * CHID + colC + 1);
        }
    }

#pragma unroll
    for (int i = 0; i < 4; i++) {
        int row0 = m0 + warpM * 64 + i * 16 + groupID;
        int row1 = row0 + 8;
        if (MODE == 3) {
            float p0 = 0.f, p1 = 0.f;
#pragma unroll
            for (int j = 0; j < 4; j++) {
                float v00 = fmaxf(acc[i][j][0] + bv0[j], 0.f);
                float v01 = fmaxf(acc[i][j][1] + bv1[j], 0.f);
                float v10 = fmaxf(acc[i][j][2] + bv0[j], 0.f);
                float v11 = fmaxf(acc[i][j][3] + bv1[j], 0.f);
                p0 += v00 * wv0[j] + v01 * wv1[j];
                p1 += v10 * wv0[j] + v11 * wv1[j];
            }
            p0 += __shfl_xor_sync(0xffffffffu, p0, 1);
            p0 += __shfl_xor_sync(0xffffffffu, p0, 2);
            p1 += __shfl_xor_sync(0xffffffffu, p1, 1);
            p1 += __shfl_xor_sync(0xffffffffu, p1, 2);
            if ((lane & 3) == 0) {
                if (row0 < M) atomicAdd(outp + (size_t)row0 * CHN + cblk, p0);
                if (row1 < M) atomicAdd(outp + (size_t)row1 * CHN + cblk, p1);
            }
        } else {
#pragma unroll
            for (int j = 0; j < 4; j++) {
                int colC = jB0 + warpN * 32 + j * 8 + tcol;
                float v00 = fmaxf(acc[i][j][0] + bv0[j], 0.f);
                float v01 = fmaxf(acc[i][j][1] + bv1[j], 0.f);
                float v10 = fmaxf(acc[i][j][2] + bv0[j], 0.f);
                float v11 = fmaxf(acc[i][j][3] + bv1[j], 0.f);

                __nv_bfloat16 h00 = __float2bfloat16(v00), h01 = __float2bfloat16(v01);
                __nv_bfloat16 h10 = __float2bfloat16(v10), h11 = __float2bfloat16(v11);
                __nv_bfloat16* p0h = outH + (size_t)row0 * ldH + cblk * outHChanStride + colC;
                __nv_bfloat16* p1h = outH + (size_t)row1 * ldH + cblk * outHChanStride + colC;
                *(__nv_bfloat162*)p0h = __nv_bfloat162(h00, h01);
                *(__nv_bfloat162*)p1h = __nv_bfloat162(h10, h11);
                __nv_bfloat16 l00 = __float2bfloat16(v00 - __bfloat162float(h00));
                __nv_bfloat16 l01 = __float2bfloat16(v01 - __bfloat162float(h01));
                __nv_bfloat16 l10 = __float2bfloat16(v10 - __bfloat162float(h10));
                __nv_bfloat16 l11 = __float2bfloat16(v11 - __bfloat162float(h11));
                *(__nv_bfloat162*)(p0h + loDeltaOut) = __nv_bfloat162(l00, l01);
                *(__nv_bfloat162*)(p1h + loDeltaOut) = __nv_bfloat162(l10, l11);

                if (MODE == 1) {
                    int gcol = j0 + warpN * 32 + j * 8 + tcol;
                    *(float2*)(outF + (size_t)row0 * ldF + gcol) = make_float2(v00, v01);
                    *(float2*)(outF + (size_t)row1 * ldF + gcol) = make_float2(v10, v11);
                }
            }
        }
    }
}

__global__ void out_bias_relu_kernel(float* __restrict__ out, const float* __restrict__ b3, int n) {
    int i = blockIdx.x * blockDim.x + threadIdx.x;
    if (i >= n * CHN) return;
    float v = out[i] + b3[i & (CHN - 1)];
    out[i] = v > 0.f ? v : 0.f;
}

// ---------------- launch ----------------
extern "C" void kernel_launch(void* const* d_in, const int* in_sizes, int n_in,
                              void* d_out, int out_size)
{
    const float* x     = (const float*)d_in[0];
    const int*   edge  = (const int*)  d_in[1];
    const float* convW = (const float*)d_in[2];
    const float* convB = (const float*)d_in[3];
    const float* cW1   = (const float*)d_in[4];
    const float* cB1   = (const float*)d_in[5];
    const float* cW2   = (const float*)d_in[6];
    const float* cB2   = (const float*)d_in[7];
    const float* cW3   = (const float*)d_in[8];
    const float* cB3   = (const float*)d_in[9];
    float* out = (float*)d_out;

    int n = in_sizes[0] / DD;
    int E = in_sizes[1] / 2;

    float *cat;
    __nv_bfloat16 *convWex, *W1ex, *W2ex, *catHL, *a0, *t0, *t1, *H1;
    int *cnt;
    cudaGetSymbolAddress((void**)&cat, g_cat);
    cudaGetSymbolAddress((void**)&catHL, g_catHL);
    cudaGetSymbolAddress((void**)&a0, g_a0);
    cudaGetSymbolAddress((void**)&t0, g_t0);
    cudaGetSymbolAddress((void**)&t1, g_t1);
    cudaGetSymbolAddress((void**)&H1, g_H1);
    cudaGetSymbolAddress((void**)&convWex, g_convWex);
    cudaGetSymbolAddress((void**)&W1ex, g_W1ex);
    cudaGetSymbolAddress((void**)&W2ex, g_W2ex);
    cudaGetSymbolAddress((void**)&cnt, g_cnt);

    const int DSMEM = STAGES * STAGE_BYTES;   // 110592
    cudaFuncSetAttribute(mma_gemm<0>, cudaFuncAttributeMaxDynamicSharedMemorySize, DSMEM);
    cudaFuncSetAttribute(mma_gemm<1>, cudaFuncAttributeMaxDynamicSharedMemorySize, DSMEM);
    cudaFuncSetAttribute(mma_gemm<3>, cudaFuncAttributeMaxDynamicSharedMemorySize, DSMEM);

    const int mBlocks = (n + 127) / 128;
    const int BIG = 1 << 30;

    // weight expansion
    { dim3 g((128 * 128 + 255) / 256, 9); expand_w_kernel<<<g, 256>>>(convW, convWex, 128, 128); }
    { dim3 g((512 * 256 + 255) / 256, CHN); expand_w_kernel<<<g, 256>>>(cW1, W1ex, 512, 256); }
    { dim3 g((256 * 256 + 255) / 256, CHN); expand_w_kernel<<<g, 256>>>(cW2, W2ex, 256, 256); }

    prep_x_kernel<<<(n * 32 + 255) / 256, 256>>>(x, n);

    // CSR build (once)
    cudaMemsetAsync(cnt, 0, (size_t)(n + 1) * sizeof(int), 0);
    hist_kernel<<<(E + 255) / 256, 256>>>(edge, E);
    int nb = (n + 1023) / 1024;
    scan1_kernel<<<nb, 256>>>(n);
    scan2_kernel<<<1, 32>>>(nb);
    scan3_kernel<<<(n + 255) / 256, 256>>>(n, E);
    fill_kernel<<<(E + 255) / 256, 256>>>(edge, E);

    for (int l = 0; l < LL; l++) {
        {
            long th = (long)n * 32;
            gather_kernel<<<(int)((th + 255) / 256), 256>>>(n, l * DD);
        }

        const float* b0 = convB + (size_t)(l * 3 + 0) * DD;
        const float* b1 = convB + (size_t)(l * 3 + 1) * DD;
        const float* b2 = convB + (size_t)(l * 3 + 2) * DD;
        const __nv_bfloat16* B0 = convWex + (size_t)(l * 3 + 0) * 128 * 384;
        const __nv_bfloat16* B1 = convWex + (size_t)(l * 3 + 1) * 128 * 384;
        const __nv_bfloat16* B2 = convWex + (size_t)(l * 3 + 2) * 128 * 384;

        dim3 grid(1, mBlocks);
        mma_gemm<0><<<grid, 256, DSMEM>>>(a0, 256, 0, 128, 128, 384, B0, 0, BIG, b0, 0,
                                          nullptr, 0, t0, 256, 0, 128, nullptr, nullptr, n);
        mma_gemm<0><<<grid, 256, DSMEM>>>(t0, 256, 0, 128, 128, 384, B1, 0, BIG, b1, 0,
                                          nullptr, 0, t1, 256, 0, 128, nullptr, nullptr, n);
        mma_gemm<1><<<grid, 256, DSMEM>>>(t1, 256, 0, 128, 128, 384, B2, 0, BIG, b2, 0,
                                          cat + (l + 1) * DD, OCW,
                                          catHL + (l + 1) * DD, 1024, 0, 512, nullptr, nullptr, n);
    }

    // channel MLP layer 1
    {
        dim3 grid((CHN * CHID) / 128, mBlocks);
        mma_gemm<0><<<grid, 256, DSMEM>>>(catHL, 1024, 0, 512, 512, 1536,
                                          W1ex, (long)256 * 1536, CHID, cB1, CHID,
                                          nullptr, 0, H1, 2048, 256, 1024, nullptr, nullptr, n);
    }

    // channel MLP layer 2 + fused final dot
    cudaMemsetAsync(out, 0, (size_t)n * CHN * sizeof(float), 0);
    {
        dim3 grid((CHN * CHID) / 128, mBlocks);
        mma_gemm<3><<<grid, 256, DSMEM>>>(H1, 2048, 256, 1024, 256, 768,
                                          W2ex, (long)256 * 768, CHID, cB2, CHID,
                                          nullptr, 0, nullptr, 0, 0, 0, cW3, out, n);
    }

    out_bias_relu_kernel<<<(n * CHN + 255) / 256, 256>>>(out, cB3, n);
}

// round 8
// speedup vs baseline: 2.6073x; 1.0002x over previous
#include <cuda_runtime.h>
#include <cuda_bf16.h>
#include <cstdint>

// Problem constants
#define NMAX   100000
#define NPAD   100128
#define DD     128
#define LL     3
#define OCW    512
#define CHN    4
#define CHID   256
#define EMAX   2000000

// ---------------- static device scratch ----------------
__device__ float g_cat[(size_t)NPAD * OCW];
__device__ __nv_bfloat16 g_catHL[(size_t)NPAD * 1024];  // [hi 512 | lo 512]
__device__ __nv_bfloat16 g_a0  [(size_t)NPAD * 256];    // [hi128|lo128]
__device__ __nv_bfloat16 g_t0  [(size_t)NPAD * 256];
__device__ __nv_bfloat16 g_t1  [(size_t)NPAD * 256];
__device__ __nv_bfloat16 g_H1  [(size_t)NPAD * 2048];   // [hi1024|lo1024]
__device__ __nv_bfloat16 g_convWex[(size_t)9 * 128 * 384];
__device__ __nv_bfloat16 g_W1ex  [(size_t)CHN * 256 * 1536];
__device__ __nv_bfloat16 g_W2ex  [(size_t)CHN * 256 * 768];
// CSR
__device__ int g_cnt   [NPAD + 1];
__device__ int g_rowptr[NPAD + 1];
__device__ int g_wp    [NPAD + 1];
__device__ int g_bsum  [256];
__device__ int g_csr   [EMAX];

// ---------------- helpers ----------------
__device__ __forceinline__ uint32_t smem_u32(const void* p) {
    uint32_t r;
    asm("{ .reg .u64 t; cvta.to.shared.u64 t, %1; cvt.u32.u64 %0, t; }" : "=r"(r) : "l"(p));
    return r;
}
#define LDSM_X4(r0, r1, r2, r3, addr) \
    asm volatile("ldmatrix.sync.aligned.m8n8.x4.shared.b16 {%0,%1,%2,%3}, [%4];" \
        : "=r"(r0), "=r"(r1), "=r"(r2), "=r"(r3) : "r"(addr))

__device__ __forceinline__ void mma16816(float* c, const uint32_t* a, uint32_t b0, uint32_t b1) {
    asm volatile(
        "mma.sync.aligned.m16n8k16.row.col.f32.bf16.bf16.f32 "
        "{%0,%1,%2,%3}, {%4,%5,%6,%7}, {%8,%9}, {%0,%1,%2,%3};"
        : "+f"(c[0]), "+f"(c[1]), "+f"(c[2]), "+f"(c[3])
        : "r"(a[0]), "r"(a[1]), "r"(a[2]), "r"(a[3]), "r"(b0), "r"(b1));
}
__device__ __forceinline__ void cp16(uint32_t dst, const void* src) {
    asm volatile("cp.async.cg.shared.global [%0], [%1], 16;" :: "r"(dst), "l"(src));
}
#define CP_COMMIT() asm volatile("cp.async.commit_group;" ::: "memory")

// ---------------- weight expansion ----------------
__global__ void expand_w_kernel(const float* __restrict__ W, __nv_bfloat16* __restrict__ Bex,
                                int K, int N) {
    int mi = blockIdx.y;
    const float* Wm = W + (size_t)mi * K * N;
    __nv_bfloat16* Bm = Bex + (size_t)mi * N * 3 * K;
    int id = blockIdx.x * blockDim.x + threadIdx.x;
    if (id >= K * N) return;
    int k = id / N, n = id % N;
    float w = Wm[id];
    __nv_bfloat16 hi = __float2bfloat16(w);
    __nv_bfloat16 lo = __float2bfloat16(w - __bfloat162float(hi));
    Bm[(size_t)n * 3 * K + k]         = hi;
    Bm[(size_t)n * 3 * K + K + k]     = lo;
    Bm[(size_t)n * 3 * K + 2 * K + k] = hi;
}

__device__ __forceinline__ void store_hilo4(__nv_bfloat16* p, int loDelta, float4 v) {
    __nv_bfloat16 h0 = __float2bfloat16(v.x), h1 = __float2bfloat16(v.y);
    __nv_bfloat16 h2 = __float2bfloat16(v.z), h3 = __float2bfloat16(v.w);
    ((__nv_bfloat162*)p)[0] = __nv_bfloat162(h0, h1);
    ((__nv_bfloat162*)p)[1] = __nv_bfloat162(h2, h3);
    __nv_bfloat16 l0 = __float2bfloat16(v.x - __bfloat162float(h0));
    __nv_bfloat16 l1 = __float2bfloat16(v.y - __bfloat162float(h1));
    __nv_bfloat16 l2 = __float2bfloat16(v.z - __bfloat162float(h2));
    __nv_bfloat16 l3 = __float2bfloat16(v.w - __bfloat162float(h3));
    ((__nv_bfloat162*)(p + loDelta))[0] = __nv_bfloat162(l0, l1);
    ((__nv_bfloat162*)(p + loDelta))[1] = __nv_bfloat162(l2, l3);
}

__global__ void prep_x_kernel(const float* __restrict__ x, int n) {
    int i = blockIdx.x * blockDim.x + threadIdx.x;
    if (i >= n * 32) return;
    int row = i >> 5, c4 = i & 31;
    float4 v = ((const float4*)x)[i];
    ((float4*)g_cat)[(size_t)row * 128 + c4] = v;
    store_hilo4(g_catHL + (size_t)row * 1024 + c4 * 4, 512, v);
}

// ---------------- CSR build ----------------
__global__ void hist_kernel(const int* __restrict__ edge, int E) {
    int e = blockIdx.x * blockDim.x + threadIdx.x;
    if (e < E) atomicAdd(&g_cnt[__ldg(edge + E + e)], 1);
}
__global__ void scan1_kernel(int n) {
    __shared__ int warpSums[8];
    int t = threadIdx.x;
    int base = blockIdx.x * 1024 + t * 4;
    int v[4];
#pragma unroll
    for (int j = 0; j < 4; j++) v[j] = (base + j < n) ? g_cnt[base + j] : 0;
    int tsum = v[0] + v[1] + v[2] + v[3];
    int lane = t & 31, w = t >> 5;
    int x = tsum;
#pragma unroll
    for (int o = 1; o < 32; o <<= 1) {
        int y = __shfl_up_sync(0xffffffffu, x, o);
        if (lane >= o) x += y;
    }
    int excl = x - tsum;
    if (lane == 31) warpSums[w] = x;
    __syncthreads();
    if (t == 0) {
        int run = 0;
#pragma unroll
        for (int i = 0; i < 8; i++) { int tm = warpSums[i]; warpSums[i] = run; run += tm; }
        g_bsum[blockIdx.x] = run;
    }
    __syncthreads();
    int off = warpSums[w] + excl;
#pragma unroll
    for (int j = 0; j < 4; j++) {
        if (base + j < n) g_rowptr[base + j] = off;
        off += v[j];
    }
}
__global__ void scan2_kernel(int nb) {
    if (threadIdx.x == 0) {
        int run = 0;
        for (int i = 0; i < nb; i++) { int t = g_bsum[i]; g_bsum[i] = run; run += t; }
    }
}
__global__ void scan3_kernel(int n, int E) {
    int i = blockIdx.x * blockDim.x + threadIdx.x;
    if (i < n) {
        int v = g_rowptr[i] + g_bsum[i >> 10];
        g_rowptr[i] = v;
        g_wp[i] = v;
    }
    if (i == 0) g_rowptr[n] = E;
}
__global__ void fill_kernel(const int* __restrict__ edge, int E) {
    int e = blockIdx.x * blockDim.x + threadIdx.x;
    if (e >= E) return;
    int s = __ldg(edge + e);
    int d = __ldg(edge + E + e);
    int pos = atomicAdd(&g_wp[d], 1);
    g_csr[pos] = s;
}

// ---------------- gather + prep fused ----------------
__global__ void gather_kernel(int n, int colOff) {
    int w = (blockIdx.x * blockDim.x + threadIdx.x) >> 5;
    if (w >= n) return;
    int lane = threadIdx.x & 31;
    int beg = __ldg(&g_rowptr[w]);
    int end = __ldg(&g_rowptr[w + 1]);
    const float* base = g_cat + colOff + lane * 4;
    float4 s = *(const float4*)(base + (size_t)w * OCW);
    int i = beg;
    for (; i + 1 < end; i += 2) {
        int s0 = __ldg(&g_csr[i]);
        int s1 = __ldg(&g_csr[i + 1]);
        float4 v0 = *(const float4*)(base + (size_t)s0 * OCW);
        float4 v1 = *(const float4*)(base + (size_t)s1 * OCW);
        s.x += v0.x; s.y += v0.y; s.z += v0.z; s.w += v0.w;
        s.x += v1.x; s.y += v1.y; s.z += v1.z; s.w += v1.w;
    }
    if (i < end) {
        int s0 = __ldg(&g_csr[i]);
        float4 v0 = *(const float4*)(base + (size_t)s0 * OCW);
        s.x += v0.x; s.y += v0.y; s.z += v0.z; s.w += v0.w;
    }
    store_hilo4(g_a0 + (size_t)w * 256 + lane * 4, 128, s);
}

// ---------------- mma.sync GEMM, cp.async 3-stage pipeline ----------------
// stage layout: [A 128x72 bf16][B 128x72 bf16] = 36864 B per stage, 3 stages dynamic smem
#define STAGES      3
#define ROWB        144               // 72 bf16 padded row, bytes
#define A_BYTES     (128 * ROWB)      // 18432
#define STAGE_BYTES (2 * A_BYTES)     // 36864

template<int MODE>
__global__ void __launch_bounds__(256, 2)
mma_gemm(const __nv_bfloat16* __restrict__ A, int lda, int aChanStride, int loOffA,
         int K, int Kex,
         const __nv_bfloat16* __restrict__ Bx, long bChanStride, int chanWidth,
         const float* __restrict__ bias, int biasChanStride,
         float* __restrict__ outF, int ldF,
         __nv_bfloat16* __restrict__ outH, int ldH, int outHChanStride, int loDeltaOut,
         const float* __restrict__ W3, float* __restrict__ outp, int M)
{
    extern __shared__ char smem[];
    uint32_t sb = smem_u32(smem);

    int tid = threadIdx.x;
    int lane = tid & 31;
    int wid = tid >> 5;
    int warpM = wid & 1;
    int warpN = wid >> 1;

    int j0 = blockIdx.x * 128;
    int m0 = blockIdx.y * 128;
    int cblk = j0 / chanWidth;
    int jB0 = j0 - cblk * chanWidth;

    const __nv_bfloat16* Ab = A + (size_t)cblk * aChanStride;
    const __nv_bfloat16* Bb = Bx + (size_t)cblk * bChanStride;

    float acc[4][4][4];
#pragma unroll
    for (int i = 0; i < 4; i++)
#pragma unroll
        for (int j = 0; j < 4; j++)
#pragma unroll
            for (int r = 0; r < 4; r++) acc[i][j][r] = 0.f;

    const int C = Kex / 64;

    auto ISSUE = [&](int c) {
        uint32_t st = sb + (c % STAGES) * STAGE_BYTES;
        int e0 = c * 64;
#pragma unroll
        for (int i = 0; i < 4; i++) {
            int id = tid + i * 256;          // 0..1023
            int row = id >> 3;
            int kg  = id & 7;
            int e = e0 + kg * 8;
            int src = e < K ? e : (e < 2 * K ? e - K : e - 2 * K + loOffA);
            cp16(st + row * ROWB + kg * 16,
                 Ab + (size_t)(m0 + row) * lda + src);
            cp16(st + A_BYTES + row * ROWB + kg * 16,
                 Bb + (size_t)(jB0 + row) * Kex + e);
        }
        CP_COMMIT();
    };

    ISSUE(0);
    if (C > 1) ISSUE(1);

    for (int c = 0; c < C; c++) {
        if (c == C - 1) asm volatile("cp.async.wait_group 0;" ::: "memory");
        else            asm volatile("cp.async.wait_group 1;" ::: "memory");
        __syncthreads();
        if (c + STAGES - 1 < C) ISSUE(c + STAGES - 1);

        uint32_t aBase = sb + (c % STAGES) * STAGE_BYTES;
        uint32_t bBase = aBase + A_BYTES;

#pragma unroll
        for (int ks = 0; ks < 4; ks++) {
            uint32_t af[4][4], bf[2][4];
            int kcol = ks * 16 + (lane >> 4) * 8;
#pragma unroll
            for (int i = 0; i < 4; i++) {
                uint32_t addr = aBase + (uint32_t)((warpM * 64 + i * 16 + (lane & 15)) * ROWB + kcol * 2);
                LDSM_X4(af[i][0], af[i][1], af[i][2], af[i][3], addr);
            }
#pragma unroll
            for (int jj = 0; jj < 2; jj++) {
                uint32_t addr = bBase + (uint32_t)((warpN * 32 + jj * 16 + (lane & 15)) * ROWB + kcol * 2);
                LDSM_X4(bf[jj][0], bf[jj][1], bf[jj][2], bf[jj][3], addr);
            }
#pragma unroll
            for (int i = 0; i < 4; i++)
#pragma unroll
                for (int j = 0; j < 4; j++) {
                    int jj = j >> 1, sel = j & 1;
                    mma16816(acc[i][j], af[i], bf[jj][sel], bf[jj][sel + 2]);
                }
        }
        __syncthreads();
    }

    // ---------------- epilogue ----------------
    int groupID = lane >> 2;
    int tcol = (lane & 3) * 2;

    float bv0[4], bv1[4], wv0[4], wv1[4];
#pragma unroll
    for (int j = 0; j < 4; j++) {
        int colC = jB0 + warpN * 32 + j * 8 + tcol;
        const float* bp = bias + (size_t)cblk * biasChanStride + colC;
        bv0[j] = __ldg(bp);
        bv1[j] = __ldg(bp + 1);
        if (MODE == 3) {
            wv0[j] = __ldg(W3 + (size_t)cblk * CHID + colC);
            wv1[j] = __ldg(W3 + (size_t)cblk * CHID + colC + 1);
        }
    }

#pragma unroll
    for (int i = 0; i < 4; i++) {
        int row0 = m0 + warpM * 64 + i * 16 + groupID;
        int row1 = row0 + 8;
        if (MODE == 3) {
            float p0 = 0.f, p1 = 0.f;
#pragma unroll
            for (int j = 0; j < 4; j++) {
                float v00 = fmaxf(acc[i][j][0] + bv0[j], 0.f);
                float v01 = fmaxf(acc[i][j][1] + bv1[j], 0.f);
                float v10 = fmaxf(acc[i][j][2] + bv0[j], 0.f);
                float v11 = fmaxf(acc[i][j][3] + bv1[j], 0.f);
                p0 += v00 * wv0[j] + v01 * wv1[j];
                p1 += v10 * wv0[j] + v11 * wv1[j];
            }
            p0 += __shfl_xor_sync(0xffffffffu, p0, 1);
            p0 += __shfl_xor_sync(0xffffffffu, p0, 2);
            p1 += __shfl_xor_sync(0xffffffffu, p1, 1);
            p1 += __shfl_xor_sync(0xffffffffu, p1, 2);
            if ((lane & 3) == 0) {
                if (row0 < M) atomicAdd(outp + (size_t)row0 * CHN + cblk, p0);
                if (row1 < M) atomicAdd(outp + (size_t)row1 * CHN + cblk, p1);
            }
        } else {
#pragma unroll
            for (int j = 0; j < 4; j++) {
                int colC = jB0 + warpN * 32 + j * 8 + tcol;
                float v00 = fmaxf(acc[i][j][0] + bv0[j], 0.f);
                float v01 = fmaxf(acc[i][j][1] + bv1[j], 0.f);
                float v10 = fmaxf(acc[i][j][2] + bv0[j], 0.f);
                float v11 = fmaxf(acc[i][j][3] + bv1[j], 0.f);

                __nv_bfloat16 h00 = __float2bfloat16(v00), h01 = __float2bfloat16(v01);
                __nv_bfloat16 h10 = __float2bfloat16(v10), h11 = __float2bfloat16(v11);
                __nv_bfloat16* p0h = outH + (size_t)row0 * ldH + cblk * outHChanStride + colC;
                __nv_bfloat16* p1h = outH + (size_t)row1 * ldH + cblk * outHChanStride + colC;
                *(__nv_bfloat162*)p0h = __nv_bfloat162(h00, h01);
                *(__nv_bfloat162*)p1h = __nv_bfloat162(h10, h11);
                __nv_bfloat16 l00 = __float2bfloat16(v00 - __bfloat162float(h00));
                __nv_bfloat16 l01 = __float2bfloat16(v01 - __bfloat162float(h01));
                __nv_bfloat16 l10 = __float2bfloat16(v10 - __bfloat162float(h10));
                __nv_bfloat16 l11 = __float2bfloat16(v11 - __bfloat162float(h11));
                *(__nv_bfloat162*)(p0h + loDeltaOut) = __nv_bfloat162(l00, l01);
                *(__nv_bfloat162*)(p1h + loDeltaOut) = __nv_bfloat162(l10, l11);

                if (MODE == 1) {
                    int gcol = j0 + warpN * 32 + j * 8 + tcol;
                    *(float2*)(outF + (size_t)row0 * ldF + gcol) = make_float2(v00, v01);
                    *(float2*)(outF + (size_t)row1 * ldF + gcol) = make_float2(v10, v11);
                }
            }
        }
    }
}

__global__ void out_bias_relu_kernel(float* __restrict__ out, const float* __restrict__ b3, int n) {
    int i = blockIdx.x * blockDim.x + threadIdx.x;
    if (i >= n * CHN) return;
    float v = out[i] + b3[i & (CHN - 1)];
    out[i] = v > 0.f ? v : 0.f;
}

// ---------------- launch ----------------
extern "C" void kernel_launch(void* const* d_in, const int* in_sizes, int n_in,
                              void* d_out, int out_size)
{
    const float* x     = (const float*)d_in[0];
    const int*   edge  = (const int*)  d_in[1];
    const float* convW = (const float*)d_in[2];
    const float* convB = (const float*)d_in[3];
    const float* cW1   = (const float*)d_in[4];
    const float* cB1   = (const float*)d_in[5];
    const float* cW2   = (const float*)d_in[6];
    const float* cB2   = (const float*)d_in[7];
    const float* cW3   = (const float*)d_in[8];
    const float* cB3   = (const float*)d_in[9];
    float* out = (float*)d_out;

    int n = in_sizes[0] / DD;
    int E = in_sizes[1] / 2;

    float *cat;
    __nv_bfloat16 *convWex, *W1ex, *W2ex, *catHL, *a0, *t0, *t1, *H1;
    int *cnt;
    cudaGetSymbolAddress((void**)&cat, g_cat);
    cudaGetSymbolAddress((void**)&catHL, g_catHL);
    cudaGetSymbolAddress((void**)&a0, g_a0);
    cudaGetSymbolAddress((void**)&t0, g_t0);
    cudaGetSymbolAddress((void**)&t1, g_t1);
    cudaGetSymbolAddress((void**)&H1, g_H1);
    cudaGetSymbolAddress((void**)&convWex, g_convWex);
    cudaGetSymbolAddress((void**)&W1ex, g_W1ex);
    cudaGetSymbolAddress((void**)&W2ex, g_W2ex);
    cudaGetSymbolAddress((void**)&cnt, g_cnt);

    const int DSMEM = STAGES * STAGE_BYTES;   // 110592
    cudaFuncSetAttribute(mma_gemm<0>, cudaFuncAttributeMaxDynamicSharedMemorySize, DSMEM);
    cudaFuncSetAttribute(mma_gemm<1>, cudaFuncAttributeMaxDynamicSharedMemorySize, DSMEM);
    cudaFuncSetAttribute(mma_gemm<3>, cudaFuncAttributeMaxDynamicSharedMemorySize, DSMEM);

    const int mBlocks = (n + 127) / 128;
    const int BIG = 1 << 30;

    // weight expansion
    { dim3 g((128 * 128 + 255) / 256, 9); expand_w_kernel<<<g, 256>>>(convW, convWex, 128, 128); }
    { dim3 g((512 * 256 + 255) / 256, CHN); expand_w_kernel<<<g, 256>>>(cW1, W1ex, 512, 256); }
    { dim3 g((256 * 256 + 255) / 256, CHN); expand_w_kernel<<<g, 256>>>(cW2, W2ex, 256, 256); }

    prep_x_kernel<<<(n * 32 + 255) / 256, 256>>>(x, n);

    // CSR build (once)
    cudaMemsetAsync(cnt, 0, (size_t)(n + 1) * sizeof(int), 0);
    hist_kernel<<<(E + 255) / 256, 256>>>(edge, E);
    int nb = (n + 1023) / 1024;
    scan1_kernel<<<nb, 256>>>(n);
    scan2_kernel<<<1, 32>>>(nb);
    scan3_kernel<<<(n + 255) / 256, 256>>>(n, E);
    fill_kernel<<<(E + 255) / 256, 256>>>(edge, E);

    for (int l = 0; l < LL; l++) {
        {
            long th = (long)n * 32;
            gather_kernel<<<(int)((th + 255) / 256), 256>>>(n, l * DD);
        }

        const float* b0 = convB + (size_t)(l * 3 + 0) * DD;
        const float* b1 = convB + (size_t)(l * 3 + 1) * DD;
        const float* b2 = convB + (size_t)(l * 3 + 2) * DD;
        const __nv_bfloat16* B0 = convWex + (size_t)(l * 3 + 0) * 128 * 384;
        const __nv_bfloat16* B1 = convWex + (size_t)(l * 3 + 1) * 128 * 384;
        const __nv_bfloat16* B2 = convWex + (size_t)(l * 3 + 2) * 128 * 384;

        dim3 grid(1, mBlocks);
        mma_gemm<0><<<grid, 256, DSMEM>>>(a0, 256, 0, 128, 128, 384, B0, 0, BIG, b0, 0,
                                          nullptr, 0, t0, 256, 0, 128, nullptr, nullptr, n);
        mma_gemm<0><<<grid, 256, DSMEM>>>(t0, 256, 0, 128, 128, 384, B1, 0, BIG, b1, 0,
                                          nullptr, 0, t1, 256, 0, 128, nullptr, nullptr, n);
        mma_gemm<1><<<grid, 256, DSMEM>>>(t1, 256, 0, 128, 128, 384, B2, 0, BIG, b2, 0,
                                          cat + (l + 1) * DD, OCW,
                                          catHL + (l + 1) * DD, 1024, 0, 512, nullptr, nullptr, n);
    }

    // channel MLP layer 1
    {
        dim3 grid((CHN * CHID) / 128, mBlocks);
        mma_gemm<0><<<grid, 256, DSMEM>>>(catHL, 1024, 0, 512, 512, 1536,
                                          W1ex, (long)256 * 1536, CHID, cB1, CHID,
                                          nullptr, 0, H1, 2048, 256, 1024, nullptr, nullptr, n);
    }

    // channel MLP layer 2 + fused final dot
    cudaMemsetAsync(out, 0, (size_t)n * CHN * sizeof(float), 0);
    {
        dim3 grid((CHN * CHID) / 128, mBlocks);
        mma_gemm<3><<<grid, 256, DSMEM>>>(H1, 2048, 256, 1024, 256, 768,
                                          W2ex, (long)256 * 768, CHID, cB2, CHID,
                                          nullptr, 0, nullptr, 0, 0, 0, cW3, out, n);
    }

    out_bias_relu_kernel<<<(n * CHN + 255) / 256, 256>>>(out, cB3, n);
}

// round 9
// speedup vs baseline: 2.6083x; 1.0004x over previous
#include <cuda_runtime.h>
#include <cuda_bf16.h>
#include <cstdint>

// Problem constants
#define NMAX   100000
#define NPAD   100128
#define DD     128
#define LL     3
#define OCW    512
#define CHN    4
#define CHID   256
#define EMAX   2000000

// ---------------- static device scratch ----------------
__device__ float g_cat[(size_t)NPAD * OCW];
__device__ __nv_bfloat16 g_catHL[(size_t)NPAD * 1024];  // [hi 512 | lo 512]
__device__ __nv_bfloat16 g_a0  [(size_t)NPAD * 256];    // [hi128|lo128]
__device__ __nv_bfloat16 g_t0  [(size_t)NPAD * 256];
__device__ __nv_bfloat16 g_t1  [(size_t)NPAD * 256];
__device__ __nv_bfloat16 g_H1  [(size_t)NPAD * 2048];   // [hi1024|lo1024]
__device__ __nv_bfloat16 g_convWex[(size_t)9 * 128 * 384];
__device__ __nv_bfloat16 g_W1ex  [(size_t)CHN * 256 * 1536];
__device__ __nv_bfloat16 g_W2ex  [(size_t)CHN * 256 * 768];
// CSR
__device__ int g_cnt   [NPAD + 1];
__device__ int g_rowptr[NPAD + 1];
__device__ int g_wp    [NPAD + 1];
__device__ int g_bsum  [256];
__device__ int g_csr   [EMAX];

// ---------------- helpers ----------------
__device__ __forceinline__ uint32_t smem_u32(const void* p) {
    uint32_t r;
    asm("{ .reg .u64 t; cvta.to.shared.u64 t, %1; cvt.u32.u64 %0, t; }" : "=r"(r) : "l"(p));
    return r;
}
#define LDSM_X4(r0, r1, r2, r3, addr) \
    asm volatile("ldmatrix.sync.aligned.m8n8.x4.shared.b16 {%0,%1,%2,%3}, [%4];" \
        : "=r"(r0), "=r"(r1), "=r"(r2), "=r"(r3) : "r"(addr))

__device__ __forceinline__ void mma16816(float* c, const uint32_t* a, uint32_t b0, uint32_t b1) {
    asm volatile(
        "mma.sync.aligned.m16n8k16.row.col.f32.bf16.bf16.f32 "
        "{%0,%1,%2,%3}, {%4,%5,%6,%7}, {%8,%9}, {%0,%1,%2,%3};"
        : "+f"(c[0]), "+f"(c[1]), "+f"(c[2]), "+f"(c[3])
        : "r"(a[0]), "r"(a[1]), "r"(a[2]), "r"(a[3]), "r"(b0), "r"(b1));
}
__device__ __forceinline__ void cp16(uint32_t dst, const void* src) {
    asm volatile("cp.async.cg.shared.global [%0], [%1], 16;" :: "r"(dst), "l"(src));
}
#define CP_COMMIT() asm volatile("cp.async.commit_group;" ::: "memory")

// ---------------- weight expansion ----------------
__global__ void expand_w_kernel(const float* __restrict__ W, __nv_bfloat16* __restrict__ Bex,
                                int K, int N) {
    int mi = blockIdx.y;
    const float* Wm = W + (size_t)mi * K * N;
    __nv_bfloat16* Bm = Bex + (size_t)mi * N * 3 * K;
    int id = blockIdx.x * blockDim.x + threadIdx.x;
    if (id >= K * N) return;
    int k = id / N, n = id % N;
    float w = Wm[id];
    __nv_bfloat16 hi = __float2bfloat16(w);
    __nv_bfloat16 lo = __float2bfloat16(w - __bfloat162float(hi));
    Bm[(size_t)n * 3 * K + k]         = hi;
    Bm[(size_t)n * 3 * K + K + k]     = lo;
    Bm[(size_t)n * 3 * K + 2 * K + k] = hi;
}

__device__ __forceinline__ void store_hilo4(__nv_bfloat16* p, int loDelta, float4 v) {
    __nv_bfloat16 h0 = __float2bfloat16(v.x), h1 = __float2bfloat16(v.y);
    __nv_bfloat16 h2 = __float2bfloat16(v.z), h3 = __float2bfloat16(v.w);
    ((__nv_bfloat162*)p)[0] = __nv_bfloat162(h0, h1);
    ((__nv_bfloat162*)p)[1] = __nv_bfloat162(h2, h3);
    __nv_bfloat16 l0 = __float2bfloat16(v.x - __bfloat162float(h0));
    __nv_bfloat16 l1 = __float2bfloat16(v.y - __bfloat162float(h1));
    __nv_bfloat16 l2 = __float2bfloat16(v.z - __bfloat162float(h2));
    __nv_bfloat16 l3 = __float2bfloat16(v.w - __bfloat162float(h3));
    ((__nv_bfloat162*)(p + loDelta))[0] = __nv_bfloat162(l0, l1);
    ((__nv_bfloat162*)(p + loDelta))[1] = __nv_bfloat162(l2, l3);
}

__global__ void prep_x_kernel(const float* __restrict__ x, int n) {
    int i = blockIdx.x * blockDim.x + threadIdx.x;
    if (i >= n * 32) return;
    int row = i >> 5, c4 = i & 31;
    float4 v = ((const float4*)x)[i];
    ((float4*)g_cat)[(size_t)row * 128 + c4] = v;
    store_hilo4(g_catHL + (size_t)row * 1024 + c4 * 4, 512, v);
}

// ---------------- CSR build ----------------
__global__ void hist_kernel(const int* __restrict__ edge, int E) {
    int e = blockIdx.x * blockDim.x + threadIdx.x;
    if (e < E) atomicAdd(&g_cnt[__ldg(edge + E + e)], 1);
}
__global__ void scan1_kernel(int n) {
    __shared__ int warpSums[8];
    int t = threadIdx.x;
    int base = blockIdx.x * 1024 + t * 4;
    int v[4];
#pragma unroll
    for (int j = 0; j < 4; j++) v[j] = (base + j < n) ? g_cnt[base + j] : 0;
    int tsum = v[0] + v[1] + v[2] + v[3];
    int lane = t & 31, w = t >> 5;
    int x = tsum;
#pragma unroll
    for (int o = 1; o < 32; o <<= 1) {
        int y = __shfl_up_sync(0xffffffffu, x, o);
        if (lane >= o) x += y;
    }
    int excl = x - tsum;
    if (lane == 31) warpSums[w] = x;
    __syncthreads();
    if (t == 0) {
        int run = 0;
#pragma unroll
        for (int i = 0; i < 8; i++) { int tm = warpSums[i]; warpSums[i] = run; run += tm; }
        g_bsum[blockIdx.x] = run;
    }
    __syncthreads();
    int off = warpSums[w] + excl;
#pragma unroll
    for (int j = 0; j < 4; j++) {
        if (base + j < n) g_rowptr[base + j] = off;
        off += v[j];
    }
}
__global__ void scan2_kernel(int nb) {
    if (threadIdx.x == 0) {
        int run = 0;
        for (int i = 0; i < nb; i++) { int t = g_bsum[i]; g_bsum[i] = run; run += t; }
    }
}
__global__ void scan3_kernel(int n, int E) {
    int i = blockIdx.x * blockDim.x + threadIdx.x;
    if (i < n) {
        int v = g_rowptr[i] + g_bsum[i >> 10];
        g_rowptr[i] = v;
        g_wp[i] = v;
    }
    if (i == 0) g_rowptr[n] = E;
}
__global__ void fill_kernel(const int* __restrict__ edge, int E) {
    int e = blockIdx.x * blockDim.x + threadIdx.x;
    if (e >= E) return;
    int s = __ldg(edge + e);
    int d = __ldg(edge + E + e);
    int pos = atomicAdd(&g_wp[d], 1);
    g_csr[pos] = s;
}

// ---------------- gather + prep fused ----------------
__global__ void gather_kernel(int n, int colOff) {
    int w = (blockIdx.x * blockDim.x + threadIdx.x) >> 5;
    if (w >= n) return;
    int lane = threadIdx.x & 31;
    int beg = __ldg(&g_rowptr[w]);
    int end = __ldg(&g_rowptr[w + 1]);
    const float* base = g_cat + colOff + lane * 4;
    float4 s = *(const float4*)(base + (size_t)w * OCW);
    int i = beg;
    for (; i + 1 < end; i += 2) {
        int s0 = __ldg(&g_csr[i]);
        int s1 = __ldg(&g_csr[i + 1]);
        float4 v0 = *(const float4*)(base + (size_t)s0 * OCW);
        float4 v1 = *(const float4*)(base + (size_t)s1 * OCW);
        s.x += v0.x; s.y += v0.y; s.z += v0.z; s.w += v0.w;
        s.x += v1.x; s.y += v1.y; s.z += v1.z; s.w += v1.w;
    }
    if (i < end) {
        int s0 = __ldg(&g_csr[i]);
        float4 v0 = *(const float4*)(base + (size_t)s0 * OCW);
        s.x += v0.x; s.y += v0.y; s.z += v0.z; s.w += v0.w;
    }
    store_hilo4(g_a0 + (size_t)w * 256 + lane * 4, 128, s);
}

// ---------------- mma.sync GEMM, cp.async 3-stage pipeline ----------------
// stage layout: [A 128x72 bf16][B 128x72 bf16] = 36864 B per stage, 3 stages dynamic smem
#define STAGES      3
#define ROWB        144               // 72 bf16 padded row, bytes
#define A_BYTES     (128 * ROWB)      // 18432
#define STAGE_BYTES (2 * A_BYTES)     // 36864

template<int MODE>
__global__ void __launch_bounds__(256, 2)
mma_gemm(const __nv_bfloat16* __restrict__ A, int lda, int aChanStride, int loOffA,
         int K, int Kex,
         const __nv_bfloat16* __restrict__ Bx, long bChanStride, int chanWidth,
         const float* __restrict__ bias, int biasChanStride,
         float* __restrict__ outF, int ldF,
         __nv_bfloat16* __restrict__ outH, int ldH, int outHChanStride, int loDeltaOut,
         const float* __restrict__ W3, float* __restrict__ outp, int M)
{
    extern __shared__ char smem[];
    uint32_t sb = smem_u32(smem);

    int tid = threadIdx.x;
    int lane = tid & 31;
    int wid = tid >> 5;
    int warpM = wid & 1;
    int warpN = wid >> 1;

    int j0 = blockIdx.x * 128;
    int m0 = blockIdx.y * 128;
    int cblk = j0 / chanWidth;
    int jB0 = j0 - cblk * chanWidth;

    const __nv_bfloat16* Ab = A + (size_t)cblk * aChanStride;
    const __nv_bfloat16* Bb = Bx + (size_t)cblk * bChanStride;

    float acc[4][4][4];
#pragma unroll
    for (int i = 0; i < 4; i++)
#pragma unroll
        for (int j = 0; j < 4; j++)
#pragma unroll
            for (int r = 0; r < 4; r++) acc[i][j][r] = 0.f;

    const int C = Kex / 64;

    auto ISSUE = [&](int c) {
        uint32_t st = sb + (c % STAGES) * STAGE_BYTES;
        int e0 = c * 64;
#pragma unroll
        for (int i = 0; i < 4; i++) {
            int id = tid + i * 256;          // 0..1023
            int row = id >> 3;
            int kg  = id & 7;
            int e = e0 + kg * 8;
            int src = e < K ? e : (e < 2 * K ? e - K : e - 2 * K + loOffA);
            cp16(st + row * ROWB + kg * 16,
                 Ab + (size_t)(m0 + row) * lda + src);
            cp16(st + A_BYTES + row * ROWB + kg * 16,
                 Bb + (size_t)(jB0 + row) * Kex + e);
        }
        CP_COMMIT();
    };

    ISSUE(0);
    if (C > 1) ISSUE(1);

    for (int c = 0; c < C; c++) {
        if (c == C - 1) asm volatile("cp.async.wait_group 0;" ::: "memory");
        else            asm volatile("cp.async.wait_group 1;" ::: "memory");
        __syncthreads();
        if (c + STAGES - 1 < C) ISSUE(c + STAGES - 1);

        uint32_t aBase = sb + (c % STAGES) * STAGE_BYTES;
        uint32_t bBase = aBase + A_BYTES;

#pragma unroll
        for (int ks = 0; ks < 4; ks++) {
            uint32_t af[4][4], bf[2][4];
            int kcol = ks * 16 + (lane >> 4) * 8;
#pragma unroll
            for (int i = 0; i < 4; i++) {
                uint32_t addr = aBase + (uint32_t)((warpM * 64 + i * 16 + (lane & 15)) * ROWB + kcol * 2);
                LDSM_X4(af[i][0], af[i][1], af[i][2], af[i][3], addr);
            }
#pragma unroll
            for (int jj = 0; jj < 2; jj++) {
                uint32_t addr = bBase + (uint32_t)((warpN * 32 + jj * 16 + (lane & 15)) * ROWB + kcol * 2);
                LDSM_X4(bf[jj][0], bf[jj][1], bf[jj][2], bf[jj][3], addr);
            }
#pragma unroll
            for (int i = 0; i < 4; i++)
#pragma unroll
                for (int j = 0; j < 4; j++) {
                    int jj = j >> 1, sel = j & 1;
                    mma16816(acc[i][j], af[i], bf[jj][sel], bf[jj][sel + 2]);
                }
        }
        __syncthreads();
    }

    // ---------------- epilogue ----------------
    int groupID = lane >> 2;
    int tcol = (lane & 3) * 2;

    float bv0[4], bv1[4], wv0[4], wv1[4];
#pragma unroll
    for (int j = 0; j < 4; j++) {
        int colC = jB0 + warpN * 32 + j * 8 + tcol;
        const float* bp = bias + (size_t)cblk * biasChanStride + colC;
        bv0[j] = __ldg(bp);
        bv1[j] = __ldg(bp + 1);
        if (MODE == 3) {
            wv0[j] = __ldg(W3 + (size_t)cblk * CHID + colC);
            wv1[j] = __ldg(W3 + (size_t)cblk * CHID + colC + 1);
        }
    }

#pragma unroll
    for (int i = 0; i < 4; i++) {
        int row0 = m0 + warpM * 64 + i * 16 + groupID;
        int row1 = row0 + 8;
        if (MODE == 3) {
            float p0 = 0.f, p1 = 0.f;
#pragma unroll
            for (int j = 0; j < 4; j++) {
                float v00 = fmaxf(acc[i][j][0] + bv0[j], 0.f);
                float v01 = fmaxf(acc[i][j][1] + bv1[j], 0.f);
                float v10 = fmaxf(acc[i][j][2] + bv0[j], 0.f);
                float v11 = fmaxf(acc[i][j][3] + bv1[j], 0.f);
                p0 += v00 * wv0[j] + v01 * wv1[j];
                p1 += v10 * wv0[j] + v11 * wv1[j];
            }
            p0 += __shfl_xor_sync(0xffffffffu, p0, 1);
            p0 += __shfl_xor_sync(0xffffffffu, p0, 2);
            p1 += __shfl_xor_sync(0xffffffffu, p1, 1);
            p1 += __shfl_xor_sync(0xffffffffu, p1, 2);
            if ((lane & 3) == 0) {
                if (row0 < M) atomicAdd(outp + (size_t)row0 * CHN + cblk, p0);
                if (row1 < M) atomicAdd(outp + (size_t)row1 * CHN + cblk, p1);
            }
        } else {
#pragma unroll
            for (int j = 0; j < 4; j++) {
                int colC = jB0 + warpN * 32 + j * 8 + tcol;
                float v00 = fmaxf(acc[i][j][0] + bv0[j], 0.f);
                float v01 = fmaxf(acc[i][j][1] + bv1[j], 0.f);
                float v10 = fmaxf(acc[i][j][2] + bv0[j], 0.f);
                float v11 = fmaxf(acc[i][j][3] + bv1[j], 0.f);

                __nv_bfloat16 h00 = __float2bfloat16(v00), h01 = __float2bfloat16(v01);
                __nv_bfloat16 h10 = __float2bfloat16(v10), h11 = __float2bfloat16(v11);
                __nv_bfloat16* p0h = outH + (size_t)row0 * ldH + cblk * outHChanStride + colC;
                __nv_bfloat16* p1h = outH + (size_t)row1 * ldH + cblk * outHChanStride + colC;
                *(__nv_bfloat162*)p0h = __nv_bfloat162(h00, h01);
                *(__nv_bfloat162*)p1h = __nv_bfloat162(h10, h11);
                __nv_bfloat16 l00 = __float2bfloat16(v00 - __bfloat162float(h00));
                __nv_bfloat16 l01 = __float2bfloat16(v01 - __bfloat162float(h01));
                __nv_bfloat16 l10 = __float2bfloat16(v10 - __bfloat162float(h10));
                __nv_bfloat16 l11 = __float2bfloat16(v11 - __bfloat162float(h11));
                *(__nv_bfloat162*)(p0h + loDeltaOut) = __nv_bfloat162(l00, l01);
                *(__nv_bfloat162*)(p1h + loDeltaOut) = __nv_bfloat162(l10, l11);

                if (MODE == 1) {
                    int gcol = j0 + warpN * 32 + j * 8 + tcol;
                    *(float2*)(outF + (size_t)row0 * ldF + gcol) = make_float2(v00, v01);
                    *(float2*)(outF + (size_t)row1 * ldF + gcol) = make_float2(v10, v11);
                }
            }
        }
    }
}

__global__ void out_bias_relu_kernel(float* __restrict__ out, const float* __restrict__ b3, int n) {
    int i = blockIdx.x * blockDim.x + threadIdx.x;
    if (i >= n * CHN) return;
    float v = out[i] + b3[i & (CHN - 1)];
    out[i] = v > 0.f ? v : 0.f;
}

// ---------------- launch ----------------
extern "C" void kernel_launch(void* const* d_in, const int* in_sizes, int n_in,
                              void* d_out, int out_size)
{
    const float* x     = (const float*)d_in[0];
    const int*   edge  = (const int*)  d_in[1];
    const float* convW = (const float*)d_in[2];
    const float* convB = (const float*)d_in[3];
    const float* cW1   = (const float*)d_in[4];
    const float* cB1   = (const float*)d_in[5];
    const float* cW2   = (const float*)d_in[6];
    const float* cB2   = (const float*)d_in[7];
    const float* cW3   = (const float*)d_in[8];
    const float* cB3   = (const float*)d_in[9];
    float* out = (float*)d_out;

    int n = in_sizes[0] / DD;
    int E = in_sizes[1] / 2;

    float *cat;
    __nv_bfloat16 *convWex, *W1ex, *W2ex, *catHL, *a0, *t0, *t1, *H1;
    int *cnt;
    cudaGetSymbolAddress((void**)&cat, g_cat);
    cudaGetSymbolAddress((void**)&catHL, g_catHL);
    cudaGetSymbolAddress((void**)&a0, g_a0);
    cudaGetSymbolAddress((void**)&t0, g_t0);
    cudaGetSymbolAddress((void**)&t1, g_t1);
    cudaGetSymbolAddress((void**)&H1, g_H1);
    cudaGetSymbolAddress((void**)&convWex, g_convWex);
    cudaGetSymbolAddress((void**)&W1ex, g_W1ex);
    cudaGetSymbolAddress((void**)&W2ex, g_W2ex);
    cudaGetSymbolAddress((void**)&cnt, g_cnt);

    const int DSMEM = STAGES * STAGE_BYTES;   // 110592
    cudaFuncSetAttribute(mma_gemm<0>, cudaFuncAttributeMaxDynamicSharedMemorySize, DSMEM);
    cudaFuncSetAttribute(mma_gemm<1>, cudaFuncAttributeMaxDynamicSharedMemorySize, DSMEM);
    cudaFuncSetAttribute(mma_gemm<3>, cudaFuncAttributeMaxDynamicSharedMemorySize, DSMEM);

    const int mBlocks = (n + 127) / 128;
    const int BIG = 1 << 30;

    // weight expansion
    { dim3 g((128 * 128 + 255) / 256, 9); expand_w_kernel<<<g, 256>>>(convW, convWex, 128, 128); }
    { dim3 g((512 * 256 + 255) / 256, CHN); expand_w_kernel<<<g, 256>>>(cW1, W1ex, 512, 256); }
    { dim3 g((256 * 256 + 255) / 256, CHN); expand_w_kernel<<<g, 256>>>(cW2, W2ex, 256, 256); }

    prep_x_kernel<<<(n * 32 + 255) / 256, 256>>>(x, n);

    // CSR build (once)
    cudaMemsetAsync(cnt, 0, (size_t)(n + 1) * sizeof(int), 0);
    hist_kernel<<<(E + 255) / 256, 256>>>(edge, E);
    int nb = (n + 1023) / 1024;
    scan1_kernel<<<nb, 256>>>(n);
    scan2_kernel<<<1, 32>>>(nb);
    scan3_kernel<<<(n + 255) / 256, 256>>>(n, E);
    fill_kernel<<<(E + 255) / 256, 256>>>(edge, E);

    for (int l = 0; l < LL; l++) {
        {
            long th = (long)n * 32;
            gather_kernel<<<(int)((th + 255) / 256), 256>>>(n, l * DD);
        }

        const float* b0 = convB + (size_t)(l * 3 + 0) * DD;
        const float* b1 = convB + (size_t)(l * 3 + 1) * DD;
        const float* b2 = convB + (size_t)(l * 3 + 2) * DD;
        const __nv_bfloat16* B0 = convWex + (size_t)(l * 3 + 0) * 128 * 384;
        const __nv_bfloat16* B1 = convWex + (size_t)(l * 3 + 1) * 128 * 384;
        const __nv_bfloat16* B2 = convWex + (size_t)(l * 3 + 2) * 128 * 384;

        dim3 grid(1, mBlocks);
        mma_gemm<0><<<grid, 256, DSMEM>>>(a0, 256, 0, 128, 128, 384, B0, 0, BIG, b0, 0,
                                          nullptr, 0, t0, 256, 0, 128, nullptr, nullptr, n);
        mma_gemm<0><<<grid, 256, DSMEM>>>(t0, 256, 0, 128, 128, 384, B1, 0, BIG, b1, 0,
                                          nullptr, 0, t1, 256, 0, 128, nullptr, nullptr, n);
        mma_gemm<1><<<grid, 256, DSMEM>>>(t1, 256, 0, 128, 128, 384, B2, 0, BIG, b2, 0,
                                          cat + (l + 1) * DD, OCW,
                                          catHL + (l + 1) * DD, 1024, 0, 512, nullptr, nullptr, n);
    }

    // channel MLP layer 1
    {
        dim3 grid((CHN * CHID) / 128, mBlocks);
        mma_gemm<0><<<grid, 256, DSMEM>>>(catHL, 1024, 0, 512, 512, 1536,
                                          W1ex, (long)256 * 1536, CHID, cB1, CHID,
                                          nullptr, 0, H1, 2048, 256, 1024, nullptr, nullptr, n);
    }

    // channel MLP layer 2 + fused final dot
    cudaMemsetAsync(out, 0, (size_t)n * CHN * sizeof(float), 0);
    {
        dim3 grid((CHN * CHID) / 128, mBlocks);
        mma_gemm<3><<<grid, 256, DSMEM>>>(H1, 2048, 256, 1024, 256, 768,
                                          W2ex, (long)256 * 768, CHID, cB2, CHID,
                                          nullptr, 0, nullptr, 0, 0, 0, cW3, out, n);
    }

    out_bias_relu_kernel<<<(n * CHN + 255) / 256, 256>>>(out, cB3, n);
}

// round 10
// speedup vs baseline: 3.4748x; 1.3322x over previous
#include <cuda_runtime.h>
#include <cuda_bf16.h>
#include <cuda_fp16.h>
#include <cstdint>

// Problem constants
#define NMAX   100000
#define NPAD   100128
#define DD     128
#define LL     3
#define OCW    512
#define CHN    4
#define CHID   256
#define EMAX   2000000

// ---------------- static device scratch ----------------
__device__ float g_cat[(size_t)NPAD * OCW];             // fp32 concat (gather source)
__device__ __half g_catF16[(size_t)NPAD * OCW];         // fp16 concat (MLP1 input)
__device__ __nv_bfloat16 g_a0[(size_t)NPAD * 256];      // conv input [hi128|lo128]
__device__ __nv_bfloat16 g_t0[(size_t)NPAD * 256];
__device__ __nv_bfloat16 g_t1[(size_t)NPAD * 256];
__device__ __half g_H1[(size_t)NPAD * 1024];            // fp16 [N,1024] plain
__device__ __nv_bfloat16 g_convWex[(size_t)9 * 128 * 384];   // bf16x3 [hi|lo|hi]
__device__ __half g_W1ex[(size_t)CHN * 256 * 1024];          // fp16x2 interleaved 64-chunks
__device__ __half g_W2ex[(size_t)CHN * 256 * 512];
// CSR
__device__ int g_cnt   [NPAD + 1];
__device__ int g_rowptr[NPAD + 1];
__device__ int g_wp    [NPAD + 1];
__device__ int g_bsum  [256];
__device__ int g_csr   [EMAX];

// ---------------- helpers ----------------
__device__ __forceinline__ uint32_t smem_u32(const void* p) {
    uint32_t r;
    asm("{ .reg .u64 t; cvta.to.shared.u64 t, %1; cvt.u32.u64 %0, t; }" : "=r"(r) : "l"(p));
    return r;
}
#define LDSM_X4(r0, r1, r2, r3, addr) \
    asm volatile("ldmatrix.sync.aligned.m8n8.x4.shared.b16 {%0,%1,%2,%3}, [%4];" \
        : "=r"(r0), "=r"(r1), "=r"(r2), "=r"(r3) : "r"(addr))

__device__ __forceinline__ void mma_bf16(float* c, const uint32_t* a, uint32_t b0, uint32_t b1) {
    asm volatile(
        "mma.sync.aligned.m16n8k16.row.col.f32.bf16.bf16.f32 "
        "{%0,%1,%2,%3}, {%4,%5,%6,%7}, {%8,%9}, {%0,%1,%2,%3};"
        : "+f"(c[0]), "+f"(c[1]), "+f"(c[2]), "+f"(c[3])
        : "r"(a[0]), "r"(a[1]), "r"(a[2]), "r"(a[3]), "r"(b0), "r"(b1));
}
__device__ __forceinline__ void mma_fp16(float* c, const uint32_t* a, uint32_t b0, uint32_t b1) {
    asm volatile(
        "mma.sync.aligned.m16n8k16.row.col.f32.f16.f16.f32 "
        "{%0,%1,%2,%3}, {%4,%5,%6,%7}, {%8,%9}, {%0,%1,%2,%3};"
        : "+f"(c[0]), "+f"(c[1]), "+f"(c[2]), "+f"(c[3])
        : "r"(a[0]), "r"(a[1]), "r"(a[2]), "r"(a[3]), "r"(b0), "r"(b1));
}
__device__ __forceinline__ void cp16(uint32_t dst, const void* src) {
    asm volatile("cp.async.cg.shared.global [%0], [%1], 16;" :: "r"(dst), "l"(src));
}
#define CP_COMMIT() asm volatile("cp.async.commit_group;" ::: "memory")

// ---------------- weight expansion: bf16x3 [hi|lo|hi] ----------------
__global__ void expand_w_kernel(const float* __restrict__ W, __nv_bfloat16* __restrict__ Bex,
                                int K, int N) {
    int mi = blockIdx.y;
    const float* Wm = W + (size_t)mi * K * N;
    __nv_bfloat16* Bm = Bex + (size_t)mi * N * 3 * K;
    int id = blockIdx.x * blockDim.x + threadIdx.x;
    if (id >= K * N) return;
    int k = id / N, n = id % N;
    float w = Wm[id];
    __nv_bfloat16 hi = __float2bfloat16(w);
    __nv_bfloat16 lo = __float2bfloat16(w - __bfloat162float(hi));
    Bm[(size_t)n * 3 * K + k]         = hi;
    Bm[(size_t)n * 3 * K + K + k]     = lo;
    Bm[(size_t)n * 3 * K + 2 * K + k] = hi;
}

// ---------------- weight expansion: fp16x2 interleaved 64-chunks ----------------
// expanded col layout per 64-chunk b: [128b,128b+64) = hi(k=64b..), [128b+64,128b+128) = lo(same k)
__global__ void expand_w16_kernel(const float* __restrict__ W, __half* __restrict__ Bex,
                                  int K, int N) {
    int mi = blockIdx.y;
    const float* Wm = W + (size_t)mi * K * N;
    __half* Bm = Bex + (size_t)mi * N * 2 * K;
    int id = blockIdx.x * blockDim.x + threadIdx.x;
    if (id >= K * N) return;
    int k = id / N, n = id % N;
    float w = Wm[id];
    __half hi = __float2half(w);
    __half lo = __float2half(w - __half2float(hi));
    int b = k >> 6, r = k & 63;
    Bm[(size_t)n * 2 * K + b * 128 + r]      = hi;
    Bm[(size_t)n * 2 * K + b * 128 + 64 + r] = lo;
}

__device__ __forceinline__ void store_hilo4(__nv_bfloat16* p, int loDelta, float4 v) {
    __nv_bfloat16 h0 = __float2bfloat16(v.x), h1 = __float2bfloat16(v.y);
    __nv_bfloat16 h2 = __float2bfloat16(v.z), h3 = __float2bfloat16(v.w);
    ((__nv_bfloat162*)p)[0] = __nv_bfloat162(h0, h1);
    ((__nv_bfloat162*)p)[1] = __nv_bfloat162(h2, h3);
    __nv_bfloat16 l0 = __float2bfloat16(v.x - __bfloat162float(h0));
    __nv_bfloat16 l1 = __float2bfloat16(v.y - __bfloat162float(h1));
    __nv_bfloat16 l2 = __float2bfloat16(v.z - __bfloat162float(h2));
    __nv_bfloat16 l3 = __float2bfloat16(v.w - __bfloat162float(h3));
    ((__nv_bfloat162*)(p + loDelta))[0] = __nv_bfloat162(l0, l1);
    ((__nv_bfloat162*)(p + loDelta))[1] = __nv_bfloat162(l2, l3);
}

__global__ void prep_x_kernel(const float* __restrict__ x, int n) {
    int i = blockIdx.x * blockDim.x + threadIdx.x;
    if (i >= n * 32) return;
    int row = i >> 5, c4 = i & 31;
    float4 v = ((const float4*)x)[i];
    ((float4*)g_cat)[(size_t)row * 128 + c4] = v;
    __half* p = g_catF16 + (size_t)row * OCW + c4 * 4;
    ((__half2*)p)[0] = __floats2half2_rn(v.x, v.y);
    ((__half2*)p)[1] = __floats2half2_rn(v.z, v.w);
}

// ---------------- CSR build ----------------
__global__ void hist_kernel(const int* __restrict__ edge, int E) {
    int e = blockIdx.x * blockDim.x + threadIdx.x;
    if (e < E) atomicAdd(&g_cnt[__ldg(edge + E + e)], 1);
}
__global__ void scan1_kernel(int n) {
    __shared__ int warpSums[8];
    int t = threadIdx.x;
    int base = blockIdx.x * 1024 + t * 4;
    int v[4];
#pragma unroll
    for (int j = 0; j < 4; j++) v[j] = (base + j < n) ? g_cnt[base + j] : 0;
    int tsum = v[0] + v[1] + v[2] + v[3];
    int lane = t & 31, w = t >> 5;
    int x = tsum;
#pragma unroll
    for (int o = 1; o < 32; o <<= 1) {
        int y = __shfl_up_sync(0xffffffffu, x, o);
        if (lane >= o) x += y;
    }
    int excl = x - tsum;
    if (lane == 31) warpSums[w] = x;
    __syncthreads();
    if (t == 0) {
        int run = 0;
#pragma unroll
        for (int i = 0; i < 8; i++) { int tm = warpSums[i]; warpSums[i] = run; run += tm; }
        g_bsum[blockIdx.x] = run;
    }
    __syncthreads();
    int off = warpSums[w] + excl;
#pragma unroll
    for (int j = 0; j < 4; j++) {
        if (base + j < n) g_rowptr[base + j] = off;
        off += v[j];
    }
}
__global__ void scan2_kernel(int nb) {
    if (threadIdx.x == 0) {
        int run = 0;
        for (int i = 0; i < nb; i++) { int t = g_bsum[i]; g_bsum[i] = run; run += t; }
    }
}
__global__ void scan3_kernel(int n, int E) {
    int i = blockIdx.x * blockDim.x + threadIdx.x;
    if (i < n) {
        int v = g_rowptr[i] + g_bsum[i >> 10];
        g_rowptr[i] = v;
        g_wp[i] = v;
    }
    if (i == 0) g_rowptr[n] = E;
}
__global__ void fill_kernel(const int* __restrict__ edge, int E) {
    int e = blockIdx.x * blockDim.x + threadIdx.x;
    if (e >= E) return;
    int s = __ldg(edge + e);
    int d = __ldg(edge + E + e);
    int pos = atomicAdd(&g_wp[d], 1);
    g_csr[pos] = s;
}

// ---------------- gather + prep fused ----------------
__global__ void gather_kernel(int n, int colOff) {
    int w = (blockIdx.x * blockDim.x + threadIdx.x) >> 5;
    if (w >= n) return;
    int lane = threadIdx.x & 31;
    int beg = __ldg(&g_rowptr[w]);
    int end = __ldg(&g_rowptr[w + 1]);
    const float* base = g_cat + colOff + lane * 4;
    float4 s = *(const float4*)(base + (size_t)w * OCW);
    int i = beg;
    for (; i + 1 < end; i += 2) {
        int s0 = __ldg(&g_csr[i]);
        int s1 = __ldg(&g_csr[i + 1]);
        float4 v0 = *(const float4*)(base + (size_t)s0 * OCW);
        float4 v1 = *(const float4*)(base + (size_t)s1 * OCW);
        s.x += v0.x; s.y += v0.y; s.z += v0.z; s.w += v0.w;
        s.x += v1.x; s.y += v1.y; s.z += v1.z; s.w += v1.w;
    }
    if (i < end) {
        int s0 = __ldg(&g_csr[i]);
        float4 v0 = *(const float4*)(base + (size_t)s0 * OCW);
        s.x += v0.x; s.y += v0.y; s.z += v0.z; s.w += v0.w;
    }
    store_hilo4(g_a0 + (size_t)w * 256 + lane * 4, 128, s);
}

// ---------------- mma.sync GEMM, cp.async 3-stage pipeline ----------------
// DT=0: bf16x3 expanded (Kex=3K), A storage [hi|..|lo at loOffA]
// DT=1: fp16x2 expanded (Kex=2K), interleaved 64-chunks; A is plain fp16 (hi only),
//       src = (e>>7)*64 + (e&63)  (each A chunk consumed by 2 consecutive pipe chunks)
// MODE 0: relu(acc+bias) -> bf16 hi/lo outH
// MODE 1: relu(acc+bias) -> fp32 outF + fp16 outG
// MODE 2: relu(acc+bias) -> fp16 outG (channel layout)
// MODE 3: fused final dot: atomicAdd(outp[row,cblk], dot(relu(acc+bias), W3[cblk]))
#define STAGES      3
#define ROWB        144
#define A_BYTES     (128 * ROWB)
#define STAGE_BYTES (2 * A_BYTES)

template<int MODE, int DT>
__global__ void __launch_bounds__(256, 2)
mma_gemm(const __nv_bfloat16* __restrict__ A, int lda, int aChanStride, int loOffA,
         int K, int Kex,
         const __nv_bfloat16* __restrict__ Bx, long bChanStride, int chanWidth,
         const float* __restrict__ bias, int biasChanStride,
         float* __restrict__ outF, int ldF,
         __nv_bfloat16* __restrict__ outH, int ldH, int outHChanStride, int loDeltaOut,
         __half* __restrict__ outG, int ldG, int outGChanStride,
         const float* __restrict__ W3, float* __restrict__ outp, int M)
{
    extern __shared__ char smem[];
    uint32_t sb = smem_u32(smem);

    int tid = threadIdx.x;
    int lane = tid & 31;
    int wid = tid >> 5;
    int warpM = wid & 1;
    int warpN = wid >> 1;

    int j0 = blockIdx.x * 128;
    int m0 = blockIdx.y * 128;
    int cblk = j0 / chanWidth;
    int jB0 = j0 - cblk * chanWidth;

    const __nv_bfloat16* Ab = A + (size_t)cblk * aChanStride;
    const __nv_bfloat16* Bb = Bx + (size_t)cblk * bChanStride;

    float acc[4][4][4];
#pragma unroll
    for (int i = 0; i < 4; i++)
#pragma unroll
        for (int j = 0; j < 4; j++)
#pragma unroll
            for (int r = 0; r < 4; r++) acc[i][j][r] = 0.f;

    const int C = Kex / 64;

    auto ISSUE = [&](int c) {
        uint32_t st = sb + (c % STAGES) * STAGE_BYTES;
        int e0 = c * 64;
#pragma unroll
        for (int i = 0; i < 4; i++) {
            int id = tid + i * 256;
            int row = id >> 3;
            int kg  = id & 7;
            int e = e0 + kg * 8;
            int src;
            if (DT == 1) src = ((e >> 7) << 6) + (e & 63);
            else         src = e < K ? e : (e < 2 * K ? e - K : e - 2 * K + loOffA);
            cp16(st + row * ROWB + kg * 16,
                 Ab + (size_t)(m0 + row) * lda + src);
            cp16(st + A_BYTES + row * ROWB + kg * 16,
                 Bb + (size_t)(jB0 + row) * Kex + e);
        }
        CP_COMMIT();
    };

    ISSUE(0);
    if (C > 1) ISSUE(1);

    for (int c = 0; c < C; c++) {
        if (c == C - 1) asm volatile("cp.async.wait_group 0;" ::: "memory");
        else            asm volatile("cp.async.wait_group 1;" ::: "memory");
        __syncthreads();
        if (c + STAGES - 1 < C) ISSUE(c + STAGES - 1);

        uint32_t aBase = sb + (c % STAGES) * STAGE_BYTES;
        uint32_t bBase = aBase + A_BYTES;

#pragma unroll
        for (int ks = 0; ks < 4; ks++) {
            uint32_t af[4][4], bf[2][4];
            int kcol = ks * 16 + (lane >> 4) * 8;
#pragma unroll
            for (int i = 0; i < 4; i++) {
                uint32_t addr = aBase + (uint32_t)((warpM * 64 + i * 16 + (lane & 15)) * ROWB + kcol * 2);
                LDSM_X4(af[i][0], af[i][1], af[i][2], af[i][3], addr);
            }
#pragma unroll
            for (int jj = 0; jj < 2; jj++) {
                uint32_t addr = bBase + (uint32_t)((warpN * 32 + jj * 16 + (lane & 15)) * ROWB + kcol * 2);
                LDSM_X4(bf[jj][0], bf[jj][1], bf[jj][2], bf[jj][3], addr);
            }
#pragma unroll
            for (int i = 0; i < 4; i++)
#pragma unroll
                for (int j = 0; j < 4; j++) {
                    int jj = j >> 1, sel = j & 1;
                    if (DT == 0) mma_bf16(acc[i][j], af[i], bf[jj][sel], bf[jj][sel + 2]);
                    else         mma_fp16(acc[i][j], af[i], bf[jj][sel], bf[jj][sel + 2]);
                }
        }
        __syncthreads();
    }

    // ---------------- epilogue ----------------
    int groupID = lane >> 2;
    int tcol = (lane & 3) * 2;

    float bv0[4], bv1[4], wv0[4], wv1[4];
#pragma unroll
    for (int j = 0; j < 4; j++) {
        int colC = jB0 + warpN * 32 + j * 8 + tcol;
        const float* bp = bias + (size_t)cblk * biasChanStride + colC;
        bv0[j] = __ldg(bp);
        bv1[j] = __ldg(bp + 1);
        if (MODE == 3) {
            wv0[j] = __ldg(W3 + (size_t)cblk * CHID + colC);
            wv1[j] = __ldg(W3 + (size_t)cblk * CHID + colC + 1);
        }
    }

#pragma unroll
    for (int i = 0; i < 4; i++) {
        int row0 = m0 + warpM * 64 + i * 16 + groupID;
        int row1 = row0 + 8;
        if (MODE == 3) {
            float p0 = 0.f, p1 = 0.f;
#pragma unroll
            for (int j = 0; j < 4; j++) {
                float v00 = fmaxf(acc[i][j][0] + bv0[j], 0.f);
                float v01 = fmaxf(acc[i][j][1] + bv1[j], 0.f);
                float v10 = fmaxf(acc[i][j][2] + bv0[j], 0.f);
                float v11 = fmaxf(acc[i][j][3] + bv1[j], 0.f);
                p0 += v00 * wv0[j] + v01 * wv1[j];
                p1 += v10 * wv0[j] + v11 * wv1[j];
            }
            p0 += __shfl_xor_sync(0xffffffffu, p0, 1);
            p0 += __shfl_xor_sync(0xffffffffu, p0, 2);
            p1 += __shfl_xor_sync(0xffffffffu, p1, 1);
            p1 += __shfl_xor_sync(0xffffffffu, p1, 2);
            if ((lane & 3) == 0) {
                if (row0 < M) atomicAdd(outp + (size_t)row0 * CHN + cblk, p0);
                if (row1 < M) atomicAdd(outp + (size_t)row1 * CHN + cblk, p1);
            }
        } else {
#pragma unroll
            for (int j = 0; j < 4; j++) {
                int colC = jB0 + warpN * 32 + j * 8 + tcol;
                float v00 = fmaxf(acc[i][j][0] + bv0[j], 0.f);
                float v01 = fmaxf(acc[i][j][1] + bv1[j], 0.f);
                float v10 = fmaxf(acc[i][j][2] + bv0[j], 0.f);
                float v11 = fmaxf(acc[i][j][3] + bv1[j], 0.f);

                if (MODE == 0) {
                    __nv_bfloat16 h00 = __float2bfloat16(v00), h01 = __float2bfloat16(v01);
                    __nv_bfloat16 h10 = __float2bfloat16(v10), h11 = __float2bfloat16(v11);
                    __nv_bfloat16* p0h = outH + (size_t)row0 * ldH + cblk * outHChanStride + colC;
                    __nv_bfloat16* p1h = outH + (size_t)row1 * ldH + cblk * outHChanStride + colC;
                    *(__nv_bfloat162*)p0h = __nv_bfloat162(h00, h01);
                    *(__nv_bfloat162*)p1h = __nv_bfloat162(h10, h11);
                    __nv_bfloat16 l00 = __float2bfloat16(v00 - __bfloat162float(h00));
                    __nv_bfloat16 l01 = __float2bfloat16(v01 - __bfloat162float(h01));
                    __nv_bfloat16 l10 = __float2bfloat16(v10 - __bfloat162float(h10));
                    __nv_bfloat16 l11 = __float2bfloat16(v11 - __bfloat162float(h11));
                    *(__nv_bfloat162*)(p0h + loDeltaOut) = __nv_bfloat162(l00, l01);
                    *(__nv_bfloat162*)(p1h + loDeltaOut) = __nv_bfloat162(l10, l11);
                } else {
                    // MODE 1 or 2: fp16 output
                    __half* p0g = outG + (size_t)row0 * ldG + cblk * outGChanStride + colC;
                    __half* p1g = outG + (size_t)row1 * ldG + cblk * outGChanStride + colC;
                    *(__half2*)p0g = __floats2half2_rn(v00, v01);
                    *(__half2*)p1g = __floats2half2_rn(v10, v11);
                    if (MODE == 1) {
                        int gcol = j0 + warpN * 32 + j * 8 + tcol;
                        *(float2*)(outF + (size_t)row0 * ldF + gcol) = make_float2(v00, v01);
                        *(float2*)(outF + (size_t)row1 * ldF + gcol) = make_float2(v10, v11);
                    }
                }
            }
        }
    }
}

__global__ void out_bias_relu_kernel(float* __restrict__ out, const float* __restrict__ b3, int n) {
    int i = blockIdx.x * blockDim.x + threadIdx.x;
    if (i >= n * CHN) return;
    float v = out[i] + b3[i & (CHN - 1)];
    out[i] = v > 0.f ? v : 0.f;
}

// ---------------- launch ----------------
extern "C" void kernel_launch(void* const* d_in, const int* in_sizes, int n_in,
                              void* d_out, int out_size)
{
    const float* x     = (const float*)d_in[0];
    const int*   edge  = (const int*)  d_in[1];
    const float* convW = (const float*)d_in[2];
    const float* convB = (const float*)d_in[3];
    const float* cW1   = (const float*)d_in[4];
    const float* cB1   = (const float*)d_in[5];
    const float* cW2   = (const float*)d_in[6];
    const float* cB2   = (const float*)d_in[7];
    const float* cW3   = (const float*)d_in[8];
    const float* cB3   = (const float*)d_in[9];
    float* out = (float*)d_out;

    int n = in_sizes[0] / DD;
    int E = in_sizes[1] / 2;

    float *cat;
    __nv_bfloat16 *convWex, *a0, *t0, *t1;
    __half *W1ex, *W2ex, *catF16, *H1;
    int *cnt;
    cudaGetSymbolAddress((void**)&cat, g_cat);
    cudaGetSymbolAddress((void**)&catF16, g_catF16);
    cudaGetSymbolAddress((void**)&a0, g_a0);
    cudaGetSymbolAddress((void**)&t0, g_t0);
    cudaGetSymbolAddress((void**)&t1, g_t1);
    cudaGetSymbolAddress((void**)&H1, g_H1);
    cudaGetSymbolAddress((void**)&convWex, g_convWex);
    cudaGetSymbolAddress((void**)&W1ex, g_W1ex);
    cudaGetSymbolAddress((void**)&W2ex, g_W2ex);
    cudaGetSymbolAddress((void**)&cnt, g_cnt);

    const int DSMEM = STAGES * STAGE_BYTES;
    cudaFuncSetAttribute(mma_gemm<0, 0>, cudaFuncAttributeMaxDynamicSharedMemorySize, DSMEM);
    cudaFuncSetAttribute(mma_gemm<1, 0>, cudaFuncAttributeMaxDynamicSharedMemorySize, DSMEM);
    cudaFuncSetAttribute(mma_gemm<2, 1>, cudaFuncAttributeMaxDynamicSharedMemorySize, DSMEM);
    cudaFuncSetAttribute(mma_gemm<3, 1>, cudaFuncAttributeMaxDynamicSharedMemorySize, DSMEM);

    const int mBlocks = (n + 127) / 128;
    const int BIG = 1 << 30;

    // weight expansion
    { dim3 g((128 * 128 + 255) / 256, 9); expand_w_kernel<<<g, 256>>>(convW, convWex, 128, 128); }
    { dim3 g((512 * 256 + 255) / 256, CHN); expand_w16_kernel<<<g, 256>>>(cW1, W1ex, 512, 256); }
    { dim3 g((256 * 256 + 255) / 256, CHN); expand_w16_kernel<<<g, 256>>>(cW2, W2ex, 256, 256); }

    prep_x_kernel<<<(n * 32 + 255) / 256, 256>>>(x, n);

    // CSR build (once)
    cudaMemsetAsync(cnt, 0, (size_t)(n + 1) * sizeof(int), 0);
    hist_kernel<<<(E + 255) / 256, 256>>>(edge, E);
    int nb = (n + 1023) / 1024;
    scan1_kernel<<<nb, 256>>>(n);
    scan2_kernel<<<1, 32>>>(nb);
    scan3_kernel<<<(n + 255) / 256, 256>>>(n, E);
    fill_kernel<<<(E + 255) / 256, 256>>>(edge, E);

    for (int l = 0; l < LL; l++) {
        {
            long th = (long)n * 32;
            gather_kernel<<<(int)((th + 255) / 256), 256>>>(n, l * DD);
        }

        const float* b0 = convB + (size_t)(l * 3 + 0) * DD;
        const float* b1 = convB + (size_t)(l * 3 + 1) * DD;
        const float* b2 = convB + (size_t)(l * 3 + 2) * DD;
        const __nv_bfloat16* B0 = convWex + (size_t)(l * 3 + 0) * 128 * 384;
        const __nv_bfloat16* B1 = convWex + (size_t)(l * 3 + 1) * 128 * 384;
        const __nv_bfloat16* B2 = convWex + (size_t)(l * 3 + 2) * 128 * 384;

        dim3 grid(1, mBlocks);
        // conv1: bf16x3, bf16 hi/lo out
        mma_gemm<0, 0><<<grid, 256, DSMEM>>>(a0, 256, 0, 128, 128, 384, B0, 0, BIG, b0, 0,
                                             nullptr, 0, t0, 256, 0, 128,
                                             nullptr, 0, 0, nullptr, nullptr, n);
        // conv2
        mma_gemm<0, 0><<<grid, 256, DSMEM>>>(t0, 256, 0, 128, 128, 384, B1, 0, BIG, b1, 0,
                                             nullptr, 0, t1, 256, 0, 128,
                                             nullptr, 0, 0, nullptr, nullptr, n);
        // conv3: fp32 cat + fp16 catF16
        mma_gemm<1, 0><<<grid, 256, DSMEM>>>(t1, 256, 0, 128, 128, 384, B2, 0, BIG, b2, 0,
                                             cat + (l + 1) * DD, OCW,
                                             nullptr, 0, 0, 0,
                                             catF16 + (l + 1) * DD, OCW, 0,
                                             nullptr, nullptr, n);
    }

    // channel MLP layer 1: fp16x2, K=512, Kex=1024 -> H1 fp16 [N,1024]
    {
        dim3 grid((CHN * CHID) / 128, mBlocks);
        mma_gemm<2, 1><<<grid, 256, DSMEM>>>((const __nv_bfloat16*)catF16, OCW, 0, 0, 512, 1024,
                                             (const __nv_bfloat16*)W1ex, (long)256 * 1024, CHID,
                                             cB1, CHID,
                                             nullptr, 0, nullptr, 0, 0, 0,
                                             H1, 1024, CHID,
                                             nullptr, nullptr, n);
    }

    // channel MLP layer 2 + fused final dot: fp16x2, K=256, Kex=512
    cudaMemsetAsync(out, 0, (size_t)n * CHN * sizeof(float), 0);
    {
        dim3 grid((CHN * CHID) / 128, mBlocks);
        mma_gemm<3, 1><<<grid, 256, DSMEM>>>((const __nv_bfloat16*)H1, 1024, 256, 0, 256, 512,
                                             (const __nv_bfloat16*)W2ex, (long)256 * 512, CHID,
                                             cB2, CHID,
                                             nullptr, 0, nullptr, 0, 0, 0,
                                             nullptr, 0, 0,
                                             cW3, out, n);
    }

    out_bias_relu_kernel<<<(n * CHN + 255) / 256, 256>>>(out, cB3, n);
}

// round 11
// speedup vs baseline: 4.2306x; 1.2175x over previous
#include <cuda_runtime.h>
#include <cuda_bf16.h>
#include <cuda_fp16.h>
#include <cstdint>

// Problem constants
#define NMAX   100000
#define NPAD   100128
#define DD     128
#define LL     3
#define OCW    512
#define CHN    4
#define CHID   256
#define EMAX   2000000

// ---------------- static device scratch ----------------
__device__ float g_cat[(size_t)NPAD * OCW];             // fp32 concat (gather source)
__device__ __half g_catF16[(size_t)NPAD * OCW];         // fp16 concat (MLP1 input)
__device__ __nv_bfloat16 g_a0[(size_t)NPAD * 256];      // conv input [hi128|lo128]
__device__ __nv_bfloat16 g_t0[(size_t)NPAD * 256];
__device__ __nv_bfloat16 g_t1[(size_t)NPAD * 256];
__device__ __half g_H1[(size_t)NPAD * 1024];            // fp16 [N,1024] plain
__device__ __nv_bfloat16 g_convWex[(size_t)9 * 128 * 384];   // bf16x3 [hi|lo|hi]
__device__ __half g_W1p [(size_t)CHN * 256 * 512];           // fp16 plain [N,K]
__device__ __half g_W2ex[(size_t)CHN * 256 * 512];           // fp16x2 interleaved 64-chunks
// CSR
__device__ int g_cnt   [NPAD + 1];
__device__ int g_rowptr[NPAD + 1];
__device__ int g_wp    [NPAD + 1];
__device__ int g_bsum  [256];
__device__ int g_csr   [EMAX];

// ---------------- helpers ----------------
__device__ __forceinline__ uint32_t smem_u32(const void* p) {
    uint32_t r;
    asm("{ .reg .u64 t; cvta.to.shared.u64 t, %1; cvt.u32.u64 %0, t; }" : "=r"(r) : "l"(p));
    return r;
}
#define LDSM_X4(r0, r1, r2, r3, addr) \
    asm volatile("ldmatrix.sync.aligned.m8n8.x4.shared.b16 {%0,%1,%2,%3}, [%4];" \
        : "=r"(r0), "=r"(r1), "=r"(r2), "=r"(r3) : "r"(addr))

__device__ __forceinline__ void mma_bf16(float* c, const uint32_t* a, uint32_t b0, uint32_t b1) {
    asm volatile(
        "mma.sync.aligned.m16n8k16.row.col.f32.bf16.bf16.f32 "
        "{%0,%1,%2,%3}, {%4,%5,%6,%7}, {%8,%9}, {%0,%1,%2,%3};"
        : "+f"(c[0]), "+f"(c[1]), "+f"(c[2]), "+f"(c[3])
        : "r"(a[0]), "r"(a[1]), "r"(a[2]), "r"(a[3]), "r"(b0), "r"(b1));
}
__device__ __forceinline__ void mma_fp16(float* c, const uint32_t* a, uint32_t b0, uint32_t b1) {
    asm volatile(
        "mma.sync.aligned.m16n8k16.row.col.f32.f16.f16.f32 "
        "{%0,%1,%2,%3}, {%4,%5,%6,%7}, {%8,%9}, {%0,%1,%2,%3};"
        : "+f"(c[0]), "+f"(c[1]), "+f"(c[2]), "+f"(c[3])
        : "r"(a[0]), "r"(a[1]), "r"(a[2]), "r"(a[3]), "r"(b0), "r"(b1));
}
__device__ __forceinline__ void cp16(uint32_t dst, const void* src) {
    asm volatile("cp.async.cg.shared.global [%0], [%1], 16;" :: "r"(dst), "l"(src));
}
#define CP_COMMIT() asm volatile("cp.async.commit_group;" ::: "memory")

// ---------------- weight expansion: bf16x3 [hi|lo|hi] ----------------
__global__ void expand_w_kernel(const float* __restrict__ W, __nv_bfloat16* __restrict__ Bex,
                                int K, int N) {
    int mi = blockIdx.y;
    const float* Wm = W + (size_t)mi * K * N;
    __nv_bfloat16* Bm = Bex + (size_t)mi * N * 3 * K;
    int id = blockIdx.x * blockDim.x + threadIdx.x;
    if (id >= K * N) return;
    int k = id / N, n = id % N;
    float w = Wm[id];
    __nv_bfloat16 hi = __float2bfloat16(w);
    __nv_bfloat16 lo = __float2bfloat16(w - __bfloat162float(hi));
    Bm[(size_t)n * 3 * K + k]         = hi;
    Bm[(size_t)n * 3 * K + K + k]     = lo;
    Bm[(size_t)n * 3 * K + 2 * K + k] = hi;
}

// ---------------- weight expansion: fp16x2 interleaved 64-chunks ----------------
__global__ void expand_w16_kernel(const float* __restrict__ W, __half* __restrict__ Bex,
                                  int K, int N) {
    int mi = blockIdx.y;
    const float* Wm = W + (size_t)mi * K * N;
    __half* Bm = Bex + (size_t)mi * N * 2 * K;
    int id = blockIdx.x * blockDim.x + threadIdx.x;
    if (id >= K * N) return;
    int k = id / N, n = id % N;
    float w = Wm[id];
    __half hi = __float2half(w);
    __half lo = __float2half(w - __half2float(hi));
    int b = k >> 6, r = k & 63;
    Bm[(size_t)n * 2 * K + b * 128 + r]      = hi;
    Bm[(size_t)n * 2 * K + b * 128 + 64 + r] = lo;
}

// ---------------- weight expansion: plain fp16 [N,K] ----------------
__global__ void expand_w16p_kernel(const float* __restrict__ W, __half* __restrict__ Bp,
                                   int K, int N) {
    int mi = blockIdx.y;
    const float* Wm = W + (size_t)mi * K * N;
    __half* Bm = Bp + (size_t)mi * N * K;
    int id = blockIdx.x * blockDim.x + threadIdx.x;
    if (id >= K * N) return;
    int k = id / N, n = id % N;
    Bm[(size_t)n * K + k] = __float2half(Wm[id]);
}

__device__ __forceinline__ void store_hilo4(__nv_bfloat16* p, int loDelta, float4 v) {
    __nv_bfloat16 h0 = __float2bfloat16(v.x), h1 = __float2bfloat16(v.y);
    __nv_bfloat16 h2 = __float2bfloat16(v.z), h3 = __float2bfloat16(v.w);
    ((__nv_bfloat162*)p)[0] = __nv_bfloat162(h0, h1);
    ((__nv_bfloat162*)p)[1] = __nv_bfloat162(h2, h3);
    __nv_bfloat16 l0 = __float2bfloat16(v.x - __bfloat162float(h0));
    __nv_bfloat16 l1 = __float2bfloat16(v.y - __bfloat162float(h1));
    __nv_bfloat16 l2 = __float2bfloat16(v.z - __bfloat162float(h2));
    __nv_bfloat16 l3 = __float2bfloat16(v.w - __bfloat162float(h3));
    ((__nv_bfloat162*)(p + loDelta))[0] = __nv_bfloat162(l0, l1);
    ((__nv_bfloat162*)(p + loDelta))[1] = __nv_bfloat162(l2, l3);
}

__global__ void prep_x_kernel(const float* __restrict__ x, int n) {
    int i = blockIdx.x * blockDim.x + threadIdx.x;
    if (i >= n * 32) return;
    int row = i >> 5, c4 = i & 31;
    float4 v = ((const float4*)x)[i];
    ((float4*)g_cat)[(size_t)row * 128 + c4] = v;
    __half* p = g_catF16 + (size_t)row * OCW + c4 * 4;
    ((__half2*)p)[0] = __floats2half2_rn(v.x, v.y);
    ((__half2*)p)[1] = __floats2half2_rn(v.z, v.w);
}

// ---------------- CSR build ----------------
__global__ void hist_kernel(const int* __restrict__ edge, int E) {
    int e = blockIdx.x * blockDim.x + threadIdx.x;
    if (e < E) atomicAdd(&g_cnt[__ldg(edge + E + e)], 1);
}
__global__ void scan1_kernel(int n) {
    __shared__ int warpSums[8];
    int t = threadIdx.x;
    int base = blockIdx.x * 1024 + t * 4;
    int v[4];
#pragma unroll
    for (int j = 0; j < 4; j++) v[j] = (base + j < n) ? g_cnt[base + j] : 0;
    int tsum = v[0] + v[1] + v[2] + v[3];
    int lane = t & 31, w = t >> 5;
    int x = tsum;
#pragma unroll
    for (int o = 1; o < 32; o <<= 1) {
        int y = __shfl_up_sync(0xffffffffu, x, o);
        if (lane >= o) x += y;
    }
    int excl = x - tsum;
    if (lane == 31) warpSums[w] = x;
    __syncthreads();
    if (t == 0) {
        int run = 0;
#pragma unroll
        for (int i = 0; i < 8; i++) { int tm = warpSums[i]; warpSums[i] = run; run += tm; }
        g_bsum[blockIdx.x] = run;
    }
    __syncthreads();
    int off = warpSums[w] + excl;
#pragma unroll
    for (int j = 0; j < 4; j++) {
        if (base + j < n) g_rowptr[base + j] = off;
        off += v[j];
    }
}
__global__ void scan2_kernel(int nb) {
    if (threadIdx.x == 0) {
        int run = 0;
        for (int i = 0; i < nb; i++) { int t = g_bsum[i]; g_bsum[i] = run; run += t; }
    }
}
__global__ void scan3_kernel(int n, int E) {
    int i = blockIdx.x * blockDim.x + threadIdx.x;
    if (i < n) {
        int v = g_rowptr[i] + g_bsum[i >> 10];
        g_rowptr[i] = v;
        g_wp[i] = v;
    }
    if (i == 0) g_rowptr[n] = E;
}
__global__ void fill_kernel(const int* __restrict__ edge, int E) {
    int e = blockIdx.x * blockDim.x + threadIdx.x;
    if (e >= E) return;
    int s = __ldg(edge + e);
    int d = __ldg(edge + E + e);
    int pos = atomicAdd(&g_wp[d], 1);
    g_csr[pos] = s;
}

// ---------------- gather + prep fused ----------------
__global__ void gather_kernel(int n, int colOff) {
    int w = (blockIdx.x * blockDim.x + threadIdx.x) >> 5;
    if (w >= n) return;
    int lane = threadIdx.x & 31;
    int beg = __ldg(&g_rowptr[w]);
    int end = __ldg(&g_rowptr[w + 1]);
    const float* base = g_cat + colOff + lane * 4;
    float4 s = *(const float4*)(base + (size_t)w * OCW);
    int i = beg;
    for (; i + 1 < end; i += 2) {
        int s0 = __ldg(&g_csr[i]);
        int s1 = __ldg(&g_csr[i + 1]);
        float4 v0 = *(const float4*)(base + (size_t)s0 * OCW);
        float4 v1 = *(const float4*)(base + (size_t)s1 * OCW);
        s.x += v0.x; s.y += v0.y; s.z += v0.z; s.w += v0.w;
        s.x += v1.x; s.y += v1.y; s.z += v1.z; s.w += v1.w;
    }
    if (i < end) {
        int s0 = __ldg(&g_csr[i]);
        float4 v0 = *(const float4*)(base + (size_t)s0 * OCW);
        s.x += v0.x; s.y += v0.y; s.z += v0.z; s.w += v0.w;
    }
    store_hilo4(g_a0 + (size_t)w * 256 + lane * 4, 128, s);
}

// ---------------- mma.sync GEMM, cp.async 3-stage pipeline ----------------
// DT=0: bf16x3 expanded (Kex=3K), A [hi|..|lo at loOffA], bf16 mma
// DT=1: fp16x2 expanded (Kex=2K) interleaved 64-chunks, A plain fp16, src=(e>>7)*64+(e&63)
// DT=2: plain fp16 (Kex=K), src=e
// MODE 0: relu(acc+bias) -> bf16 hi/lo outH
// MODE 1: relu(acc+bias) -> fp32 outF + fp16 outG
// MODE 2: relu(acc+bias) -> fp16 outG (channel layout)
// MODE 3: fused final dot -> atomicAdd(outp)
#define STAGES      3
#define ROWB        144
#define A_BYTES     (128 * ROWB)
#define STAGE_BYTES (2 * A_BYTES)

template<int MODE, int DT>
__global__ void __launch_bounds__(256, 2)
mma_gemm(const __nv_bfloat16* __restrict__ A, int lda, int aChanStride, int loOffA,
         int K, int Kex,
         const __nv_bfloat16* __restrict__ Bx, long bChanStride, int chanWidth,
         const float* __restrict__ bias, int biasChanStride,
         float* __restrict__ outF, int ldF,
         __nv_bfloat16* __restrict__ outH, int ldH, int outHChanStride, int loDeltaOut,
         __half* __restrict__ outG, int ldG, int outGChanStride,
         const float* __restrict__ W3, float* __restrict__ outp, int M)
{
    extern __shared__ char smem[];
    uint32_t sb = smem_u32(smem);

    int tid = threadIdx.x;
    int lane = tid & 31;
    int wid = tid >> 5;
    int warpM = wid & 1;
    int warpN = wid >> 1;

    int j0 = blockIdx.x * 128;
    int m0 = blockIdx.y * 128;
    int cblk = j0 / chanWidth;
    int jB0 = j0 - cblk * chanWidth;

    const __nv_bfloat16* Ab = A + (size_t)cblk * aChanStride;
    const __nv_bfloat16* Bb = Bx + (size_t)cblk * bChanStride;

    float acc[4][4][4];
#pragma unroll
    for (int i = 0; i < 4; i++)
#pragma unroll
        for (int j = 0; j < 4; j++)
#pragma unroll
            for (int r = 0; r < 4; r++) acc[i][j][r] = 0.f;

    const int C = Kex / 64;

    auto ISSUE = [&](int c) {
        uint32_t st = sb + (c % STAGES) * STAGE_BYTES;
        int e0 = c * 64;
#pragma unroll
        for (int i = 0; i < 4; i++) {
            int id = tid + i * 256;
            int row = id >> 3;
            int kg  = id & 7;
            int e = e0 + kg * 8;
            int src;
            if (DT == 1)      src = ((e >> 7) << 6) + (e & 63);
            else if (DT == 2) src = e;
            else              src = e < K ? e : (e < 2 * K ? e - K : e - 2 * K + loOffA);
            cp16(st + row * ROWB + kg * 16,
                 Ab + (size_t)(m0 + row) * lda + src);
            cp16(st + A_BYTES + row * ROWB + kg * 16,
                 Bb + (size_t)(jB0 + row) * Kex + e);
        }
        CP_COMMIT();
    };

    ISSUE(0);
    if (C > 1) ISSUE(1);

    for (int c = 0; c < C; c++) {
        if (c == C - 1) asm volatile("cp.async.wait_group 0;" ::: "memory");
        else            asm volatile("cp.async.wait_group 1;" ::: "memory");
        __syncthreads();
        if (c + STAGES - 1 < C) ISSUE(c + STAGES - 1);

        uint32_t aBase = sb + (c % STAGES) * STAGE_BYTES;
        uint32_t bBase = aBase + A_BYTES;

#pragma unroll
        for (int ks = 0; ks < 4; ks++) {
            uint32_t af[4][4], bf[2][4];
            int kcol = ks * 16 + (lane >> 4) * 8;
#pragma unroll
            for (int i = 0; i < 4; i++) {
                uint32_t addr = aBase + (uint32_t)((warpM * 64 + i * 16 + (lane & 15)) * ROWB + kcol * 2);
                LDSM_X4(af[i][0], af[i][1], af[i][2], af[i][3], addr);
            }
#pragma unroll
            for (int jj = 0; jj < 2; jj++) {
                uint32_t addr = bBase + (uint32_t)((warpN * 32 + jj * 16 + (lane & 15)) * ROWB + kcol * 2);
                LDSM_X4(bf[jj][0], bf[jj][1], bf[jj][2], bf[jj][3], addr);
            }
#pragma unroll
            for (int i = 0; i < 4; i++)
#pragma unroll
                for (int j = 0; j < 4; j++) {
                    int jj = j >> 1, sel = j & 1;
                    if (DT == 0) mma_bf16(acc[i][j], af[i], bf[jj][sel], bf[jj][sel + 2]);
                    else         mma_fp16(acc[i][j], af[i], bf[jj][sel], bf[jj][sel + 2]);
                }
        }
        __syncthreads();
    }

    // ---------------- epilogue ----------------
    int groupID = lane >> 2;
    int tcol = (lane & 3) * 2;

    float bv0[4], bv1[4], wv0[4], wv1[4];
#pragma unroll
    for (int j = 0; j < 4; j++) {
        int colC = jB0 + warpN * 32 + j * 8 + tcol;
        const float* bp = bias + (size_t)cblk * biasChanStride + colC;
        bv0[j] = __ldg(bp);
        bv1[j] = __ldg(bp + 1);
        if (MODE == 3) {
            wv0[j] = __ldg(W3 + (size_t)cblk * CHID + colC);
            wv1[j] = __ldg(W3 + (size_t)cblk * CHID + colC + 1);
        }
    }

#pragma unroll
    for (int i = 0; i < 4; i++) {
        int row0 = m0 + warpM * 64 + i * 16 + groupID;
        int row1 = row0 + 8;
        if (MODE == 3) {
            float p0 = 0.f, p1 = 0.f;
#pragma unroll
            for (int j = 0; j < 4; j++) {
                float v00 = fmaxf(acc[i][j][0] + bv0[j], 0.f);
                float v01 = fmaxf(acc[i][j][1] + bv1[j], 0.f);
                float v10 = fmaxf(acc[i][j][2] + bv0[j], 0.f);
                float v11 = fmaxf(acc[i][j][3] + bv1[j], 0.f);
                p0 += v00 * wv0[j] + v01 * wv1[j];
                p1 += v10 * wv0[j] + v11 * wv1[j];
            }
            p0 += __shfl_xor_sync(0xffffffffu, p0, 1);
            p0 += __shfl_xor_sync(0xffffffffu, p0, 2);
            p1 += __shfl_xor_sync(0xffffffffu, p1, 1);
            p1 += __shfl_xor_sync(0xffffffffu, p1, 2);
            if ((lane & 3) == 0) {
                if (row0 < M) atomicAdd(outp + (size_t)row0 * CHN + cblk, p0);
                if (row1 < M) atomicAdd(outp + (size_t)row1 * CHN + cblk, p1);
            }
        } else {
#pragma unroll
            for (int j = 0; j < 4; j++) {
                int colC = jB0 + warpN * 32 + j * 8 + tcol;
                float v00 = fmaxf(acc[i][j][0] + bv0[j], 0.f);
                float v01 = fmaxf(acc[i][j][1] + bv1[j], 0.f);
                float v10 = fmaxf(acc[i][j][2] + bv0[j], 0.f);
                float v11 = fmaxf(acc[i][j][3] + bv1[j], 0.f);

                if (MODE == 0) {
                    __nv_bfloat16 h00 = __float2bfloat16(v00), h01 = __float2bfloat16(v01);
                    __nv_bfloat16 h10 = __float2bfloat16(v10), h11 = __float2bfloat16(v11);
                    __nv_bfloat16* p0h = outH + (size_t)row0 * ldH + cblk * outHChanStride + colC;
                    __nv_bfloat16* p1h = outH + (size_t)row1 * ldH + cblk * outHChanStride + colC;
                    *(__nv_bfloat162*)p0h = __nv_bfloat162(h00, h01);
                    *(__nv_bfloat162*)p1h = __nv_bfloat162(h10, h11);
                    __nv_bfloat16 l00 = __float2bfloat16(v00 - __bfloat162float(h00));
                    __nv_bfloat16 l01 = __float2bfloat16(v01 - __bfloat162float(h01));
                    __nv_bfloat16 l10 = __float2bfloat16(v10 - __bfloat162float(h10));
                    __nv_bfloat16 l11 = __float2bfloat16(v11 - __bfloat162float(h11));
                    *(__nv_bfloat162*)(p0h + loDeltaOut) = __nv_bfloat162(l00, l01);
                    *(__nv_bfloat162*)(p1h + loDeltaOut) = __nv_bfloat162(l10, l11);
                } else {
                    __half* p0g = outG + (size_t)row0 * ldG + cblk * outGChanStride + colC;
                    __half* p1g = outG + (size_t)row1 * ldG + cblk * outGChanStride + colC;
                    *(__half2*)p0g = __floats2half2_rn(v00, v01);
                    *(__half2*)p1g = __floats2half2_rn(v10, v11);
                    if (MODE == 1) {
                        int gcol = j0 + warpN * 32 + j * 8 + tcol;
                        *(float2*)(outF + (size_t)row0 * ldF + gcol) = make_float2(v00, v01);
                        *(float2*)(outF + (size_t)row1 * ldF + gcol) = make_float2(v10, v11);
                    }
                }
            }
        }
    }
}

__global__ void out_bias_relu_kernel(float* __restrict__ out, const float* __restrict__ b3, int n) {
    int i = blockIdx.x * blockDim.x + threadIdx.x;
    if (i >= n * CHN) return;
    float v = out[i] + b3[i & (CHN - 1)];
    out[i] = v > 0.f ? v : 0.f;
}

// ---------------- launch ----------------
extern "C" void kernel_launch(void* const* d_in, const int* in_sizes, int n_in,
                              void* d_out, int out_size)
{
    const float* x     = (const float*)d_in[0];
    const int*   edge  = (const int*)  d_in[1];
    const float* convW = (const float*)d_in[2];
    const float* convB = (const float*)d_in[3];
    const float* cW1   = (const float*)d_in[4];
    const float* cB1   = (const float*)d_in[5];
    const float* cW2   = (const float*)d_in[6];
    const float* cB2   = (const float*)d_in[7];
    const float* cW3   = (const float*)d_in[8];
    const float* cB3   = (const float*)d_in[9];
    float* out = (float*)d_out;

    int n = in_sizes[0] / DD;
    int E = in_sizes[1] / 2;

    float *cat;
    __nv_bfloat16 *convWex, *a0, *t0, *t1;
    __half *W1p, *W2ex, *catF16, *H1;
    int *cnt;
    cudaGetSymbolAddress((void**)&cat, g_cat);
    cudaGetSymbolAddress((void**)&catF16, g_catF16);
    cudaGetSymbolAddress((void**)&a0, g_a0);
    cudaGetSymbolAddress((void**)&t0, g_t0);
    cudaGetSymbolAddress((void**)&t1, g_t1);
    cudaGetSymbolAddress((void**)&H1, g_H1);
    cudaGetSymbolAddress((void**)&convWex, g_convWex);
    cudaGetSymbolAddress((void**)&W1p, g_W1p);
    cudaGetSymbolAddress((void**)&W2ex, g_W2ex);
    cudaGetSymbolAddress((void**)&cnt, g_cnt);

    const int DSMEM = STAGES * STAGE_BYTES;
    cudaFuncSetAttribute(mma_gemm<0, 0>, cudaFuncAttributeMaxDynamicSharedMemorySize, DSMEM);
    cudaFuncSetAttribute(mma_gemm<1, 0>, cudaFuncAttributeMaxDynamicSharedMemorySize, DSMEM);
    cudaFuncSetAttribute(mma_gemm<2, 2>, cudaFuncAttributeMaxDynamicSharedMemorySize, DSMEM);
    cudaFuncSetAttribute(mma_gemm<3, 1>, cudaFuncAttributeMaxDynamicSharedMemorySize, DSMEM);

    const int mBlocks = (n + 127) / 128;
    const int BIG = 1 << 30;

    // weight expansion
    { dim3 g((128 * 128 + 255) / 256, 9); expand_w_kernel<<<g, 256>>>(convW, convWex, 128, 128); }
    { dim3 g((512 * 256 + 255) / 256, CHN); expand_w16p_kernel<<<g, 256>>>(cW1, W1p, 512, 256); }
    { dim3 g((256 * 256 + 255) / 256, CHN); expand_w16_kernel<<<g, 256>>>(cW2, W2ex, 256, 256); }

    prep_x_kernel<<<(n * 32 + 255) / 256, 256>>>(x, n);

    // CSR build (once)
    cudaMemsetAsync(cnt, 0, (size_t)(n + 1) * sizeof(int), 0);
    hist_kernel<<<(E + 255) / 256, 256>>>(edge, E);
    int nb = (n + 1023) / 1024;
    scan1_kernel<<<nb, 256>>>(n);
    scan2_kernel<<<1, 32>>>(nb);
    scan3_kernel<<<(n + 255) / 256, 256>>>(n, E);
    fill_kernel<<<(E + 255) / 256, 256>>>(edge, E);

    for (int l = 0; l < LL; l++) {
        {
            long th = (long)n * 32;
            gather_kernel<<<(int)((th + 255) / 256), 256>>>(n, l * DD);
        }

        const float* b0 = convB + (size_t)(l * 3 + 0) * DD;
        const float* b1 = convB + (size_t)(l * 3 + 1) * DD;
        const float* b2 = convB + (size_t)(l * 3 + 2) * DD;
        const __nv_bfloat16* B0 = convWex + (size_t)(l * 3 + 0) * 128 * 384;
        const __nv_bfloat16* B1 = convWex + (size_t)(l * 3 + 1) * 128 * 384;
        const __nv_bfloat16* B2 = convWex + (size_t)(l * 3 + 2) * 128 * 384;

        dim3 grid(1, mBlocks);
        mma_gemm<0, 0><<<grid, 256, DSMEM>>>(a0, 256, 0, 128, 128, 384, B0, 0, BIG, b0, 0,
                                             nullptr, 0, t0, 256, 0, 128,
                                             nullptr, 0, 0, nullptr, nullptr, n);
        mma_gemm<0, 0><<<grid, 256, DSMEM>>>(t0, 256, 0, 128, 128, 384, B1, 0, BIG, b1, 0,
                                             nullptr, 0, t1, 256, 0, 128,
                                             nullptr, 0, 0, nullptr, nullptr, n);
        mma_gemm<1, 0><<<grid, 256, DSMEM>>>(t1, 256, 0, 128, 128, 384, B2, 0, BIG, b2, 0,
                                             cat + (l + 1) * DD, OCW,
                                             nullptr, 0, 0, 0,
                                             catF16 + (l + 1) * DD, OCW, 0,
                                             nullptr, nullptr, n);
    }

    // channel MLP layer 1: plain fp16, K=Kex=512 -> H1 fp16 [N,1024]
    {
        dim3 grid((CHN * CHID) / 128, mBlocks);
        mma_gemm<2, 2><<<grid, 256, DSMEM>>>((const __nv_bfloat16*)catF16, OCW, 0, 0, 512, 512,
                                             (const __nv_bfloat16*)W1p, (long)256 * 512, CHID,
                                             cB1, CHID,
                                             nullptr, 0, nullptr, 0, 0, 0,
                                             H1, 1024, CHID,
                                             nullptr, nullptr, n);
    }

    // channel MLP layer 2 + fused final dot: fp16x2, K=256, Kex=512
    cudaMemsetAsync(out, 0, (size_t)n * CHN * sizeof(float), 0);
    {
        dim3 grid((CHN * CHID) / 128, mBlocks);
        mma_gemm<3, 1><<<grid, 256, DSMEM>>>((const __nv_bfloat16*)H1, 1024, 256, 0, 256, 512,
                                             (const __nv_bfloat16*)W2ex, (long)256 * 512, CHID,
                                             cB2, CHID,
                                             nullptr, 0, nullptr, 0, 0, 0,
                                             nullptr, 0, 0,
                                             cW3, out, n);
    }

    out_bias_relu_kernel<<<(n * CHN + 255) / 256, 256>>>(out, cB3, n);
}

// round 12
// speedup vs baseline: 4.7594x; 1.1250x over previous
#include <cuda_runtime.h>
#include <cuda_bf16.h>
#include <cuda_fp16.h>
#include <cstdint>

// Problem constants
#define NMAX   100000
#define NPAD   100128
#define DD     128
#define LL     3
#define OCW    512
#define CHN    4
#define CHID   256
#define EMAX   2000000

// ---------------- static device scratch ----------------
__device__ float g_cat[(size_t)NPAD * OCW];             // fp32 concat (gather source)
__device__ __half g_catF16[(size_t)NPAD * OCW];         // fp16 concat (MLP1 input)
__device__ __nv_bfloat16 g_a0[(size_t)NPAD * 256];      // conv input [hi128|lo128]
__device__ __nv_bfloat16 g_t0[(size_t)NPAD * 256];
__device__ __nv_bfloat16 g_t1[(size_t)NPAD * 256];
__device__ __half g_H1[(size_t)NPAD * 1024];            // fp16 [N,1024] plain
__device__ __nv_bfloat16 g_convWex[(size_t)9 * 128 * 384];   // bf16x3 [hi|lo|hi]
__device__ __half g_W1p[(size_t)CHN * 256 * 512];            // fp16 plain [N,K]
__device__ __half g_W2p[(size_t)CHN * 256 * 256];            // fp16 plain [N,K]
// CSR
__device__ int g_cnt   [NPAD + 1];
__device__ int g_rowptr[NPAD + 1];
__device__ int g_wp    [NPAD + 1];
__device__ int g_bsum  [256];
__device__ int g_csr   [EMAX];

// ---------------- helpers ----------------
__device__ __forceinline__ uint32_t smem_u32(const void* p) {
    uint32_t r;
    asm("{ .reg .u64 t; cvta.to.shared.u64 t, %1; cvt.u32.u64 %0, t; }" : "=r"(r) : "l"(p));
    return r;
}
#define LDSM_X4(r0, r1, r2, r3, addr) \
    asm volatile("ldmatrix.sync.aligned.m8n8.x4.shared.b16 {%0,%1,%2,%3}, [%4];" \
        : "=r"(r0), "=r"(r1), "=r"(r2), "=r"(r3) : "r"(addr))

__device__ __forceinline__ void mma_bf16(float* c, const uint32_t* a, uint32_t b0, uint32_t b1) {
    asm volatile(
        "mma.sync.aligned.m16n8k16.row.col.f32.bf16.bf16.f32 "
        "{%0,%1,%2,%3}, {%4,%5,%6,%7}, {%8,%9}, {%0,%1,%2,%3};"
        : "+f"(c[0]), "+f"(c[1]), "+f"(c[2]), "+f"(c[3])
        : "r"(a[0]), "r"(a[1]), "r"(a[2]), "r"(a[3]), "r"(b0), "r"(b1));
}
__device__ __forceinline__ void mma_fp16(float* c, const uint32_t* a, uint32_t b0, uint32_t b1) {
    asm volatile(
        "mma.sync.aligned.m16n8k16.row.col.f32.f16.f16.f32 "
        "{%0,%1,%2,%3}, {%4,%5,%6,%7}, {%8,%9}, {%0,%1,%2,%3};"
        : "+f"(c[0]), "+f"(c[1]), "+f"(c[2]), "+f"(c[3])
        : "r"(a[0]), "r"(a[1]), "r"(a[2]), "r"(a[3]), "r"(b0), "r"(b1));
}
__device__ __forceinline__ void cp16(uint32_t dst, const void* src) {
    asm volatile("cp.async.cg.shared.global [%0], [%1], 16;" :: "r"(dst), "l"(src));
}
#define CP_COMMIT() asm volatile("cp.async.commit_group;" ::: "memory")

// ---------------- weight expansion: bf16x3 [hi|lo|hi] ----------------
__global__ void expand_w_kernel(const float* __restrict__ W, __nv_bfloat16* __restrict__ Bex,
                                int K, int N) {
    int mi = blockIdx.y;
    const float* Wm = W + (size_t)mi * K * N;
    __nv_bfloat16* Bm = Bex + (size_t)mi * N * 3 * K;
    int id = blockIdx.x * blockDim.x + threadIdx.x;
    if (id >= K * N) return;
    int k = id / N, n = id % N;
    float w = Wm[id];
    __nv_bfloat16 hi = __float2bfloat16(w);
    __nv_bfloat16 lo = __float2bfloat16(w - __bfloat162float(hi));
    Bm[(size_t)n * 3 * K + k]         = hi;
    Bm[(size_t)n * 3 * K + K + k]     = lo;
    Bm[(size_t)n * 3 * K + 2 * K + k] = hi;
}

// ---------------- weight expansion: plain fp16 [N,K] ----------------
__global__ void expand_w16p_kernel(const float* __restrict__ W, __half* __restrict__ Bp,
                                   int K, int N) {
    int mi = blockIdx.y;
    const float* Wm = W + (size_t)mi * K * N;
    __half* Bm = Bp + (size_t)mi * N * K;
    int id = blockIdx.x * blockDim.x + threadIdx.x;
    if (id >= K * N) return;
    int k = id / N, n = id % N;
    Bm[(size_t)n * K + k] = __float2half(Wm[id]);
}

__device__ __forceinline__ void store_hilo4(__nv_bfloat16* p, int loDelta, float4 v) {
    __nv_bfloat16 h0 = __float2bfloat16(v.x), h1 = __float2bfloat16(v.y);
    __nv_bfloat16 h2 = __float2bfloat16(v.z), h3 = __float2bfloat16(v.w);
    ((__nv_bfloat162*)p)[0] = __nv_bfloat162(h0, h1);
    ((__nv_bfloat162*)p)[1] = __nv_bfloat162(h2, h3);
    __nv_bfloat16 l0 = __float2bfloat16(v.x - __bfloat162float(h0));
    __nv_bfloat16 l1 = __float2bfloat16(v.y - __bfloat162float(h1));
    __nv_bfloat16 l2 = __float2bfloat16(v.z - __bfloat162float(h2));
    __nv_bfloat16 l3 = __float2bfloat16(v.w - __bfloat162float(h3));
    ((__nv_bfloat162*)(p + loDelta))[0] = __nv_bfloat162(l0, l1);
    ((__nv_bfloat162*)(p + loDelta))[1] = __nv_bfloat162(l2, l3);
}

__global__ void prep_x_kernel(const float* __restrict__ x, int n) {
    int i = blockIdx.x * blockDim.x + threadIdx.x;
    if (i >= n * 32) return;
    int row = i >> 5, c4 = i & 31;
    float4 v = ((const float4*)x)[i];
    ((float4*)g_cat)[(size_t)row * 128 + c4] = v;
    __half* p = g_catF16 + (size_t)row * OCW + c4 * 4;
    ((__half2*)p)[0] = __floats2half2_rn(v.x, v.y);
    ((__half2*)p)[1] = __floats2half2_rn(v.z, v.w);
}

// ---------------- CSR build ----------------
__global__ void hist_kernel(const int* __restrict__ edge, int E) {
    int e = blockIdx.x * blockDim.x + threadIdx.x;
    if (e < E) atomicAdd(&g_cnt[__ldg(edge + E + e)], 1);
}
__global__ void scan1_kernel(int n) {
    __shared__ int warpSums[8];
    int t = threadIdx.x;
    int base = blockIdx.x * 1024 + t * 4;
    int v[4];
#pragma unroll
    for (int j = 0; j < 4; j++) v[j] = (base + j < n) ? g_cnt[base + j] : 0;
    int tsum = v[0] + v[1] + v[2] + v[3];
    int lane = t & 31, w = t >> 5;
    int x = tsum;
#pragma unroll
    for (int o = 1; o < 32; o <<= 1) {
        int y = __shfl_up_sync(0xffffffffu, x, o);
        if (lane >= o) x += y;
    }
    int excl = x - tsum;
    if (lane == 31) warpSums[w] = x;
    __syncthreads();
    if (t == 0) {
        int run = 0;
#pragma unroll
        for (int i = 0; i < 8; i++) { int tm = warpSums[i]; warpSums[i] = run; run += tm; }
        g_bsum[blockIdx.x] = run;
    }
    __syncthreads();
    int off = warpSums[w] + excl;
#pragma unroll
    for (int j = 0; j < 4; j++) {
        if (base + j < n) g_rowptr[base + j] = off;
        off += v[j];
    }
}
__global__ void scan2_kernel(int nb) {
    if (threadIdx.x == 0) {
        int run = 0;
        for (int i = 0; i < nb; i++) { int t = g_bsum[i]; g_bsum[i] = run; run += t; }
    }
}
__global__ void scan3_kernel(int n, int E) {
    int i = blockIdx.x * blockDim.x + threadIdx.x;
    if (i < n) {
        int v = g_rowptr[i] + g_bsum[i >> 10];
        g_rowptr[i] = v;
        g_wp[i] = v;
    }
    if (i == 0) g_rowptr[n] = E;
}
__global__ void fill_kernel(const int* __restrict__ edge, int E) {
    int e = blockIdx.x * blockDim.x + threadIdx.x;
    if (e >= E) return;
    int s = __ldg(edge + e);
    int d = __ldg(edge + E + e);
    int pos = atomicAdd(&g_wp[d], 1);
    g_csr[pos] = s;
}

// ---------------- gather + prep fused ----------------
__global__ void gather_kernel(int n, int colOff) {
    int w = (blockIdx.x * blockDim.x + threadIdx.x) >> 5;
    if (w >= n) return;
    int lane = threadIdx.x & 31;
    int beg = __ldg(&g_rowptr[w]);
    int end = __ldg(&g_rowptr[w + 1]);
    const float* base = g_cat + colOff + lane * 4;
    float4 s = *(const float4*)(base + (size_t)w * OCW);
    int i = beg;
    for (; i + 1 < end; i += 2) {
        int s0 = __ldg(&g_csr[i]);
        int s1 = __ldg(&g_csr[i + 1]);
        float4 v0 = *(const float4*)(base + (size_t)s0 * OCW);
        float4 v1 = *(const float4*)(base + (size_t)s1 * OCW);
        s.x += v0.x; s.y += v0.y; s.z += v0.z; s.w += v0.w;
        s.x += v1.x; s.y += v1.y; s.z += v1.z; s.w += v1.w;
    }
    if (i < end) {
        int s0 = __ldg(&g_csr[i]);
        float4 v0 = *(const float4*)(base + (size_t)s0 * OCW);
        s.x += v0.x; s.y += v0.y; s.z += v0.z; s.w += v0.w;
    }
    store_hilo4(g_a0 + (size_t)w * 256 + lane * 4, 128, s);
}

// ---------------- mma.sync GEMM, cp.async 3-stage pipeline ----------------
// DT=0: bf16x3 expanded (Kex=3K), A [hi|..|lo at loOffA], bf16 mma
// DT=2: plain fp16 (Kex=K), src=e
// MODE 0: relu(acc+bias) -> bf16 hi/lo outH
// MODE 1: relu(acc+bias) -> fp32 outF + fp16 outG
// MODE 2: relu(acc+bias) -> fp16 outG (channel layout)
// MODE 3: fused final dot -> atomicAdd(outp)
#define STAGES      3
#define ROWB        144
#define A_BYTES     (128 * ROWB)
#define STAGE_BYTES (2 * A_BYTES)

template<int MODE, int DT>
__global__ void __launch_bounds__(256, 2)
mma_gemm(const __nv_bfloat16* __restrict__ A, int lda, int aChanStride, int loOffA,
         int K, int Kex,
         const __nv_bfloat16* __restrict__ Bx, long bChanStride, int chanWidth,
         const float* __restrict__ bias, int biasChanStride,
         float* __restrict__ outF, int ldF,
         __nv_bfloat16* __restrict__ outH, int ldH, int outHChanStride, int loDeltaOut,
         __half* __restrict__ outG, int ldG, int outGChanStride,
         const float* __restrict__ W3, float* __restrict__ outp, int M)
{
    extern __shared__ char smem[];
    uint32_t sb = smem_u32(smem);

    int tid = threadIdx.x;
    int lane = tid & 31;
    int wid = tid >> 5;
    int warpM = wid & 1;
    int warpN = wid >> 1;

    int j0 = blockIdx.x * 128;
    int m0 = blockIdx.y * 128;
    int cblk = j0 / chanWidth;
    int jB0 = j0 - cblk * chanWidth;

    const __nv_bfloat16* Ab = A + (size_t)cblk * aChanStride;
    const __nv_bfloat16* Bb = Bx + (size_t)cblk * bChanStride;

    float acc[4][4][4];
#pragma unroll
    for (int i = 0; i < 4; i++)
#pragma unroll
        for (int j = 0; j < 4; j++)
#pragma unroll
            for (int r = 0; r < 4; r++) acc[i][j][r] = 0.f;

    const int C = Kex / 64;

    auto ISSUE = [&](int c) {
        uint32_t st = sb + (c % STAGES) * STAGE_BYTES;
        int e0 = c * 64;
#pragma unroll
        for (int i = 0; i < 4; i++) {
            int id = tid + i * 256;
            int row = id >> 3;
            int kg  = id & 7;
            int e = e0 + kg * 8;
            int src;
            if (DT == 2) src = e;
            else         src = e < K ? e : (e < 2 * K ? e - K : e - 2 * K + loOffA);
            cp16(st + row * ROWB + kg * 16,
                 Ab + (size_t)(m0 + row) * lda + src);
            cp16(st + A_BYTES + row * ROWB + kg * 16,
                 Bb + (size_t)(jB0 + row) * Kex + e);
        }
        CP_COMMIT();
    };

    ISSUE(0);
    if (C > 1) ISSUE(1);

    for (int c = 0; c < C; c++) {
        if (c == C - 1) asm volatile("cp.async.wait_group 0;" ::: "memory");
        else            asm volatile("cp.async.wait_group 1;" ::: "memory");
        __syncthreads();
        if (c + STAGES - 1 < C) ISSUE(c + STAGES - 1);

        uint32_t aBase = sb + (c % STAGES) * STAGE_BYTES;
        uint32_t bBase = aBase + A_BYTES;

#pragma unroll
        for (int ks = 0; ks < 4; ks++) {
            uint32_t af[4][4], bf[2][4];
            int kcol = ks * 16 + (lane >> 4) * 8;
#pragma unroll
            for (int i = 0; i < 4; i++) {
                uint32_t addr = aBase + (uint32_t)((warpM * 64 + i * 16 + (lane & 15)) * ROWB + kcol * 2);
                LDSM_X4(af[i][0], af[i][1], af[i][2], af[i][3], addr);
            }
#pragma unroll
            for (int jj = 0; jj < 2; jj++) {
                uint32_t addr = bBase + (uint32_t)((warpN * 32 + jj * 16 + (lane & 15)) * ROWB + kcol * 2);
                LDSM_X4(bf[jj][0], bf[jj][1], bf[jj][2], bf[jj][3], addr);
            }
#pragma unroll
            for (int i = 0; i < 4; i++)
#pragma unroll
                for (int j = 0; j < 4; j++) {
                    int jj = j >> 1, sel = j & 1;
                    if (DT == 0) mma_bf16(acc[i][j], af[i], bf[jj][sel], bf[jj][sel + 2]);
                    else         mma_fp16(acc[i][j], af[i], bf[jj][sel], bf[jj][sel + 2]);
                }
        }
        __syncthreads();
    }

    // ---------------- epilogue ----------------
    int groupID = lane >> 2;
    int tcol = (lane & 3) * 2;

    float bv0[4], bv1[4], wv0[4], wv1[4];
#pragma unroll
    for (int j = 0; j < 4; j++) {
        int colC = jB0 + warpN * 32 + j * 8 + tcol;
        const float* bp = bias + (size_t)cblk * biasChanStride + colC;
        bv0[j] = __ldg(bp);
        bv1[j] = __ldg(bp + 1);
        if (MODE == 3) {
            wv0[j] = __ldg(W3 + (size_t)cblk * CHID + colC);
            wv1[j] = __ldg(W3 + (size_t)cblk * CHID + colC + 1);
        }
    }

#pragma unroll
    for (int i = 0; i < 4; i++) {
        int row0 = m0 + warpM * 64 + i * 16 + groupID;
        int row1 = row0 + 8;
        if (MODE == 3) {
            float p0 = 0.f, p1 = 0.f;
#pragma unroll
            for (int j = 0; j < 4; j++) {
                float v00 = fmaxf(acc[i][j][0] + bv0[j], 0.f);
                float v01 = fmaxf(acc[i][j][1] + bv1[j], 0.f);
                float v10 = fmaxf(acc[i][j][2] + bv0[j], 0.f);
                float v11 = fmaxf(acc[i][j][3] + bv1[j], 0.f);
                p0 += v00 * wv0[j] + v01 * wv1[j];
                p1 += v10 * wv0[j] + v11 * wv1[j];
            }
            p0 += __shfl_xor_sync(0xffffffffu, p0, 1);
            p0 += __shfl_xor_sync(0xffffffffu, p0, 2);
            p1 += __shfl_xor_sync(0xffffffffu, p1, 1);
            p1 += __shfl_xor_sync(0xffffffffu, p1, 2);
            if ((lane & 3) == 0) {
                if (row0 < M) atomicAdd(outp + (size_t)row0 * CHN + cblk, p0);
                if (row1 < M) atomicAdd(outp + (size_t)row1 * CHN + cblk, p1);
            }
        } else {
#pragma unroll
            for (int j = 0; j < 4; j++) {
                int colC = jB0 + warpN * 32 + j * 8 + tcol;
                float v00 = fmaxf(acc[i][j][0] + bv0[j], 0.f);
                float v01 = fmaxf(acc[i][j][1] + bv1[j], 0.f);
                float v10 = fmaxf(acc[i][j][2] + bv0[j], 0.f);
                float v11 = fmaxf(acc[i][j][3] + bv1[j], 0.f);

                if (MODE == 0) {
                    __nv_bfloat16 h00 = __float2bfloat16(v00), h01 = __float2bfloat16(v01);
                    __nv_bfloat16 h10 = __float2bfloat16(v10), h11 = __float2bfloat16(v11);
                    __nv_bfloat16* p0h = outH + (size_t)row0 * ldH + cblk * outHChanStride + colC;
                    __nv_bfloat16* p1h = outH + (size_t)row1 * ldH + cblk * outHChanStride + colC;
                    *(__nv_bfloat162*)p0h = __nv_bfloat162(h00, h01);
                    *(__nv_bfloat162*)p1h = __nv_bfloat162(h10, h11);
                    __nv_bfloat16 l00 = __float2bfloat16(v00 - __bfloat162float(h00));
                    __nv_bfloat16 l01 = __float2bfloat16(v01 - __bfloat162float(h01));
                    __nv_bfloat16 l10 = __float2bfloat16(v10 - __bfloat162float(h10));
                    __nv_bfloat16 l11 = __float2bfloat16(v11 - __bfloat162float(h11));
                    *(__nv_bfloat162*)(p0h + loDeltaOut) = __nv_bfloat162(l00, l01);
                    *(__nv_bfloat162*)(p1h + loDeltaOut) = __nv_bfloat162(l10, l11);
                } else {
                    __half* p0g = outG + (size_t)row0 * ldG + cblk * outGChanStride + colC;
                    __half* p1g = outG + (size_t)row1 * ldG + cblk * outGChanStride + colC;
                    *(__half2*)p0g = __floats2half2_rn(v00, v01);
                    *(__half2*)p1g = __floats2half2_rn(v10, v11);
                    if (MODE == 1) {
                        int gcol = j0 + warpN * 32 + j * 8 + tcol;
                        *(float2*)(outF + (size_t)row0 * ldF + gcol) = make_float2(v00, v01);
                        *(float2*)(outF + (size_t)row1 * ldF + gcol) = make_float2(v10, v11);
                    }
                }
            }
        }
    }
}

__global__ void out_bias_relu_kernel(float* __restrict__ out, const float* __restrict__ b3, int n) {
    int i = blockIdx.x * blockDim.x + threadIdx.x;
    if (i >= n * CHN) return;
    float v = out[i] + b3[i & (CHN - 1)];
    out[i] = v > 0.f ? v : 0.f;
}

// ---------------- launch ----------------
extern "C" void kernel_launch(void* const* d_in, const int* in_sizes, int n_in,
                              void* d_out, int out_size)
{
    const float* x     = (const float*)d_in[0];
    const int*   edge  = (const int*)  d_in[1];
    const float* convW = (const float*)d_in[2];
    const float* convB = (const float*)d_in[3];
    const float* cW1   = (const float*)d_in[4];
    const float* cB1   = (const float*)d_in[5];
    const float* cW2   = (const float*)d_in[6];
    const float* cB2   = (const float*)d_in[7];
    const float* cW3   = (const float*)d_in[8];
    const float* cB3   = (const float*)d_in[9];
    float* out = (float*)d_out;

    int n = in_sizes[0] / DD;
    int E = in_sizes[1] / 2;

    float *cat;
    __nv_bfloat16 *convWex, *a0, *t0, *t1;
    __half *W1p, *W2p, *catF16, *H1;
    int *cnt;
    cudaGetSymbolAddress((void**)&cat, g_cat);
    cudaGetSymbolAddress((void**)&catF16, g_catF16);
    cudaGetSymbolAddress((void**)&a0, g_a0);
    cudaGetSymbolAddress((void**)&t0, g_t0);
    cudaGetSymbolAddress((void**)&t1, g_t1);
    cudaGetSymbolAddress((void**)&H1, g_H1);
    cudaGetSymbolAddress((void**)&convWex, g_convWex);
    cudaGetSymbolAddress((void**)&W1p, g_W1p);
    cudaGetSymbolAddress((void**)&W2p, g_W2p);
    cudaGetSymbolAddress((void**)&cnt, g_cnt);

    const int DSMEM = STAGES * STAGE_BYTES;
    cudaFuncSetAttribute(mma_gemm<0, 0>, cudaFuncAttributeMaxDynamicSharedMemorySize, DSMEM);
    cudaFuncSetAttribute(mma_gemm<1, 0>, cudaFuncAttributeMaxDynamicSharedMemorySize, DSMEM);
    cudaFuncSetAttribute(mma_gemm<2, 2>, cudaFuncAttributeMaxDynamicSharedMemorySize, DSMEM);
    cudaFuncSetAttribute(mma_gemm<3, 2>, cudaFuncAttributeMaxDynamicSharedMemorySize, DSMEM);

    const int mBlocks = (n + 127) / 128;
    const int BIG = 1 << 30;

    // weight expansion
    { dim3 g((128 * 128 + 255) / 256, 9); expand_w_kernel<<<g, 256>>>(convW, convWex, 128, 128); }
    { dim3 g((512 * 256 + 255) / 256, CHN); expand_w16p_kernel<<<g, 256>>>(cW1, W1p, 512, 256); }
    { dim3 g((256 * 256 + 255) / 256, CHN); expand_w16p_kernel<<<g, 256>>>(cW2, W2p, 256, 256); }

    prep_x_kernel<<<(n * 32 + 255) / 256, 256>>>(x, n);

    // CSR build (once)
    cudaMemsetAsync(cnt, 0, (size_t)(n + 1) * sizeof(int), 0);
    hist_kernel<<<(E + 255) / 256, 256>>>(edge, E);
    int nb = (n + 1023) / 1024;
    scan1_kernel<<<nb, 256>>>(n);
    scan2_kernel<<<1, 32>>>(nb);
    scan3_kernel<<<(n + 255) / 256, 256>>>(n, E);
    fill_kernel<<<(E + 255) / 256, 256>>>(edge, E);

    for (int l = 0; l < LL; l++) {
        {
            long th = (long)n * 32;
            gather_kernel<<<(int)((th + 255) / 256), 256>>>(n, l * DD);
        }

        const float* b0 = convB + (size_t)(l * 3 + 0) * DD;
        const float* b1 = convB + (size_t)(l * 3 + 1) * DD;
        const float* b2 = convB + (size_t)(l * 3 + 2) * DD;
        const __nv_bfloat16* B0 = convWex + (size_t)(l * 3 + 0) * 128 * 384;
        const __nv_bfloat16* B1 = convWex + (size_t)(l * 3 + 1) * 128 * 384;
        const __nv_bfloat16* B2 = convWex + (size_t)(l * 3 + 2) * 128 * 384;

        dim3 grid(1, mBlocks);
        mma_gemm<0, 0><<<grid, 256, DSMEM>>>(a0, 256, 0, 128, 128, 384, B0, 0, BIG, b0, 0,
                                             nullptr, 0, t0, 256, 0, 128,
                                             nullptr, 0, 0, nullptr, nullptr, n);
        mma_gemm<0, 0><<<grid, 256, DSMEM>>>(t0, 256, 0, 128, 128, 384, B1, 0, BIG, b1, 0,
                                             nullptr, 0, t1, 256, 0, 128,
                                             nullptr, 0, 0, nullptr, nullptr, n);
        mma_gemm<1, 0><<<grid, 256, DSMEM>>>(t1, 256, 0, 128, 128, 384, B2, 0, BIG, b2, 0,
                                             cat + (l + 1) * DD, OCW,
                                             nullptr, 0, 0, 0,
                                             catF16 + (l + 1) * DD, OCW, 0,
                                             nullptr, nullptr, n);
    }

    // channel MLP layer 1: plain fp16, K=Kex=512 -> H1 fp16 [N,1024]
    {
        dim3 grid((CHN * CHID) / 128, mBlocks);
        mma_gemm<2, 2><<<grid, 256, DSMEM>>>((const __nv_bfloat16*)catF16, OCW, 0, 0, 512, 512,
                                             (const __nv_bfloat16*)W1p, (long)256 * 512, CHID,
                                             cB1, CHID,
                                             nullptr, 0, nullptr, 0, 0, 0,
                                             H1, 1024, CHID,
                                             nullptr, nullptr, n);
    }

    // channel MLP layer 2 + fused final dot: plain fp16, K=Kex=256
    cudaMemsetAsync(out, 0, (size_t)n * CHN * sizeof(float), 0);
    {
        dim3 grid((CHN * CHID) / 128, mBlocks);
        mma_gemm<3, 2><<<grid, 256, DSMEM>>>((const __nv_bfloat16*)H1, 1024, 256, 0, 256, 256,
                                             (const __nv_bfloat16*)W2p, (long)256 * 256, CHID,
                                             cB2, CHID,
                                             nullptr, 0, nullptr, 0, 0, 0,
                                             nullptr, 0, 0,
                                             cW3, out, n);
    }

    out_bias_relu_kernel<<<(n * CHN + 255) / 256, 256>>>(out, cB3, n);
}